// round 8
// baseline (speedup 1.0000x reference)
#include <cuda_runtime.h>
#include <cuda_fp16.h>
#include <cstdint>

#define L_SEQ 2048
#define EMB   512
#define NHEAD 8
#define HDIM  64
#define NTYPE 10
#define KSPLIT 1536      // 3 * EMB  (activations [hi|lo|hi], weights [hi|hi|lo])

// q scale folded with log2(e): softmax done in base-2 domain
#define QSCALE 0.18033688011112042f   // 0.125 * log2(e)

// ---------------------------------------------------------------------------
// Scratch (allocation-free rule: device globals)
// ---------------------------------------------------------------------------
__device__ float g_v[L_SEQ * EMB];
__device__ float g_ts[NHEAD * L_SEQ * 16];

__device__ __half g_aq[L_SEQ * KSPLIT];
__device__ __half g_ak[L_SEQ * KSPLIT];
__device__ __half g_av[L_SEQ * KSPLIT];
__device__ __half g_wqkv[3 * EMB * KSPLIT];
__device__ __half g_wo[EMB * KSPLIT];     // k-cols PAIR-PERMUTED
__device__ __half g_sq[L_SEQ * KSPLIT];   // projected q (log2-scaled), hlh, permuted
__device__ __half g_sk[L_SEQ * KSPLIT];   // projected k, hhl, permuted
__device__ __half g_actx[L_SEQ * KSPLIT]; // ctx, hlh, permuted
__device__ __half g_svt[NHEAD * 2 * HDIM * L_SEQ];  // [h][vh|vl][j] permuted pairs

__device__ __forceinline__ int permute_paircol(int col) {   // col even
    int p = (col >> 1) & 7;
    return (col & ~15) + (((p & 3) * 2 + (p >> 2)) << 1);
}

// ---------------------------------------------------------------------------
// helpers
// ---------------------------------------------------------------------------
__device__ __forceinline__ uint32_t packh(float lo, float hi) {
    uint32_t r;
    asm("cvt.rn.f16x2.f32 %0, %1, %2;" : "=r"(r) : "f"(hi), "f"(lo));
    return r;
}
__device__ __forceinline__ uint32_t ex2h2(float lo, float hi) {
    uint32_t r;
    asm("cvt.rn.f16x2.f32 %0, %1, %2;" : "=r"(r) : "f"(hi), "f"(lo));
    asm("ex2.approx.f16x2 %0, %0;" : "+r"(r));
    return r;
}
__device__ __forceinline__ float ex2f(float x) {
    float r;
    asm("ex2.approx.f32 %0, %1;" : "=f"(r) : "f"(x));
    return r;
}
__device__ __forceinline__ float2 unph(uint32_t u) {
    __half2 h = *reinterpret_cast<__half2*>(&u);
    return __half22float2(h);
}
__device__ __forceinline__ uint32_t smem_to_u32(const void* p) {
    uint32_t a;
    asm("{ .reg .u64 t; cvta.to.shared.u64 t, %1; cvt.u32.u64 %0, t; }"
        : "=r"(a) : "l"(p));
    return a;
}
__device__ __forceinline__ void mma16816(float* d, const uint32_t* a,
                                         uint32_t b0, uint32_t b1) {
    asm volatile(
        "mma.sync.aligned.m16n8k16.row.col.f32.f16.f16.f32 "
        "{%0,%1,%2,%3}, {%4,%5,%6,%7}, {%8,%9}, {%0,%1,%2,%3};"
        : "+f"(d[0]), "+f"(d[1]), "+f"(d[2]), "+f"(d[3])
        : "r"(a[0]), "r"(a[1]), "r"(a[2]), "r"(a[3]), "r"(b0), "r"(b1));
}
__device__ __forceinline__ void mma16816h(uint32_t* c, const uint32_t* a,
                                          uint32_t b0, uint32_t b1) {
    asm volatile(
        "mma.sync.aligned.m16n8k16.row.col.f16.f16.f16.f16 "
        "{%0,%1}, {%2,%3,%4,%5}, {%6,%7}, {%0,%1};"
        : "+r"(c[0]), "+r"(c[1])
        : "r"(a[0]), "r"(a[1]), "r"(a[2]), "r"(a[3]), "r"(b0), "r"(b1));
}
__device__ __forceinline__ void cp16(uint32_t s, const void* g) {
    asm volatile("cp.async.cg.shared.global [%0], [%1], 16;"
                 :: "r"(s), "l"(g) : "memory");
}
#define CP_COMMIT asm volatile("cp.async.commit_group;" ::: "memory")

__device__ __forceinline__ void store_split(__half* d, float v0, float v1,
                                            int mode) {
    float h0 = __half2float(__float2half(v0));
    float h1 = __half2float(__float2half(v1));
    uint32_t hh = packh(h0, h1), ll = packh(v0 - h0, v1 - h1);
    *(uint32_t*)d          = hh;
    *(uint32_t*)(d + 512)  = (mode == 1) ? ll : hh;
    *(uint32_t*)(d + 1024) = (mode == 1) ? hh : ll;
}

// ---------------------------------------------------------------------------
// ONE fused split kernel: 3 activations (hlh) + w_in (hhl) + w_out (hhl perm)
// ---------------------------------------------------------------------------
__global__ __launch_bounds__(256) void split_all(
    const float* __restrict__ q, const float* __restrict__ k,
    const float* __restrict__ v, const float* __restrict__ w,
    const float* __restrict__ wo) {
    int idx = blockIdx.x * 256 + threadIdx.x;   // 0 .. 4194303
    if (idx < 3145728) {                        // activations, hlh
        const float* src = idx < 1048576 ? q : (idx < 2097152 ? k : v);
        __half* dst = idx < 1048576 ? g_aq : (idx < 2097152 ? g_ak : g_av);
        int li = idx & 1048575;
        int r = li >> 9, c = li & 511;
        float x = src[li];
        __half h = __float2half(x);
        __half l = __float2half(x - __half2float(h));
        __half* yr = dst + (size_t)r * KSPLIT;
        yr[c] = h; yr[512 + c] = l; yr[1024 + c] = h;
    } else if (idx < 3932160) {                 // w_in, hhl
        int li = idx - 3145728;
        int r = li >> 9, c = li & 511;
        float x = w[li];
        __half h = __float2half(x);
        __half l = __float2half(x - __half2float(h));
        __half* yr = g_wqkv + (size_t)r * KSPLIT;
        yr[c] = h; yr[512 + c] = h; yr[1024 + c] = l;
    } else {                                    // w_out, hhl + pair perm
        int li = idx - 3932160;
        int r = li >> 9, c = li & 511;
        float x = wo[li];
        __half h = __float2half(x);
        __half l = __float2half(x - __half2float(h));
        int cp_ = permute_paircol(c & ~1) + (c & 1);
        __half* yr = g_wo + (size_t)r * KSPLIT;
        yr[cp_] = h; yr[512 + cp_] = h; yr[1024 + cp_] = l;
    }
}

// ---------------------------------------------------------------------------
// mma.sync GEMM, cp.async double-buffered (unchanged core).
// ---------------------------------------------------------------------------
__device__ __forceinline__ void gemm_core(const __half* __restrict__ A,
                                          const __half* __restrict__ B,
                                          const float* __restrict__ bias,
                                          float* __restrict__ Cf,
                                          __half* __restrict__ Cs,
                                          int cn0, int m0, float scale, int mode) {
    __shared__ __half As[2][128 * 40];
    __shared__ __half Bs[2][128 * 40];
    int tid = threadIdx.x, wid = tid >> 5, lane = tid & 31;
    int gid = lane >> 2, qt = lane & 3;
    int wm = wid >> 2, wn = wid & 3;

    float acc[4][4][4] = {};
    uint32_t acch[4][4][2] = {};
    int lrow = tid >> 1, lcol = (tid & 1) * 16;
    const __half* Ap = A + (size_t)(m0 + lrow) * KSPLIT + lcol;
    const __half* Bp = B + (size_t)lrow * KSPLIT + lcol;
    uint32_t sA[2] = {smem_to_u32(&As[0][lrow * 40 + lcol]),
                      smem_to_u32(&As[1][lrow * 40 + lcol])};
    uint32_t sB[2] = {smem_to_u32(&Bs[0][lrow * 40 + lcol]),
                      smem_to_u32(&Bs[1][lrow * 40 + lcol])};

    cp16(sA[0], Ap); cp16(sA[0] + 16, Ap + 8);
    cp16(sB[0], Bp); cp16(sB[0] + 16, Bp + 8);
    CP_COMMIT;

    for (int kt = 0; kt < KSPLIT / 32; kt++) {
        int cur = kt & 1;
        if (kt + 1 < KSPLIT / 32) {
            int nx = cur ^ 1;
            const __half* a = Ap + (kt + 1) * 32;
            const __half* b = Bp + (kt + 1) * 32;
            cp16(sA[nx], a); cp16(sA[nx] + 16, a + 8);
            cp16(sB[nx], b); cp16(sB[nx] + 16, b + 8);
            CP_COMMIT;
            asm volatile("cp.async.wait_group 1;" ::: "memory");
        } else {
            asm volatile("cp.async.wait_group 0;" ::: "memory");
        }
        __syncthreads();
        bool hi_term = (kt < 16);
        #pragma unroll
        for (int kc = 0; kc < 2; kc++) {
            uint32_t a[4][4];
            #pragma unroll
            for (int mf = 0; mf < 4; mf++) {
                int r = wm * 64 + mf * 16 + gid;
                int c = kc * 16 + qt * 2;
                a[mf][0] = *(const uint32_t*)&As[cur][r * 40 + c];
                a[mf][1] = *(const uint32_t*)&As[cur][(r + 8) * 40 + c];
                a[mf][2] = *(const uint32_t*)&As[cur][r * 40 + c + 8];
                a[mf][3] = *(const uint32_t*)&As[cur][(r + 8) * 40 + c + 8];
            }
            #pragma unroll
            for (int nf = 0; nf < 4; nf++) {
                int n = wn * 32 + nf * 8 + gid;
                int c = kc * 16 + qt * 2;
                uint32_t b0 = *(const uint32_t*)&Bs[cur][n * 40 + c];
                uint32_t b1 = *(const uint32_t*)&Bs[cur][n * 40 + c + 8];
                if (hi_term) {
                    #pragma unroll
                    for (int mf = 0; mf < 4; mf++)
                        mma16816(acc[mf][nf], a[mf], b0, b1);
                } else {
                    #pragma unroll
                    for (int mf = 0; mf < 4; mf++)
                        mma16816h(acch[mf][nf], a[mf], b0, b1);
                }
            }
        }
        __syncthreads();
    }
    #pragma unroll
    for (int mf = 0; mf < 4; mf++) {
        int r = m0 + wm * 64 + mf * 16 + gid;
        #pragma unroll
        for (int nf = 0; nf < 4; nf++) {
            int cb = wn * 32 + nf * 8 + qt * 2;
            float b0 = __ldg(bias + cb), b1 = __ldg(bias + cb + 1);
            float2 c0 = unph(acch[mf][nf][0]);
            float2 c1 = unph(acch[mf][nf][1]);
            float v00 = scale * (acc[mf][nf][0] + c0.x + b0);
            float v01 = scale * (acc[mf][nf][1] + c0.y + b1);
            float v10 = scale * (acc[mf][nf][2] + c1.x + b0);
            float v11 = scale * (acc[mf][nf][3] + c1.y + b1);
            int col = cn0 + cb;
            if (mode == 0) {
                *(float2*)&Cf[(size_t)r * EMB + col]       = make_float2(v00, v01);
                *(float2*)&Cf[(size_t)(r + 8) * EMB + col] = make_float2(v10, v11);
            } else {
                int colp = permute_paircol(col);
                store_split(Cs + (size_t)r * KSPLIT + colp, v00, v01, mode);
                store_split(Cs + (size_t)(r + 8) * KSPLIT + colp, v10, v11, mode);
            }
        }
    }
}

__global__ __launch_bounds__(256) void gemm_qkv_kernel(const float* __restrict__ bias) {
    int m0 = blockIdx.x * 128;
    int nt = blockIdx.y;
    int sect = nt >> 2;
    int cn0 = (nt & 3) * 128;
    const __half* Bw = g_wqkv + (size_t)nt * 128 * KSPLIT;
    if (sect == 0)
        gemm_core(g_aq, Bw, bias + nt * 128, nullptr, g_sq, cn0, m0, QSCALE, 1);
    else if (sect == 1)
        gemm_core(g_ak, Bw, bias + nt * 128, nullptr, g_sk, cn0, m0, 1.0f, 2);
    else
        gemm_core(g_av, Bw, bias + nt * 128, g_v, nullptr, cn0, m0, 1.0f, 0);
}
__global__ __launch_bounds__(256) void gemm_out_kernel(const float* __restrict__ bias,
                                                       float* __restrict__ C) {
    gemm_core(g_actx, g_wo + (size_t)blockIdx.y * 128 * KSPLIT,
              bias + blockIdx.y * 128, C, nullptr, blockIdx.y * 128,
              blockIdx.x * 128, 1.0f, 0);
}

// ---------------------------------------------------------------------------
// Fused: V split+transpose (blocks 0..255) + type_scores (blocks 256..2303)
// ---------------------------------------------------------------------------
__global__ __launch_bounds__(256) void tsvt_kernel(const float* __restrict__ edge_embs) {
    __shared__ float sh[64 * 68];
    int tid = threadIdx.x;
    if (blockIdx.x < 256) {
        // ---- v_split_transpose ----
        int h = blockIdx.x >> 5, j0 = (blockIdx.x & 31) * 64;
        {
            int row = tid >> 2, cg = (tid & 3) * 16;
            const float* src = g_v + (size_t)(j0 + row) * EMB + h * HDIM + cg;
            #pragma unroll
            for (int i = 0; i < 4; i++)
                *(float4*)&sh[row * 68 + cg + i * 4] = *(const float4*)(src + i * 4);
        }
        __syncthreads();
        int d = tid >> 2, jg = (tid & 3) * 16;
        uint32_t hw[8], lw[8];
        #pragma unroll
        for (int p = 0; p < 8; p++) {
            float v0 = sh[(jg + 2 * p) * 68 + d], v1 = sh[(jg + 2 * p + 1) * 68 + d];
            float h0 = __half2float(__float2half(v0));
            float h1 = __half2float(__float2half(v1));
            hw[p] = packh(h0, h1);
            lw[p] = packh(v0 - h0, v1 - h1);
        }
        __half* dsth = g_svt + ((size_t)(h * 128 + d) * L_SEQ + j0 + jg);
        __half* dstl = g_svt + ((size_t)(h * 128 + 64 + d) * L_SEQ + j0 + jg);
        *(uint4*)dsth       = make_uint4(hw[0], hw[4], hw[1], hw[5]);
        *(uint4*)(dsth + 8) = make_uint4(hw[2], hw[6], hw[3], hw[7]);
        *(uint4*)dstl       = make_uint4(lw[0], lw[4], lw[1], lw[5]);
        *(uint4*)(dstl + 8) = make_uint4(lw[2], lw[6], lw[3], lw[7]);
    } else {
        // ---- type_scores (log2-domain automatically: g_sq carries log2 scale) ----
        float* emb = sh;
        for (int i = tid; i < NTYPE * HDIM; i += 256) emb[i] = edge_embs[i];
        __syncthreads();
        int warp = (blockIdx.x - 256) * 8 + (tid >> 5);
        int lane = tid & 31;
        int h = warp >> 11, i = warp & (L_SEQ - 1);
        int pw = lane & 7;
        int colp = (lane >> 3) * 16 + ((pw & 3) * 2 + (pw >> 2)) * 2;
        const __half* qr = g_sq + (size_t)i * KSPLIT + h * HDIM + colp;
        float2 qh = __half22float2(*(const __half2*)qr);
        float2 ql = __half22float2(*(const __half2*)(qr + 512));
        float2 qv = make_float2(qh.x + ql.x, qh.y + ql.y);
        float s[NTYPE];
        #pragma unroll
        for (int t = 0; t < NTYPE; t++) {
            float2 e = *(const float2*)(emb + t * HDIM + lane * 2);
            s[t] = qv.x * e.x + qv.y * e.y;
        }
        #pragma unroll
        for (int off = 16; off > 0; off >>= 1)
            #pragma unroll
            for (int t = 0; t < NTYPE; t++)
                s[t] += __shfl_xor_sync(0xffffffffu, s[t], off);
        if (lane == 0) {
            float* dst = g_ts + (size_t)warp * 16;
            #pragma unroll
            for (int t = 0; t < NTYPE; t++) dst[t] = s[t];
        }
    }
}

// ---------------------------------------------------------------------------
// Flash attention, base-2 softmax with ex2.approx.f16x2; P fp16-only;
// row sums via MMA against ones; PV = ph*vh (fp32acc) + ph*vl (fp16acc).
// ---------------------------------------------------------------------------
#define QPITCH 144
#define VPITCH 80
#define SM_K 36864
#define SM_V 73728
#define SM_T 114688
#define ATTN_SMEM 122880

__global__ __launch_bounds__(256) void attn_mma_kernel(const int* __restrict__ edge_id) {
    extern __shared__ char smb[];
    __half* Qs = (__half*)smb;
    float* Ts = (float*)(smb + SM_T);
    uint32_t sbase = smem_to_u32(smb);

    int h = blockIdx.y;
    int i0 = blockIdx.x * 128;
    int tid = threadIdx.x, wid = tid >> 5, lane = tid & 31;
    int gid = lane >> 2, qt = lane & 3;
    const uint32_t ones2 = 0x3C003C00u;

    auto load_kv = [&](int j0, int buf) {
        int row = tid >> 2, q4 = tid & 3;
        {
            int half_ = q4 >> 1, part = q4 & 1;
            const __half* src = g_sk + (size_t)(j0 + row) * KSPLIT
                                + half_ * 1024 + h * HDIM + part * 32;
            uint32_t dst = sbase + SM_K + buf * 18432 + row * 288 + half_ * 128 + part * 64;
            #pragma unroll
            for (int i = 0; i < 4; i++) cp16(dst + i * 16, src + i * 8);
        }
        {
            int vrow = tid >> 1, part = tid & 1;
            const __half* src = g_svt + (size_t)(h * 128 + vrow) * L_SEQ
                                + j0 + part * 32;
            uint32_t dst = sbase + SM_V + buf * 20480 + vrow * 160 + part * 64;
            #pragma unroll
            for (int i = 0; i < 4; i++) cp16(dst + i * 16, src + i * 8);
        }
    };

    {
        int row = tid >> 1, half_ = tid & 1;
        const __half* src = g_sq + (size_t)(i0 + row) * KSPLIT
                            + half_ * 512 + h * HDIM;
        uint32_t dst = sbase + row * 288 + half_ * 128;
        #pragma unroll
        for (int i = 0; i < 8; i++) cp16(dst + i * 16, src + i * 8);
        const float* tsrc = g_ts + ((size_t)h * L_SEQ + i0 + row) * 16 + half_ * 8;
        *(float4*)(Ts + row * 16 + half_ * 8)     = *(const float4*)tsrc;
        *(float4*)(Ts + row * 16 + half_ * 8 + 4) = *(const float4*)(tsrc + 4);
    }
    CP_COMMIT;
    load_kv(0, 0);
    CP_COMMIT;
    asm volatile("cp.async.wait_group 1;" ::: "memory");
    __syncthreads();

    int r0 = wid * 16 + gid;
    uint32_t qh[4][4], ql[4][4];
    #pragma unroll
    for (int kc = 0; kc < 4; kc++) {
        uint2 lo = *(const uint2*)&Qs[r0 * QPITCH + kc * 16 + qt * 4];
        uint2 hi = *(const uint2*)&Qs[(r0 + 8) * QPITCH + kc * 16 + qt * 4];
        qh[kc][0] = lo.x; qh[kc][1] = hi.x; qh[kc][2] = lo.y; qh[kc][3] = hi.y;
        uint2 lo2 = *(const uint2*)&Qs[r0 * QPITCH + 64 + kc * 16 + qt * 4];
        uint2 hi2 = *(const uint2*)&Qs[(r0 + 8) * QPITCH + 64 + kc * 16 + qt * 4];
        ql[kc][0] = lo2.x; ql[kc][1] = hi2.x; ql[kc][2] = lo2.y; ql[kc][3] = hi2.y;
    }

    float o[8][4] = {};
    float rm0 = -1e30f, rm1 = -1e30f, rl0 = 0.f, rl1 = 0.f;
    const float* T0 = Ts + r0 * 16;
    const float* T1 = T0 + 128;

    for (int t = 0; t < 32; t++) {
        int cur = t & 1;
        if (t + 1 < 32) {
            load_kv((t + 1) * 64, cur ^ 1);
            CP_COMMIT;
            asm volatile("cp.async.wait_group 1;" ::: "memory");
        } else {
            asm volatile("cp.async.wait_group 0;" ::: "memory");
        }
        __syncthreads();
        const __half* Ks = (const __half*)(smb + SM_K + cur * 18432);
        const __half* Vt = (const __half*)(smb + SM_V + cur * 20480);
        int j0 = t * 64;

        // ---- edge-id prefetch (long-latency, consumed after S MMAs) ----
        int grow0 = i0 + r0, grow1 = grow0 + 8;
        int2 e0r[8], e1r[8];
        #pragma unroll
        for (int nt = 0; nt < 8; nt++) {
            int col = j0 + nt * 8 + qt * 2;
            e0r[nt] = *(const int2*)&edge_id[(size_t)grow0 * L_SEQ + col];
            e1r[nt] = *(const int2*)&edge_id[(size_t)grow1 * L_SEQ + col];
        }

        // ---- S: hi fp32-acc, crosses fp16-acc ----
        float sa[8][4] = {};
        uint32_t sc[8][2] = {};
        #pragma unroll
        for (int kc = 0; kc < 4; kc++) {
            #pragma unroll
            for (int nt = 0; nt < 8; nt++) {
                int brow = nt * 8 + gid;
                uint2 kh = *(const uint2*)&Ks[brow * QPITCH + kc * 16 + qt * 4];
                uint2 kl = *(const uint2*)&Ks[brow * QPITCH + 64 + kc * 16 + qt * 4];
                mma16816(sa[nt], qh[kc], kh.x, kh.y);
                mma16816h(sc[nt], ql[kc], kh.x, kh.y);
                mma16816h(sc[nt], qh[kc], kl.x, kl.y);
            }
        }
        #pragma unroll
        for (int nt = 0; nt < 8; nt++) {
            float2 ca = unph(sc[nt][0]);
            float2 cb = unph(sc[nt][1]);
            sa[nt][0] += ca.x + T0[e0r[nt].x];
            sa[nt][1] += ca.y + T0[e0r[nt].y];
            sa[nt][2] += cb.x + T1[e1r[nt].x];
            sa[nt][3] += cb.y + T1[e1r[nt].y];
        }

        // ---- online softmax (base 2) ----
        float mx0 = -1e30f, mx1 = -1e30f;
        #pragma unroll
        for (int nt = 0; nt < 8; nt++) {
            mx0 = fmaxf(mx0, fmaxf(sa[nt][0], sa[nt][1]));
            mx1 = fmaxf(mx1, fmaxf(sa[nt][2], sa[nt][3]));
        }
        mx0 = fmaxf(mx0, __shfl_xor_sync(0xffffffffu, mx0, 1));
        mx0 = fmaxf(mx0, __shfl_xor_sync(0xffffffffu, mx0, 2));
        mx1 = fmaxf(mx1, __shfl_xor_sync(0xffffffffu, mx1, 1));
        mx1 = fmaxf(mx1, __shfl_xor_sync(0xffffffffu, mx1, 2));
        float mn0 = fmaxf(rm0, mx0), mn1 = fmaxf(rm1, mx1);
        float c0 = ex2f(rm0 - mn0), c1 = ex2f(rm1 - mn1);
        rm0 = mn0; rm1 = mn1;

        // P = 2^(s - m) directly as packed fp16 A-fragments; row sums via MMA
        uint32_t ph[4][4];
        float ls[4] = {};
        #pragma unroll
        for (int kc = 0; kc < 4; kc++) {
            const float* t0v = sa[2 * kc];
            const float* t1v = sa[2 * kc + 1];
            ph[kc][0] = ex2h2(t0v[0] - mn0, t0v[1] - mn0);
            ph[kc][1] = ex2h2(t0v[2] - mn1, t0v[3] - mn1);
            ph[kc][2] = ex2h2(t1v[0] - mn0, t1v[1] - mn0);
            ph[kc][3] = ex2h2(t1v[2] - mn1, t1v[3] - mn1);
            mma16816(ls, ph[kc], ones2, ones2);
        }
        rl0 = rl0 * c0 + ls[0];
        rl1 = rl1 * c1 + ls[2];
        #pragma unroll
        for (int dt = 0; dt < 8; dt++) {
            o[dt][0] *= c0; o[dt][1] *= c0;
            o[dt][2] *= c1; o[dt][3] *= c1;
        }

        // ---- PV: O += ph*vh (fp32) + ph*vl (fp16) ----
        uint32_t oc[8][2] = {};
        #pragma unroll
        for (int kc = 0; kc < 4; kc++) {
            #pragma unroll
            for (int dt = 0; dt < 8; dt++) {
                int vrh = dt * 8 + gid;
                uint2 vh = *(const uint2*)&Vt[vrh * VPITCH + kc * 16 + qt * 4];
                uint2 vl = *(const uint2*)&Vt[(64 + vrh) * VPITCH + kc * 16 + qt * 4];
                mma16816(o[dt], ph[kc], vh.x, vh.y);
                mma16816h(oc[dt], ph[kc], vl.x, vl.y);
            }
        }
        #pragma unroll
        for (int dt = 0; dt < 8; dt++) {
            float2 ca = unph(oc[dt][0]);
            float2 cb = unph(oc[dt][1]);
            o[dt][0] += ca.x; o[dt][1] += ca.y;
            o[dt][2] += cb.x; o[dt][3] += cb.y;
        }
        __syncthreads();
    }

    float inv0 = 1.0f / rl0, inv1 = 1.0f / rl1;
    __half* dst0 = g_actx + (size_t)(i0 + r0) * KSPLIT + h * HDIM;
    __half* dst1 = g_actx + (size_t)(i0 + r0 + 8) * KSPLIT + h * HDIM;
    #pragma unroll
    for (int dt = 0; dt < 8; dt++) {
        int c = dt * 8 + qt * 2;
        int cp_ = permute_paircol(c);
        store_split(dst0 + cp_, o[dt][0] * inv0, o[dt][1] * inv0, 1);
        store_split(dst1 + cp_, o[dt][2] * inv1, o[dt][3] * inv1, 1);
    }
}

// ---------------------------------------------------------------------------
extern "C" void kernel_launch(void* const* d_in, const int* in_sizes, int n_in,
                              void* d_out, int out_size)
{
    const float* query = (const float*)d_in[0];
    const float* key   = (const float*)d_in[1];
    const float* value = (const float*)d_in[2];
    const int*   eid   = (const int*)d_in[3];
    const float* w_in  = (const float*)d_in[4];
    const float* b_in  = (const float*)d_in[5];
    const float* w_out = (const float*)d_in[6];
    const float* b_out = (const float*)d_in[7];
    const float* embK  = (const float*)d_in[8];
    float* out = (float*)d_out;

    // launch 0: all splits fused
    split_all<<<16384, 256>>>(query, key, value, w_in, w_out);

    // launch 1: QKV projection (q log2-scaled)
    dim3 qkv_grid(L_SEQ / 128, 12);
    gemm_qkv_kernel<<<qkv_grid, 256>>>(b_in);

    // launch 2: V transpose/split + type scores
    tsvt_kernel<<<2304, 256>>>(embK);

    // launch 3: flash attention (ncu-visible slot)
    cudaFuncSetAttribute(attn_mma_kernel, cudaFuncAttributeMaxDynamicSharedMemorySize,
                         ATTN_SMEM);
    dim3 attn_grid(L_SEQ / 128, NHEAD);
    attn_mma_kernel<<<attn_grid, 256, ATTN_SMEM>>>(eid);

    // launch 4: out projection
    dim3 out_grid(L_SEQ / 128, 4);
    gemm_out_kernel<<<out_grid, 256>>>(b_out, out);
}

// round 9
// speedup vs baseline: 1.0656x; 1.0656x over previous
#include <cuda_runtime.h>
#include <cuda_fp16.h>
#include <cstdint>

#define L_SEQ 2048
#define EMB   512
#define NHEAD 8
#define HDIM  64
#define NTYPE 10
#define KSPLIT 1536      // 3 * EMB  (activations [hi|lo|hi], weights [hi|hi|lo])

// q scale folded with log2(e): softmax done in base-2 domain
#define QSCALE 0.18033688011112042f   // 0.125 * log2(e)

// ---------------------------------------------------------------------------
// Scratch (allocation-free rule: device globals)
// ---------------------------------------------------------------------------
__device__ float g_v[L_SEQ * EMB];
__device__ float g_ts[NHEAD * L_SEQ * 16];

__device__ __half g_aq[L_SEQ * KSPLIT];
__device__ __half g_ak[L_SEQ * KSPLIT];
__device__ __half g_av[L_SEQ * KSPLIT];
__device__ __half g_wqkv[3 * EMB * KSPLIT];
__device__ __half g_wo[EMB * KSPLIT];     // k-cols PAIR-PERMUTED
__device__ __half g_sq[L_SEQ * KSPLIT];   // projected q (log2-scaled), hlh, permuted
__device__ __half g_sk[L_SEQ * KSPLIT];   // projected k, hhl, permuted
__device__ __half g_actx[L_SEQ * KSPLIT]; // ctx, hlh, permuted
__device__ __half g_svt[NHEAD * 2 * HDIM * L_SEQ];  // [h][vh|vl][j] permuted pairs

__device__ __forceinline__ int permute_paircol(int col) {   // col even
    int p = (col >> 1) & 7;
    return (col & ~15) + (((p & 3) * 2 + (p >> 2)) << 1);
}

// ---------------------------------------------------------------------------
// helpers
// ---------------------------------------------------------------------------
__device__ __forceinline__ uint32_t packh(float lo, float hi) {
    uint32_t r;
    asm("cvt.rn.f16x2.f32 %0, %1, %2;" : "=r"(r) : "f"(hi), "f"(lo));
    return r;
}
__device__ __forceinline__ uint32_t ex2h2(float lo, float hi) {
    uint32_t r;
    asm("cvt.rn.f16x2.f32 %0, %1, %2;" : "=r"(r) : "f"(hi), "f"(lo));
    asm("ex2.approx.f16x2 %0, %0;" : "+r"(r));
    return r;
}
__device__ __forceinline__ float ex2f(float x) {
    float r;
    asm("ex2.approx.f32 %0, %1;" : "=f"(r) : "f"(x));
    return r;
}
__device__ __forceinline__ float2 unph(uint32_t u) {
    __half2 h = *reinterpret_cast<__half2*>(&u);
    return __half22float2(h);
}
__device__ __forceinline__ uint32_t smem_to_u32(const void* p) {
    uint32_t a;
    asm("{ .reg .u64 t; cvta.to.shared.u64 t, %1; cvt.u32.u64 %0, t; }"
        : "=r"(a) : "l"(p));
    return a;
}
__device__ __forceinline__ void mma16816(float* d, const uint32_t* a,
                                         uint32_t b0, uint32_t b1) {
    asm volatile(
        "mma.sync.aligned.m16n8k16.row.col.f32.f16.f16.f32 "
        "{%0,%1,%2,%3}, {%4,%5,%6,%7}, {%8,%9}, {%0,%1,%2,%3};"
        : "+f"(d[0]), "+f"(d[1]), "+f"(d[2]), "+f"(d[3])
        : "r"(a[0]), "r"(a[1]), "r"(a[2]), "r"(a[3]), "r"(b0), "r"(b1));
}
__device__ __forceinline__ void mma16816h(uint32_t* c, const uint32_t* a,
                                          uint32_t b0, uint32_t b1) {
    asm volatile(
        "mma.sync.aligned.m16n8k16.row.col.f16.f16.f16.f16 "
        "{%0,%1}, {%2,%3,%4,%5}, {%6,%7}, {%0,%1};"
        : "+r"(c[0]), "+r"(c[1])
        : "r"(a[0]), "r"(a[1]), "r"(a[2]), "r"(a[3]), "r"(b0), "r"(b1));
}
__device__ __forceinline__ void cp16(uint32_t s, const void* g) {
    asm volatile("cp.async.cg.shared.global [%0], [%1], 16;"
                 :: "r"(s), "l"(g) : "memory");
}
#define CP_COMMIT asm volatile("cp.async.commit_group;" ::: "memory")

__device__ __forceinline__ void store_split(__half* d, float v0, float v1,
                                            int mode) {
    float h0 = __half2float(__float2half(v0));
    float h1 = __half2float(__float2half(v1));
    uint32_t hh = packh(h0, h1), ll = packh(v0 - h0, v1 - h1);
    *(uint32_t*)d          = hh;
    *(uint32_t*)(d + 512)  = (mode == 1) ? ll : hh;
    *(uint32_t*)(d + 1024) = (mode == 1) ? hh : ll;
}

// ---------------------------------------------------------------------------
// ONE fused split kernel: 3 activations (hlh) + w_in (hhl) + w_out (hhl perm)
// ---------------------------------------------------------------------------
__global__ __launch_bounds__(256) void split_all(
    const float* __restrict__ q, const float* __restrict__ k,
    const float* __restrict__ v, const float* __restrict__ w,
    const float* __restrict__ wo) {
    int idx = blockIdx.x * 256 + threadIdx.x;   // 0 .. 4194303
    if (idx < 3145728) {                        // activations, hlh
        const float* src = idx < 1048576 ? q : (idx < 2097152 ? k : v);
        __half* dst = idx < 1048576 ? g_aq : (idx < 2097152 ? g_ak : g_av);
        int li = idx & 1048575;
        int r = li >> 9, c = li & 511;
        float x = src[li];
        __half h = __float2half(x);
        __half l = __float2half(x - __half2float(h));
        __half* yr = dst + (size_t)r * KSPLIT;
        yr[c] = h; yr[512 + c] = l; yr[1024 + c] = h;
    } else if (idx < 3932160) {                 // w_in, hhl
        int li = idx - 3145728;
        int r = li >> 9, c = li & 511;
        float x = w[li];
        __half h = __float2half(x);
        __half l = __float2half(x - __half2float(h));
        __half* yr = g_wqkv + (size_t)r * KSPLIT;
        yr[c] = h; yr[512 + c] = h; yr[1024 + c] = l;
    } else {                                    // w_out, hhl + pair perm
        int li = idx - 3932160;
        int r = li >> 9, c = li & 511;
        float x = wo[li];
        __half h = __float2half(x);
        __half l = __float2half(x - __half2float(h));
        int cp_ = permute_paircol(c & ~1) + (c & 1);
        __half* yr = g_wo + (size_t)r * KSPLIT;
        yr[cp_] = h; yr[512 + cp_] = h; yr[1024 + cp_] = l;
    }
}

// ---------------------------------------------------------------------------
// mma.sync GEMM, cp.async double-buffered (unchanged core).
// ---------------------------------------------------------------------------
__device__ __forceinline__ void gemm_core(const __half* __restrict__ A,
                                          const __half* __restrict__ B,
                                          const float* __restrict__ bias,
                                          float* __restrict__ Cf,
                                          __half* __restrict__ Cs,
                                          int cn0, int m0, float scale, int mode) {
    __shared__ __half As[2][128 * 40];
    __shared__ __half Bs[2][128 * 40];
    int tid = threadIdx.x, wid = tid >> 5, lane = tid & 31;
    int gid = lane >> 2, qt = lane & 3;
    int wm = wid >> 2, wn = wid & 3;

    float acc[4][4][4] = {};
    uint32_t acch[4][4][2] = {};
    int lrow = tid >> 1, lcol = (tid & 1) * 16;
    const __half* Ap = A + (size_t)(m0 + lrow) * KSPLIT + lcol;
    const __half* Bp = B + (size_t)lrow * KSPLIT + lcol;
    uint32_t sA[2] = {smem_to_u32(&As[0][lrow * 40 + lcol]),
                      smem_to_u32(&As[1][lrow * 40 + lcol])};
    uint32_t sB[2] = {smem_to_u32(&Bs[0][lrow * 40 + lcol]),
                      smem_to_u32(&Bs[1][lrow * 40 + lcol])};

    cp16(sA[0], Ap); cp16(sA[0] + 16, Ap + 8);
    cp16(sB[0], Bp); cp16(sB[0] + 16, Bp + 8);
    CP_COMMIT;

    for (int kt = 0; kt < KSPLIT / 32; kt++) {
        int cur = kt & 1;
        if (kt + 1 < KSPLIT / 32) {
            int nx = cur ^ 1;
            const __half* a = Ap + (kt + 1) * 32;
            const __half* b = Bp + (kt + 1) * 32;
            cp16(sA[nx], a); cp16(sA[nx] + 16, a + 8);
            cp16(sB[nx], b); cp16(sB[nx] + 16, b + 8);
            CP_COMMIT;
            asm volatile("cp.async.wait_group 1;" ::: "memory");
        } else {
            asm volatile("cp.async.wait_group 0;" ::: "memory");
        }
        __syncthreads();
        bool hi_term = (kt < 16);
        #pragma unroll
        for (int kc = 0; kc < 2; kc++) {
            uint32_t a[4][4];
            #pragma unroll
            for (int mf = 0; mf < 4; mf++) {
                int r = wm * 64 + mf * 16 + gid;
                int c = kc * 16 + qt * 2;
                a[mf][0] = *(const uint32_t*)&As[cur][r * 40 + c];
                a[mf][1] = *(const uint32_t*)&As[cur][(r + 8) * 40 + c];
                a[mf][2] = *(const uint32_t*)&As[cur][r * 40 + c + 8];
                a[mf][3] = *(const uint32_t*)&As[cur][(r + 8) * 40 + c + 8];
            }
            #pragma unroll
            for (int nf = 0; nf < 4; nf++) {
                int n = wn * 32 + nf * 8 + gid;
                int c = kc * 16 + qt * 2;
                uint32_t b0 = *(const uint32_t*)&Bs[cur][n * 40 + c];
                uint32_t b1 = *(const uint32_t*)&Bs[cur][n * 40 + c + 8];
                if (hi_term) {
                    #pragma unroll
                    for (int mf = 0; mf < 4; mf++)
                        mma16816(acc[mf][nf], a[mf], b0, b1);
                } else {
                    #pragma unroll
                    for (int mf = 0; mf < 4; mf++)
                        mma16816h(acch[mf][nf], a[mf], b0, b1);
                }
            }
        }
        __syncthreads();
    }
    #pragma unroll
    for (int mf = 0; mf < 4; mf++) {
        int r = m0 + wm * 64 + mf * 16 + gid;
        #pragma unroll
        for (int nf = 0; nf < 4; nf++) {
            int cb = wn * 32 + nf * 8 + qt * 2;
            float b0 = __ldg(bias + cb), b1 = __ldg(bias + cb + 1);
            float2 c0 = unph(acch[mf][nf][0]);
            float2 c1 = unph(acch[mf][nf][1]);
            float v00 = scale * (acc[mf][nf][0] + c0.x + b0);
            float v01 = scale * (acc[mf][nf][1] + c0.y + b1);
            float v10 = scale * (acc[mf][nf][2] + c1.x + b0);
            float v11 = scale * (acc[mf][nf][3] + c1.y + b1);
            int col = cn0 + cb;
            if (mode == 0) {
                *(float2*)&Cf[(size_t)r * EMB + col]       = make_float2(v00, v01);
                *(float2*)&Cf[(size_t)(r + 8) * EMB + col] = make_float2(v10, v11);
            } else {
                int colp = permute_paircol(col);
                store_split(Cs + (size_t)r * KSPLIT + colp, v00, v01, mode);
                store_split(Cs + (size_t)(r + 8) * KSPLIT + colp, v10, v11, mode);
            }
        }
    }
}

__global__ __launch_bounds__(256) void gemm_qkv_kernel(const float* __restrict__ bias) {
    int m0 = blockIdx.x * 128;
    int nt = blockIdx.y;
    int sect = nt >> 2;
    int cn0 = (nt & 3) * 128;
    const __half* Bw = g_wqkv + (size_t)nt * 128 * KSPLIT;
    if (sect == 0)
        gemm_core(g_aq, Bw, bias + nt * 128, nullptr, g_sq, cn0, m0, QSCALE, 1);
    else if (sect == 1)
        gemm_core(g_ak, Bw, bias + nt * 128, nullptr, g_sk, cn0, m0, 1.0f, 2);
    else
        gemm_core(g_av, Bw, bias + nt * 128, g_v, nullptr, cn0, m0, 1.0f, 0);
}
__global__ __launch_bounds__(256) void gemm_out_kernel(const float* __restrict__ bias,
                                                       float* __restrict__ C) {
    gemm_core(g_actx, g_wo + (size_t)blockIdx.y * 128 * KSPLIT,
              bias + blockIdx.y * 128, C, nullptr, blockIdx.y * 128,
              blockIdx.x * 128, 1.0f, 0);
}

// ---------------------------------------------------------------------------
// Fused: V split+transpose (blocks 0..255) + type_scores (blocks 256..2303)
// ---------------------------------------------------------------------------
__global__ __launch_bounds__(256) void tsvt_kernel(const float* __restrict__ edge_embs) {
    __shared__ float sh[64 * 68];
    int tid = threadIdx.x;
    if (blockIdx.x < 256) {
        int h = blockIdx.x >> 5, j0 = (blockIdx.x & 31) * 64;
        {
            int row = tid >> 2, cg = (tid & 3) * 16;
            const float* src = g_v + (size_t)(j0 + row) * EMB + h * HDIM + cg;
            #pragma unroll
            for (int i = 0; i < 4; i++)
                *(float4*)&sh[row * 68 + cg + i * 4] = *(const float4*)(src + i * 4);
        }
        __syncthreads();
        int d = tid >> 2, jg = (tid & 3) * 16;
        uint32_t hw[8], lw[8];
        #pragma unroll
        for (int p = 0; p < 8; p++) {
            float v0 = sh[(jg + 2 * p) * 68 + d], v1 = sh[(jg + 2 * p + 1) * 68 + d];
            float h0 = __half2float(__float2half(v0));
            float h1 = __half2float(__float2half(v1));
            hw[p] = packh(h0, h1);
            lw[p] = packh(v0 - h0, v1 - h1);
        }
        __half* dsth = g_svt + ((size_t)(h * 128 + d) * L_SEQ + j0 + jg);
        __half* dstl = g_svt + ((size_t)(h * 128 + 64 + d) * L_SEQ + j0 + jg);
        *(uint4*)dsth       = make_uint4(hw[0], hw[4], hw[1], hw[5]);
        *(uint4*)(dsth + 8) = make_uint4(hw[2], hw[6], hw[3], hw[7]);
        *(uint4*)dstl       = make_uint4(lw[0], lw[4], lw[1], lw[5]);
        *(uint4*)(dstl + 8) = make_uint4(lw[2], lw[6], lw[3], lw[7]);
    } else {
        float* emb = sh;
        for (int i = tid; i < NTYPE * HDIM; i += 256) emb[i] = edge_embs[i];
        __syncthreads();
        int warp = (blockIdx.x - 256) * 8 + (tid >> 5);
        int lane = tid & 31;
        int h = warp >> 11, i = warp & (L_SEQ - 1);
        int pw = lane & 7;
        int colp = (lane >> 3) * 16 + ((pw & 3) * 2 + (pw >> 2)) * 2;
        const __half* qr = g_sq + (size_t)i * KSPLIT + h * HDIM + colp;
        float2 qh = __half22float2(*(const __half2*)qr);
        float2 ql = __half22float2(*(const __half2*)(qr + 512));
        float2 qv = make_float2(qh.x + ql.x, qh.y + ql.y);
        float s[NTYPE];
        #pragma unroll
        for (int t = 0; t < NTYPE; t++) {
            float2 e = *(const float2*)(emb + t * HDIM + lane * 2);
            s[t] = qv.x * e.x + qv.y * e.y;
        }
        #pragma unroll
        for (int off = 16; off > 0; off >>= 1)
            #pragma unroll
            for (int t = 0; t < NTYPE; t++)
                s[t] += __shfl_xor_sync(0xffffffffu, s[t], off);
        if (lane == 0) {
            float* dst = g_ts + (size_t)warp * 16;
            #pragma unroll
            for (int t = 0; t < NTYPE; t++) dst[t] = s[t];
        }
    }
}

// ---------------------------------------------------------------------------
// Flash attention: i-tile 64, 8 warps = 4 row-warps x 2 n-groups,
// 2 CTAs/SM (smem 98KB), double-buffered K/V, base-2 softmax.
// smem: Q 0..18432 (pitch 288B), K 2x18432 @18432, V 2x20480 @55296,
//       Ts 4096 @96256. total 100352.
// ---------------------------------------------------------------------------
#define QPITCH 144
#define VPITCH 80
#define SM_K 18432
#define SM_V 55296
#define SM_T 96256
#define ATTN_SMEM 100352

__global__ void __launch_bounds__(256, 2) attn_mma_kernel(const int* __restrict__ edge_id) {
    extern __shared__ char smb[];
    __half* Qs = (__half*)smb;
    float* Ts = (float*)(smb + SM_T);
    uint32_t sbase = smem_to_u32(smb);

    int h = blockIdx.y;
    int i0 = blockIdx.x * 64;
    int tid = threadIdx.x, wid = tid >> 5, lane = tid & 31;
    int gid = lane >> 2, qt = lane & 3;
    int ngrp = wid >> 2, wg = wid & 3;
    const uint32_t ones2 = 0x3C003C00u;

    auto load_kv = [&](int j0, int buf) {
        int row = tid >> 2, q4 = tid & 3;
        {   // K: 64 j-rows x [kh(64)|kl(64)]
            int half_ = q4 >> 1, part = q4 & 1;
            const __half* src = g_sk + (size_t)(j0 + row) * KSPLIT
                                + half_ * 1024 + h * HDIM + part * 32;
            uint32_t dst = sbase + SM_K + buf * 18432 + row * 288 + half_ * 128 + part * 64;
            #pragma unroll
            for (int i = 0; i < 4; i++) cp16(dst + i * 16, src + i * 8);
        }
        {   // V: 128 d-rows x 64 j
            int vrow = tid >> 1, part = tid & 1;
            const __half* src = g_svt + (size_t)(h * 128 + vrow) * L_SEQ
                                + j0 + part * 32;
            uint32_t dst = sbase + SM_V + buf * 20480 + vrow * 160 + part * 64;
            #pragma unroll
            for (int i = 0; i < 4; i++) cp16(dst + i * 16, src + i * 8);
        }
    };

    {   // Q tile (64 rows x [qh|ql]) + Ts
        int row = tid >> 2, q4 = tid & 3;
        int half_ = q4 >> 1, part = q4 & 1;
        const __half* src = g_sq + (size_t)(i0 + row) * KSPLIT
                            + half_ * 512 + h * HDIM + part * 32;
        uint32_t dst = sbase + row * 288 + half_ * 128 + part * 64;
        #pragma unroll
        for (int i = 0; i < 4; i++) cp16(dst + i * 16, src + i * 8);
        *(float4*)(Ts + row * 16 + q4 * 4) =
            *(const float4*)(g_ts + ((size_t)h * L_SEQ + i0 + row) * 16 + q4 * 4);
    }
    CP_COMMIT;
    load_kv(0, 0);
    CP_COMMIT;
    asm volatile("cp.async.wait_group 1;" ::: "memory");
    __syncthreads();

    int r0 = wg * 16 + gid;                    // 0..63
    uint32_t qh[4][4], ql[4][4];
    #pragma unroll
    for (int kc = 0; kc < 4; kc++) {
        uint2 lo = *(const uint2*)&Qs[r0 * QPITCH + kc * 16 + qt * 4];
        uint2 hi = *(const uint2*)&Qs[(r0 + 8) * QPITCH + kc * 16 + qt * 4];
        qh[kc][0] = lo.x; qh[kc][1] = hi.x; qh[kc][2] = lo.y; qh[kc][3] = hi.y;
        uint2 lo2 = *(const uint2*)&Qs[r0 * QPITCH + 64 + kc * 16 + qt * 4];
        uint2 hi2 = *(const uint2*)&Qs[(r0 + 8) * QPITCH + 64 + kc * 16 + qt * 4];
        ql[kc][0] = lo2.x; ql[kc][1] = hi2.x; ql[kc][2] = lo2.y; ql[kc][3] = hi2.y;
    }

    float o[8][4] = {};
    float rm0 = -1e30f, rm1 = -1e30f, rl0 = 0.f, rl1 = 0.f;
    const float* T0 = Ts + r0 * 16;
    const float* T1 = T0 + 128;

    for (int t = 0; t < 32; t++) {
        int cur = t & 1;
        if (t + 1 < 32) {
            load_kv((t + 1) * 64, cur ^ 1);
            CP_COMMIT;
            asm volatile("cp.async.wait_group 1;" ::: "memory");
        } else {
            asm volatile("cp.async.wait_group 0;" ::: "memory");
        }
        __syncthreads();
        const __half* Ks = (const __half*)(smb + SM_K + cur * 18432);
        const __half* Vt = (const __half*)(smb + SM_V + cur * 20480);
        int j0 = t * 64;

        // ---- edge-id prefetch (group's 32-j half) ----
        int grow0 = i0 + r0, grow1 = grow0 + 8;
        int2 e0r[4], e1r[4];
        #pragma unroll
        for (int ntl = 0; ntl < 4; ntl++) {
            int col = j0 + (ngrp * 4 + ntl) * 8 + qt * 2;
            e0r[ntl] = *(const int2*)&edge_id[(size_t)grow0 * L_SEQ + col];
            e1r[ntl] = *(const int2*)&edge_id[(size_t)grow1 * L_SEQ + col];
        }

        // ---- S (group's 32 j-cols): hi fp32-acc, crosses fp16-acc ----
        float sa[4][4] = {};
        uint32_t sc[4][2] = {};
        #pragma unroll
        for (int kc = 0; kc < 4; kc++) {
            #pragma unroll
            for (int ntl = 0; ntl < 4; ntl++) {
                int brow = (ngrp * 4 + ntl) * 8 + gid;
                uint2 kh = *(const uint2*)&Ks[brow * QPITCH + kc * 16 + qt * 4];
                uint2 kl = *(const uint2*)&Ks[brow * QPITCH + 64 + kc * 16 + qt * 4];
                mma16816(sa[ntl], qh[kc], kh.x, kh.y);
                mma16816h(sc[ntl], ql[kc], kh.x, kh.y);
                mma16816h(sc[ntl], qh[kc], kl.x, kl.y);
            }
        }
        #pragma unroll
        for (int ntl = 0; ntl < 4; ntl++) {
            float2 ca = unph(sc[ntl][0]);
            float2 cb = unph(sc[ntl][1]);
            sa[ntl][0] += ca.x + T0[e0r[ntl].x];
            sa[ntl][1] += ca.y + T0[e0r[ntl].y];
            sa[ntl][2] += cb.x + T1[e1r[ntl].x];
            sa[ntl][3] += cb.y + T1[e1r[ntl].y];
        }

        // ---- online softmax (base 2, group-local) ----
        float mx0 = -1e30f, mx1 = -1e30f;
        #pragma unroll
        for (int ntl = 0; ntl < 4; ntl++) {
            mx0 = fmaxf(mx0, fmaxf(sa[ntl][0], sa[ntl][1]));
            mx1 = fmaxf(mx1, fmaxf(sa[ntl][2], sa[ntl][3]));
        }
        mx0 = fmaxf(mx0, __shfl_xor_sync(0xffffffffu, mx0, 1));
        mx0 = fmaxf(mx0, __shfl_xor_sync(0xffffffffu, mx0, 2));
        mx1 = fmaxf(mx1, __shfl_xor_sync(0xffffffffu, mx1, 1));
        mx1 = fmaxf(mx1, __shfl_xor_sync(0xffffffffu, mx1, 2));
        float mn0 = fmaxf(rm0, mx0), mn1 = fmaxf(rm1, mx1);
        float c0 = ex2f(rm0 - mn0), c1 = ex2f(rm1 - mn1);
        rm0 = mn0; rm1 = mn1;

        // P = 2^(s - m) as packed fp16 A-fragments; row sums via MMA
        uint32_t ph[2][4];
        float ls[4] = {};
        #pragma unroll
        for (int kcp = 0; kcp < 2; kcp++) {
            const float* t0v = sa[2 * kcp];
            const float* t1v = sa[2 * kcp + 1];
            ph[kcp][0] = ex2h2(t0v[0] - mn0, t0v[1] - mn0);
            ph[kcp][1] = ex2h2(t0v[2] - mn1, t0v[3] - mn1);
            ph[kcp][2] = ex2h2(t1v[0] - mn0, t1v[1] - mn0);
            ph[kcp][3] = ex2h2(t1v[2] - mn1, t1v[3] - mn1);
            mma16816(ls, ph[kcp], ones2, ones2);
        }
        rl0 = rl0 * c0 + ls[0];
        rl1 = rl1 * c1 + ls[2];
        #pragma unroll
        for (int dt = 0; dt < 8; dt++) {
            o[dt][0] *= c0; o[dt][1] *= c0;
            o[dt][2] *= c1; o[dt][3] *= c1;
        }

        // ---- PV over group's 32 j: O += ph*vh (fp32) + ph*vl (fp16) ----
        uint32_t oc[8][2] = {};
        #pragma unroll
        for (int kcp = 0; kcp < 2; kcp++) {
            int vc = ngrp * 32 + kcp * 16 + qt * 4;
            #pragma unroll
            for (int dt = 0; dt < 8; dt++) {
                int vrh = dt * 8 + gid;
                uint2 vh = *(const uint2*)&Vt[vrh * VPITCH + vc];
                uint2 vl = *(const uint2*)&Vt[(64 + vrh) * VPITCH + vc];
                mma16816(o[dt], ph[kcp], vh.x, vh.y);
                mma16816h(oc[dt], ph[kcp], vl.x, vl.y);
            }
        }
        #pragma unroll
        for (int dt = 0; dt < 8; dt++) {
            float2 ca = unph(oc[dt][0]);
            float2 cb = unph(oc[dt][1]);
            o[dt][0] += ca.x; o[dt][1] += ca.y;
            o[dt][2] += cb.x; o[dt][3] += cb.y;
        }
        __syncthreads();
    }

    // ---- combine the two n-groups' partial softmax states ----
    __syncthreads();
    float* co = (float*)(smb + SM_K);            // [64][66]
    float* cm = (float*)(smb + SM_K + 16896);    // [64]
    float* cl = (float*)(smb + SM_K + 17152);    // [64]
    if (ngrp == 1) {
        if (qt == 0) {
            cm[r0] = rm0; cm[r0 + 8] = rm1;
            cl[r0] = rl0; cl[r0 + 8] = rl1;
        }
        #pragma unroll
        for (int dt = 0; dt < 8; dt++) {
            int c = dt * 8 + qt * 2;
            *(float2*)&co[r0 * 66 + c]       = make_float2(o[dt][0], o[dt][1]);
            *(float2*)&co[(r0 + 8) * 66 + c] = make_float2(o[dt][2], o[dt][3]);
        }
    }
    __syncthreads();
    if (ngrp == 0) {
        float m1a = cm[r0], l1a = cl[r0];
        float m1b = cm[r0 + 8], l1b = cl[r0 + 8];
        float M0 = fmaxf(rm0, m1a), M1 = fmaxf(rm1, m1b);
        float a0 = ex2f(rm0 - M0), b0 = ex2f(m1a - M0);
        float a1 = ex2f(rm1 - M1), b1 = ex2f(m1b - M1);
        float inv0 = 1.0f / (rl0 * a0 + l1a * b0);
        float inv1 = 1.0f / (rl1 * a1 + l1b * b1);
        __half* dst0 = g_actx + (size_t)(i0 + r0) * KSPLIT + h * HDIM;
        __half* dst1 = g_actx + (size_t)(i0 + r0 + 8) * KSPLIT + h * HDIM;
        #pragma unroll
        for (int dt = 0; dt < 8; dt++) {
            int c = dt * 8 + qt * 2;
            int cp_ = permute_paircol(c);
            float v0 = (o[dt][0] * a0 + co[r0 * 66 + c] * b0) * inv0;
            float v1 = (o[dt][1] * a0 + co[r0 * 66 + c + 1] * b0) * inv0;
            float w0 = (o[dt][2] * a1 + co[(r0 + 8) * 66 + c] * b1) * inv1;
            float w1 = (o[dt][3] * a1 + co[(r0 + 8) * 66 + c + 1] * b1) * inv1;
            store_split(dst0 + cp_, v0, v1, 1);
            store_split(dst1 + cp_, w0, w1, 1);
        }
    }
}

// ---------------------------------------------------------------------------
extern "C" void kernel_launch(void* const* d_in, const int* in_sizes, int n_in,
                              void* d_out, int out_size)
{
    const float* query = (const float*)d_in[0];
    const float* key   = (const float*)d_in[1];
    const float* value = (const float*)d_in[2];
    const int*   eid   = (const int*)d_in[3];
    const float* w_in  = (const float*)d_in[4];
    const float* b_in  = (const float*)d_in[5];
    const float* w_out = (const float*)d_in[6];
    const float* b_out = (const float*)d_in[7];
    const float* embK  = (const float*)d_in[8];
    float* out = (float*)d_out;

    // launch 0: all splits fused
    split_all<<<16384, 256>>>(query, key, value, w_in, w_out);

    // launch 1: QKV projection (q log2-scaled)
    dim3 qkv_grid(L_SEQ / 128, 12);
    gemm_qkv_kernel<<<qkv_grid, 256>>>(b_in);

    // launch 2: V transpose/split + type scores
    tsvt_kernel<<<2304, 256>>>(embK);

    // launch 3: flash attention — i-tile 64, 2 CTAs/SM
    cudaFuncSetAttribute(attn_mma_kernel, cudaFuncAttributeMaxDynamicSharedMemorySize,
                         ATTN_SMEM);
    dim3 attn_grid(L_SEQ / 64, NHEAD);
    attn_mma_kernel<<<attn_grid, 256, ATTN_SMEM>>>(eid);

    // launch 4: out projection
    dim3 out_grid(L_SEQ / 128, 4);
    gemm_out_kernel<<<out_grid, 256>>>(b_out, out);
}

// round 10
// speedup vs baseline: 1.2012x; 1.1272x over previous
#include <cuda_runtime.h>
#include <cuda_fp16.h>
#include <cstdint>

#define L_SEQ 2048
#define EMB   512
#define NHEAD 8
#define HDIM  64
#define NTYPE 10
#define KSPLIT 1536      // 3 * EMB  (activations [hi|lo|hi], weights [hi|hi|lo])
#define QSCALE 0.18033688011112042f   // 0.125 * log2(e)

// ---------------------------------------------------------------------------
__device__ float g_v[L_SEQ * EMB];
__device__ float g_ts[NHEAD * L_SEQ * 16];

__device__ __half g_aq[L_SEQ * KSPLIT];
__device__ __half g_ak[L_SEQ * KSPLIT];
__device__ __half g_av[L_SEQ * KSPLIT];
__device__ __half g_wqkv[3 * EMB * KSPLIT];
__device__ __half g_wo[EMB * KSPLIT];     // k-cols PAIR-PERMUTED
__device__ __half g_sq[L_SEQ * KSPLIT];   // projected q (log2-scaled), hlh, permuted
__device__ __half g_sk[L_SEQ * KSPLIT];   // projected k, hhl, permuted
__device__ __half g_actx[L_SEQ * KSPLIT]; // ctx, hlh, permuted
__device__ __half g_svt[NHEAD * 2 * HDIM * L_SEQ];  // [h][vh|vl][j] permuted pairs

__device__ __forceinline__ int permute_paircol(int col) {   // col even
    int p = (col >> 1) & 7;
    return (col & ~15) + (((p & 3) * 2 + (p >> 2)) << 1);
}

// ---------------------------------------------------------------------------
__device__ __forceinline__ uint32_t packh(float lo, float hi) {
    uint32_t r;
    asm("cvt.rn.f16x2.f32 %0, %1, %2;" : "=r"(r) : "f"(hi), "f"(lo));
    return r;
}
__device__ __forceinline__ uint32_t ex2h2(float lo, float hi) {
    uint32_t r;
    asm("cvt.rn.f16x2.f32 %0, %1, %2;" : "=r"(r) : "f"(hi), "f"(lo));
    asm("ex2.approx.f16x2 %0, %0;" : "+r"(r));
    return r;
}
__device__ __forceinline__ float ex2f(float x) {
    float r;
    asm("ex2.approx.f32 %0, %1;" : "=f"(r) : "f"(x));
    return r;
}
__device__ __forceinline__ float2 unph(uint32_t u) {
    __half2 h = *reinterpret_cast<__half2*>(&u);
    return __half22float2(h);
}
__device__ __forceinline__ uint32_t smem_to_u32(const void* p) {
    uint32_t a;
    asm("{ .reg .u64 t; cvta.to.shared.u64 t, %1; cvt.u32.u64 %0, t; }"
        : "=r"(a) : "l"(p));
    return a;
}
__device__ __forceinline__ void mma16816(float* d, const uint32_t* a,
                                         uint32_t b0, uint32_t b1) {
    asm volatile(
        "mma.sync.aligned.m16n8k16.row.col.f32.f16.f16.f32 "
        "{%0,%1,%2,%3}, {%4,%5,%6,%7}, {%8,%9}, {%0,%1,%2,%3};"
        : "+f"(d[0]), "+f"(d[1]), "+f"(d[2]), "+f"(d[3])
        : "r"(a[0]), "r"(a[1]), "r"(a[2]), "r"(a[3]), "r"(b0), "r"(b1));
}
__device__ __forceinline__ void mma16816h(uint32_t* c, const uint32_t* a,
                                          uint32_t b0, uint32_t b1) {
    asm volatile(
        "mma.sync.aligned.m16n8k16.row.col.f16.f16.f16.f16 "
        "{%0,%1}, {%2,%3,%4,%5}, {%6,%7}, {%0,%1};"
        : "+r"(c[0]), "+r"(c[1])
        : "r"(a[0]), "r"(a[1]), "r"(a[2]), "r"(a[3]), "r"(b0), "r"(b1));
}
__device__ __forceinline__ void cp16(uint32_t s, const void* g) {
    asm volatile("cp.async.cg.shared.global [%0], [%1], 16;"
                 :: "r"(s), "l"(g) : "memory");
}
#define CP_COMMIT asm volatile("cp.async.commit_group;" ::: "memory")

__device__ __forceinline__ void store_split(__half* d, float v0, float v1,
                                            int mode) {
    float h0 = __half2float(__float2half(v0));
    float h1 = __half2float(__float2half(v1));
    uint32_t hh = packh(h0, h1), ll = packh(v0 - h0, v1 - h1);
    *(uint32_t*)d          = hh;
    *(uint32_t*)(d + 512)  = (mode == 1) ? ll : hh;
    *(uint32_t*)(d + 1024) = (mode == 1) ? hh : ll;
}

// ---------------------------------------------------------------------------
// ONE fused split kernel
// ---------------------------------------------------------------------------
__global__ __launch_bounds__(256) void split_all(
    const float* __restrict__ q, const float* __restrict__ k,
    const float* __restrict__ v, const float* __restrict__ w,
    const float* __restrict__ wo) {
    int idx = blockIdx.x * 256 + threadIdx.x;
    if (idx < 3145728) {
        const float* src = idx < 1048576 ? q : (idx < 2097152 ? k : v);
        __half* dst = idx < 1048576 ? g_aq : (idx < 2097152 ? g_ak : g_av);
        int li = idx & 1048575;
        int r = li >> 9, c = li & 511;
        float x = src[li];
        __half h = __float2half(x);
        __half l = __float2half(x - __half2float(h));
        __half* yr = dst + (size_t)r * KSPLIT;
        yr[c] = h; yr[512 + c] = l; yr[1024 + c] = h;
    } else if (idx < 3932160) {
        int li = idx - 3145728;
        int r = li >> 9, c = li & 511;
        float x = w[li];
        __half h = __float2half(x);
        __half l = __float2half(x - __half2float(h));
        __half* yr = g_wqkv + (size_t)r * KSPLIT;
        yr[c] = h; yr[512 + c] = h; yr[1024 + c] = l;
    } else {
        int li = idx - 3932160;
        int r = li >> 9, c = li & 511;
        float x = wo[li];
        __half h = __float2half(x);
        __half l = __float2half(x - __half2float(h));
        int cp_ = permute_paircol(c & ~1) + (c & 1);
        __half* yr = g_wo + (size_t)r * KSPLIT;
        yr[cp_] = h; yr[512 + cp_] = h; yr[1024 + cp_] = l;
    }
}

// ---------------------------------------------------------------------------
// GEMM: 64 x (32*NF) block tile, 8 warps (2x4), warp tile 32 x (8*NF).
// ~90 regs -> 2 CTAs/SM (4 warps/SMSP). cp.async double-buffered.
// ---------------------------------------------------------------------------
template <int NF>
__device__ __forceinline__ void gemm_core(const __half* __restrict__ A,
                                          const __half* __restrict__ B,
                                          const float* __restrict__ bias,
                                          float* __restrict__ Cf,
                                          __half* __restrict__ Cs,
                                          int cn0, int m0, float scale, int mode) {
    constexpr int BROWS = 32 * NF;
    __shared__ __half As[2][64 * 40];
    __shared__ __half Bs[2][BROWS * 40];
    int tid = threadIdx.x, wid = tid >> 5, lane = tid & 31;
    int gid = lane >> 2, qt = lane & 3;
    int wm = wid >> 2, wn = wid & 3;

    float acc[2][NF][4] = {};
    uint32_t acch[2][NF][2] = {};
    int lrA = tid >> 2, lcA = (tid & 3) * 8;
    const __half* Ap = A + (size_t)(m0 + lrA) * KSPLIT + lcA;
    int lrB = (NF == 4) ? (tid >> 1) : (tid >> 2);
    int lcB = (NF == 4) ? ((tid & 1) * 16) : ((tid & 3) * 8);
    const __half* Bp = B + (size_t)lrB * KSPLIT + lcB;
    uint32_t sA[2] = {smem_to_u32(&As[0][lrA * 40 + lcA]),
                      smem_to_u32(&As[1][lrA * 40 + lcA])};
    uint32_t sB[2] = {smem_to_u32(&Bs[0][lrB * 40 + lcB]),
                      smem_to_u32(&Bs[1][lrB * 40 + lcB])};

    cp16(sA[0], Ap);
    cp16(sB[0], Bp);
    if (NF == 4) cp16(sB[0] + 16, Bp + 8);
    CP_COMMIT;

    for (int kt = 0; kt < KSPLIT / 32; kt++) {
        int cur = kt & 1;
        if (kt + 1 < KSPLIT / 32) {
            int nx = cur ^ 1;
            const __half* a = Ap + (kt + 1) * 32;
            const __half* b = Bp + (kt + 1) * 32;
            cp16(sA[nx], a);
            cp16(sB[nx], b);
            if (NF == 4) cp16(sB[nx] + 16, b + 8);
            CP_COMMIT;
            asm volatile("cp.async.wait_group 1;" ::: "memory");
        } else {
            asm volatile("cp.async.wait_group 0;" ::: "memory");
        }
        __syncthreads();
        bool hi_term = (kt < 16);
        #pragma unroll
        for (int kc = 0; kc < 2; kc++) {
            uint32_t a[2][4];
            #pragma unroll
            for (int mf = 0; mf < 2; mf++) {
                int r = wm * 32 + mf * 16 + gid;
                int c = kc * 16 + qt * 2;
                a[mf][0] = *(const uint32_t*)&As[cur][r * 40 + c];
                a[mf][1] = *(const uint32_t*)&As[cur][(r + 8) * 40 + c];
                a[mf][2] = *(const uint32_t*)&As[cur][r * 40 + c + 8];
                a[mf][3] = *(const uint32_t*)&As[cur][(r + 8) * 40 + c + 8];
            }
            #pragma unroll
            for (int nf = 0; nf < NF; nf++) {
                int n = wn * (8 * NF) + nf * 8 + gid;
                int c = kc * 16 + qt * 2;
                uint32_t b0 = *(const uint32_t*)&Bs[cur][n * 40 + c];
                uint32_t b1 = *(const uint32_t*)&Bs[cur][n * 40 + c + 8];
                if (hi_term) {
                    #pragma unroll
                    for (int mf = 0; mf < 2; mf++)
                        mma16816(acc[mf][nf], a[mf], b0, b1);
                } else {
                    #pragma unroll
                    for (int mf = 0; mf < 2; mf++)
                        mma16816h(acch[mf][nf], a[mf], b0, b1);
                }
            }
        }
        __syncthreads();
    }
    #pragma unroll
    for (int mf = 0; mf < 2; mf++) {
        int r = m0 + wm * 32 + mf * 16 + gid;
        #pragma unroll
        for (int nf = 0; nf < NF; nf++) {
            int cb = wn * (8 * NF) + nf * 8 + qt * 2;
            float b0 = __ldg(bias + cb), b1 = __ldg(bias + cb + 1);
            float2 c0 = unph(acch[mf][nf][0]);
            float2 c1 = unph(acch[mf][nf][1]);
            float v00 = scale * (acc[mf][nf][0] + c0.x + b0);
            float v01 = scale * (acc[mf][nf][1] + c0.y + b1);
            float v10 = scale * (acc[mf][nf][2] + c1.x + b0);
            float v11 = scale * (acc[mf][nf][3] + c1.y + b1);
            int col = cn0 + cb;
            if (mode == 0) {
                *(float2*)&Cf[(size_t)r * EMB + col]       = make_float2(v00, v01);
                *(float2*)&Cf[(size_t)(r + 8) * EMB + col] = make_float2(v10, v11);
            } else {
                int colp = permute_paircol(col);
                store_split(Cs + (size_t)r * KSPLIT + colp, v00, v01, mode);
                store_split(Cs + (size_t)(r + 8) * KSPLIT + colp, v10, v11, mode);
            }
        }
    }
}

__global__ void __launch_bounds__(256, 2) gemm_qkv_kernel(const float* __restrict__ bias) {
    int m0 = blockIdx.x * 64;
    int nt = blockIdx.y;          // 0..11
    int sect = nt >> 2;
    int cn0 = (nt & 3) * 128;
    const __half* Bw = g_wqkv + (size_t)nt * 128 * KSPLIT;
    if (sect == 0)
        gemm_core<4>(g_aq, Bw, bias + nt * 128, nullptr, g_sq, cn0, m0, QSCALE, 1);
    else if (sect == 1)
        gemm_core<4>(g_ak, Bw, bias + nt * 128, nullptr, g_sk, cn0, m0, 1.0f, 2);
    else
        gemm_core<4>(g_av, Bw, bias + nt * 128, g_v, nullptr, cn0, m0, 1.0f, 0);
}
__global__ void __launch_bounds__(256, 2) gemm_out_kernel(const float* __restrict__ bias,
                                                          float* __restrict__ C) {
    gemm_core<2>(g_actx, g_wo + (size_t)blockIdx.y * 64 * KSPLIT,
                 bias + blockIdx.y * 64, C, nullptr, blockIdx.y * 64,
                 blockIdx.x * 64, 1.0f, 0);
}

// ---------------------------------------------------------------------------
// Fused: V split+transpose (blocks 0..255) + type_scores (blocks 256..2303)
// ---------------------------------------------------------------------------
__global__ __launch_bounds__(256) void tsvt_kernel(const float* __restrict__ edge_embs) {
    __shared__ float sh[64 * 68];
    int tid = threadIdx.x;
    if (blockIdx.x < 256) {
        int h = blockIdx.x >> 5, j0 = (blockIdx.x & 31) * 64;
        {
            int row = tid >> 2, cg = (tid & 3) * 16;
            const float* src = g_v + (size_t)(j0 + row) * EMB + h * HDIM + cg;
            #pragma unroll
            for (int i = 0; i < 4; i++)
                *(float4*)&sh[row * 68 + cg + i * 4] = *(const float4*)(src + i * 4);
        }
        __syncthreads();
        int d = tid >> 2, jg = (tid & 3) * 16;
        uint32_t hw[8], lw[8];
        #pragma unroll
        for (int p = 0; p < 8; p++) {
            float v0 = sh[(jg + 2 * p) * 68 + d], v1 = sh[(jg + 2 * p + 1) * 68 + d];
            float h0 = __half2float(__float2half(v0));
            float h1 = __half2float(__float2half(v1));
            hw[p] = packh(h0, h1);
            lw[p] = packh(v0 - h0, v1 - h1);
        }
        __half* dsth = g_svt + ((size_t)(h * 128 + d) * L_SEQ + j0 + jg);
        __half* dstl = g_svt + ((size_t)(h * 128 + 64 + d) * L_SEQ + j0 + jg);
        *(uint4*)dsth       = make_uint4(hw[0], hw[4], hw[1], hw[5]);
        *(uint4*)(dsth + 8) = make_uint4(hw[2], hw[6], hw[3], hw[7]);
        *(uint4*)dstl       = make_uint4(lw[0], lw[4], lw[1], lw[5]);
        *(uint4*)(dstl + 8) = make_uint4(lw[2], lw[6], lw[3], lw[7]);
    } else {
        float* emb = sh;
        for (int i = tid; i < NTYPE * HDIM; i += 256) emb[i] = edge_embs[i];
        __syncthreads();
        int warp = (blockIdx.x - 256) * 8 + (tid >> 5);
        int lane = tid & 31;
        int h = warp >> 11, i = warp & (L_SEQ - 1);
        int pw = lane & 7;
        int colp = (lane >> 3) * 16 + ((pw & 3) * 2 + (pw >> 2)) * 2;
        const __half* qr = g_sq + (size_t)i * KSPLIT + h * HDIM + colp;
        float2 qh = __half22float2(*(const __half2*)qr);
        float2 ql = __half22float2(*(const __half2*)(qr + 512));
        float2 qv = make_float2(qh.x + ql.x, qh.y + ql.y);
        float s[NTYPE];
        #pragma unroll
        for (int t = 0; t < NTYPE; t++) {
            float2 e = *(const float2*)(emb + t * HDIM + lane * 2);
            s[t] = qv.x * e.x + qv.y * e.y;
        }
        #pragma unroll
        for (int off = 16; off > 0; off >>= 1)
            #pragma unroll
            for (int t = 0; t < NTYPE; t++)
                s[t] += __shfl_xor_sync(0xffffffffu, s[t], off);
        if (lane == 0) {
            float* dst = g_ts + (size_t)warp * 16;
            #pragma unroll
            for (int t = 0; t < NTYPE; t++) dst[t] = s[t];
        }
    }
}

// ---------------------------------------------------------------------------
// Flash attention: i-tile 64, 8 warps = 4 row-warps x 2 n-groups, 2 CTAs/SM.
// S = qh*kh (fp32) + ql*kh (fp16); k_lo term dropped. kh-only K tiles.
// smem: Q 18432 @0 (pitch 288B), K 2x9216 @18432 (pitch 144B),
//       V 2x20480 @36864 (pitch 160B), Ts 4096 @77824. total 81920.
// ---------------------------------------------------------------------------
#define QPITCH 144   // halfs
#define KPITCH 72    // halfs
#define VPITCH 80    // halfs
#define SM_K 18432
#define SM_V 36864
#define SM_T 77824
#define ATTN_SMEM 81920

__global__ void __launch_bounds__(256, 2) attn_mma_kernel(const int* __restrict__ edge_id) {
    extern __shared__ char smb[];
    __half* Qs = (__half*)smb;
    float* Ts = (float*)(smb + SM_T);
    uint32_t sbase = smem_to_u32(smb);

    int h = blockIdx.y;
    int i0 = blockIdx.x * 64;
    int tid = threadIdx.x, wid = tid >> 5, lane = tid & 31;
    int gid = lane >> 2, qt = lane & 3;
    int ngrp = wid >> 2, wg = wid & 3;
    const uint32_t ones2 = 0x3C003C00u;

    auto load_kv = [&](int j0, int buf) {
        {   // K: 64 j-rows x kh(64 halfs), pitch 144B; 2 cp16/thread
            int row = tid >> 2, part = tid & 3;
            const __half* src = g_sk + (size_t)(j0 + row) * KSPLIT
                                + h * HDIM + part * 16;
            uint32_t dst = sbase + SM_K + buf * 9216 + row * 144 + part * 32;
            cp16(dst, src); cp16(dst + 16, src + 8);
        }
        {   // V: 128 d-rows x 64 j; 4 cp16/thread
            int vrow = tid >> 1, part = tid & 1;
            const __half* src = g_svt + (size_t)(h * 128 + vrow) * L_SEQ
                                + j0 + part * 32;
            uint32_t dst = sbase + SM_V + buf * 20480 + vrow * 160 + part * 64;
            #pragma unroll
            for (int i = 0; i < 4; i++) cp16(dst + i * 16, src + i * 8);
        }
    };

    {   // Q tile (64 rows x [qh|ql]) + Ts
        int row = tid >> 2, q4 = tid & 3;
        int half_ = q4 >> 1, part = q4 & 1;
        const __half* src = g_sq + (size_t)(i0 + row) * KSPLIT
                            + half_ * 512 + h * HDIM + part * 32;
        uint32_t dst = sbase + row * 288 + half_ * 128 + part * 64;
        #pragma unroll
        for (int i = 0; i < 4; i++) cp16(dst + i * 16, src + i * 8);
        *(float4*)(Ts + row * 16 + q4 * 4) =
            *(const float4*)(g_ts + ((size_t)h * L_SEQ + i0 + row) * 16 + q4 * 4);
    }
    CP_COMMIT;
    load_kv(0, 0);
    CP_COMMIT;
    asm volatile("cp.async.wait_group 1;" ::: "memory");
    __syncthreads();

    int r0 = wg * 16 + gid;                    // 0..63
    uint32_t qh[4][4], ql[4][4];
    #pragma unroll
    for (int kc = 0; kc < 4; kc++) {
        uint2 lo = *(const uint2*)&Qs[r0 * QPITCH + kc * 16 + qt * 4];
        uint2 hi = *(const uint2*)&Qs[(r0 + 8) * QPITCH + kc * 16 + qt * 4];
        qh[kc][0] = lo.x; qh[kc][1] = hi.x; qh[kc][2] = lo.y; qh[kc][3] = hi.y;
        uint2 lo2 = *(const uint2*)&Qs[r0 * QPITCH + 64 + kc * 16 + qt * 4];
        uint2 hi2 = *(const uint2*)&Qs[(r0 + 8) * QPITCH + 64 + kc * 16 + qt * 4];
        ql[kc][0] = lo2.x; ql[kc][1] = hi2.x; ql[kc][2] = lo2.y; ql[kc][3] = hi2.y;
    }

    float o[8][4] = {};
    float rm0 = -1e30f, rm1 = -1e30f, rl0 = 0.f, rl1 = 0.f;
    const float* T0 = Ts + r0 * 16;
    const float* T1 = T0 + 128;

    for (int t = 0; t < 32; t++) {
        int cur = t & 1;
        if (t + 1 < 32) {
            load_kv((t + 1) * 64, cur ^ 1);
            CP_COMMIT;
            asm volatile("cp.async.wait_group 1;" ::: "memory");
        } else {
            asm volatile("cp.async.wait_group 0;" ::: "memory");
        }
        __syncthreads();
        const __half* Ks = (const __half*)(smb + SM_K + cur * 9216);
        const __half* Vt = (const __half*)(smb + SM_V + cur * 20480);
        int j0 = t * 64;

        // ---- edge-id prefetch ----
        int grow0 = i0 + r0, grow1 = grow0 + 8;
        int2 e0r[4], e1r[4];
        #pragma unroll
        for (int ntl = 0; ntl < 4; ntl++) {
            int col = j0 + (ngrp * 4 + ntl) * 8 + qt * 2;
            e0r[ntl] = *(const int2*)&edge_id[(size_t)grow0 * L_SEQ + col];
            e1r[ntl] = *(const int2*)&edge_id[(size_t)grow1 * L_SEQ + col];
        }

        // ---- S = qh*kh (fp32) + ql*kh (fp16) ----
        float sa[4][4] = {};
        uint32_t sc[4][2] = {};
        #pragma unroll
        for (int kc = 0; kc < 4; kc++) {
            #pragma unroll
            for (int ntl = 0; ntl < 4; ntl++) {
                int brow = (ngrp * 4 + ntl) * 8 + gid;
                uint2 kh = *(const uint2*)&Ks[brow * KPITCH + kc * 16 + qt * 4];
                mma16816(sa[ntl], qh[kc], kh.x, kh.y);
                mma16816h(sc[ntl], ql[kc], kh.x, kh.y);
            }
        }
        #pragma unroll
        for (int ntl = 0; ntl < 4; ntl++) {
            float2 ca = unph(sc[ntl][0]);
            float2 cb = unph(sc[ntl][1]);
            sa[ntl][0] += ca.x + T0[e0r[ntl].x];
            sa[ntl][1] += ca.y + T0[e0r[ntl].y];
            sa[ntl][2] += cb.x + T1[e1r[ntl].x];
            sa[ntl][3] += cb.y + T1[e1r[ntl].y];
        }

        // ---- online softmax (base 2) ----
        float mx0 = -1e30f, mx1 = -1e30f;
        #pragma unroll
        for (int ntl = 0; ntl < 4; ntl++) {
            mx0 = fmaxf(mx0, fmaxf(sa[ntl][0], sa[ntl][1]));
            mx1 = fmaxf(mx1, fmaxf(sa[ntl][2], sa[ntl][3]));
        }
        mx0 = fmaxf(mx0, __shfl_xor_sync(0xffffffffu, mx0, 1));
        mx0 = fmaxf(mx0, __shfl_xor_sync(0xffffffffu, mx0, 2));
        mx1 = fmaxf(mx1, __shfl_xor_sync(0xffffffffu, mx1, 1));
        mx1 = fmaxf(mx1, __shfl_xor_sync(0xffffffffu, mx1, 2));
        float mn0 = fmaxf(rm0, mx0), mn1 = fmaxf(rm1, mx1);
        bool skip = __all_sync(0xffffffffu, (mn0 == rm0) & (mn1 == rm1));

        // P = 2^(s - m) as packed fp16 A-fragments; row sums via MMA
        uint32_t ph[2][4];
        float ls[4] = {};
        #pragma unroll
        for (int kcp = 0; kcp < 2; kcp++) {
            const float* t0v = sa[2 * kcp];
            const float* t1v = sa[2 * kcp + 1];
            ph[kcp][0] = ex2h2(t0v[0] - mn0, t0v[1] - mn0);
            ph[kcp][1] = ex2h2(t0v[2] - mn1, t0v[3] - mn1);
            ph[kcp][2] = ex2h2(t1v[0] - mn0, t1v[1] - mn0);
            ph[kcp][3] = ex2h2(t1v[2] - mn1, t1v[3] - mn1);
            mma16816(ls, ph[kcp], ones2, ones2);
        }
        if (!skip) {
            float c0 = ex2f(rm0 - mn0), c1 = ex2f(rm1 - mn1);
            rl0 *= c0; rl1 *= c1;
            #pragma unroll
            for (int dt = 0; dt < 8; dt++) {
                o[dt][0] *= c0; o[dt][1] *= c0;
                o[dt][2] *= c1; o[dt][3] *= c1;
            }
            rm0 = mn0; rm1 = mn1;
        }
        rl0 += ls[0];
        rl1 += ls[2];

        // ---- PV over group's 32 j: O += ph*vh (fp32) + ph*vl (fp16) ----
        uint32_t oc[8][2] = {};
        #pragma unroll
        for (int kcp = 0; kcp < 2; kcp++) {
            int vc = ngrp * 32 + kcp * 16 + qt * 4;
            #pragma unroll
            for (int dt = 0; dt < 8; dt++) {
                int vrh = dt * 8 + gid;
                uint2 vh = *(const uint2*)&Vt[vrh * VPITCH + vc];
                uint2 vl = *(const uint2*)&Vt[(64 + vrh) * VPITCH + vc];
                mma16816(o[dt], ph[kcp], vh.x, vh.y);
                mma16816h(oc[dt], ph[kcp], vl.x, vl.y);
            }
        }
        #pragma unroll
        for (int dt = 0; dt < 8; dt++) {
            float2 ca = unph(oc[dt][0]);
            float2 cb = unph(oc[dt][1]);
            o[dt][0] += ca.x; o[dt][1] += ca.y;
            o[dt][2] += cb.x; o[dt][3] += cb.y;
        }
        __syncthreads();
    }

    // ---- combine the two n-groups (reuse K region: 18432B >= 17408) ----
    __syncthreads();
    float* co = (float*)(smb + SM_K);            // [64][66]
    float* cm = (float*)(smb + SM_K + 16896);    // [64]
    float* cl = (float*)(smb + SM_K + 17152);    // [64]
    if (ngrp == 1) {
        if (qt == 0) {
            cm[r0] = rm0; cm[r0 + 8] = rm1;
            cl[r0] = rl0; cl[r0 + 8] = rl1;
        }
        #pragma unroll
        for (int dt = 0; dt < 8; dt++) {
            int c = dt * 8 + qt * 2;
            *(float2*)&co[r0 * 66 + c]       = make_float2(o[dt][0], o[dt][1]);
            *(float2*)&co[(r0 + 8) * 66 + c] = make_float2(o[dt][2], o[dt][3]);
        }
    }
    __syncthreads();
    if (ngrp == 0) {
        float m1a = cm[r0], l1a = cl[r0];
        float m1b = cm[r0 + 8], l1b = cl[r0 + 8];
        float M0 = fmaxf(rm0, m1a), M1 = fmaxf(rm1, m1b);
        float a0 = ex2f(rm0 - M0), b0 = ex2f(m1a - M0);
        float a1 = ex2f(rm1 - M1), b1 = ex2f(m1b - M1);
        float inv0 = 1.0f / (rl0 * a0 + l1a * b0);
        float inv1 = 1.0f / (rl1 * a1 + l1b * b1);
        __half* dst0 = g_actx + (size_t)(i0 + r0) * KSPLIT + h * HDIM;
        __half* dst1 = g_actx + (size_t)(i0 + r0 + 8) * KSPLIT + h * HDIM;
        #pragma unroll
        for (int dt = 0; dt < 8; dt++) {
            int c = dt * 8 + qt * 2;
            int cp_ = permute_paircol(c);
            float v0 = (o[dt][0] * a0 + co[r0 * 66 + c] * b0) * inv0;
            float v1 = (o[dt][1] * a0 + co[r0 * 66 + c + 1] * b0) * inv0;
            float w0 = (o[dt][2] * a1 + co[(r0 + 8) * 66 + c] * b1) * inv1;
            float w1 = (o[dt][3] * a1 + co[(r0 + 8) * 66 + c + 1] * b1) * inv1;
            store_split(dst0 + cp_, v0, v1, 1);
            store_split(dst1 + cp_, w0, w1, 1);
        }
    }
}

// ---------------------------------------------------------------------------
extern "C" void kernel_launch(void* const* d_in, const int* in_sizes, int n_in,
                              void* d_out, int out_size)
{
    const float* query = (const float*)d_in[0];
    const float* key   = (const float*)d_in[1];
    const float* value = (const float*)d_in[2];
    const int*   eid   = (const int*)d_in[3];
    const float* w_in  = (const float*)d_in[4];
    const float* b_in  = (const float*)d_in[5];
    const float* w_out = (const float*)d_in[6];
    const float* b_out = (const float*)d_in[7];
    const float* embK  = (const float*)d_in[8];
    float* out = (float*)d_out;

    // launch 0: all splits fused
    split_all<<<16384, 256>>>(query, key, value, w_in, w_out);

    // launch 1: QKV projection — 64-row tiles, 2 CTAs/SM
    dim3 qkv_grid(L_SEQ / 64, 12);
    gemm_qkv_kernel<<<qkv_grid, 256>>>(b_in);

    // launch 2: V transpose/split + type scores
    tsvt_kernel<<<2304, 256>>>(embK);

    // launch 3: flash attention
    cudaFuncSetAttribute(attn_mma_kernel, cudaFuncAttributeMaxDynamicSharedMemorySize,
                         ATTN_SMEM);
    dim3 attn_grid(L_SEQ / 64, NHEAD);
    attn_mma_kernel<<<attn_grid, 256, ATTN_SMEM>>>(eid);

    // launch 4: out projection — 64x64 tiles, full chip
    dim3 out_grid(L_SEQ / 64, EMB / 64);
    gemm_out_kernel<<<out_grid, 256>>>(b_out, out);
}

// round 11
// speedup vs baseline: 1.5065x; 1.2541x over previous
#include <cuda_runtime.h>
#include <cuda_fp16.h>
#include <cstdint>

#define L_SEQ 2048
#define EMB   512
#define NHEAD 8
#define HDIM  64
#define NTYPE 10
#define KSPLIT 1536      // 3 * EMB  (activations [hi|lo|hi], weights [hi|hi|lo])
#define QSCALE 0.18033688011112042f   // 0.125 * log2(e)

// ---------------------------------------------------------------------------
__device__ float g_v[L_SEQ * EMB];
__device__ float g_ts[NHEAD * L_SEQ * 16];

__device__ __half g_aq[L_SEQ * KSPLIT];
__device__ __half g_ak[L_SEQ * KSPLIT];
__device__ __half g_av[L_SEQ * KSPLIT];
__device__ __half g_wqkv[3 * EMB * KSPLIT];
__device__ __half g_wo[EMB * KSPLIT];     // k-cols PAIR-PERMUTED
__device__ __half g_sq[L_SEQ * KSPLIT];   // projected q (log2-scaled), hlh, permuted
__device__ __half g_sk[L_SEQ * KSPLIT];   // projected k, hhl, permuted
__device__ __half g_actx[L_SEQ * KSPLIT]; // ctx, hlh, permuted
__device__ __half g_svt[NHEAD * 2 * HDIM * L_SEQ];  // [h][vh|vl][j] permuted pairs

__device__ __forceinline__ int permute_paircol(int col) {   // col even
    int p = (col >> 1) & 7;
    return (col & ~15) + (((p & 3) * 2 + (p >> 2)) << 1);
}

// ---------------------------------------------------------------------------
__device__ __forceinline__ uint32_t packh(float lo, float hi) {
    uint32_t r;
    asm("cvt.rn.f16x2.f32 %0, %1, %2;" : "=r"(r) : "f"(hi), "f"(lo));
    return r;
}
__device__ __forceinline__ uint32_t ex2h2(float lo, float hi) {
    uint32_t r;
    asm("cvt.rn.f16x2.f32 %0, %1, %2;" : "=r"(r) : "f"(hi), "f"(lo));
    asm("ex2.approx.f16x2 %0, %0;" : "+r"(r));
    return r;
}
__device__ __forceinline__ float ex2f(float x) {
    float r;
    asm("ex2.approx.f32 %0, %1;" : "=f"(r) : "f"(x));
    return r;
}
__device__ __forceinline__ float2 unph(uint32_t u) {
    __half2 h = *reinterpret_cast<__half2*>(&u);
    return __half22float2(h);
}
__device__ __forceinline__ uint32_t smem_to_u32(const void* p) {
    uint32_t a;
    asm("{ .reg .u64 t; cvta.to.shared.u64 t, %1; cvt.u32.u64 %0, t; }"
        : "=r"(a) : "l"(p));
    return a;
}
__device__ __forceinline__ void mma16816(float* d, const uint32_t* a,
                                         uint32_t b0, uint32_t b1) {
    asm volatile(
        "mma.sync.aligned.m16n8k16.row.col.f32.f16.f16.f32 "
        "{%0,%1,%2,%3}, {%4,%5,%6,%7}, {%8,%9}, {%0,%1,%2,%3};"
        : "+f"(d[0]), "+f"(d[1]), "+f"(d[2]), "+f"(d[3])
        : "r"(a[0]), "r"(a[1]), "r"(a[2]), "r"(a[3]), "r"(b0), "r"(b1));
}
__device__ __forceinline__ void mma16816h(uint32_t* c, const uint32_t* a,
                                          uint32_t b0, uint32_t b1) {
    asm volatile(
        "mma.sync.aligned.m16n8k16.row.col.f16.f16.f16.f16 "
        "{%0,%1}, {%2,%3,%4,%5}, {%6,%7}, {%0,%1};"
        : "+r"(c[0]), "+r"(c[1])
        : "r"(a[0]), "r"(a[1]), "r"(a[2]), "r"(a[3]), "r"(b0), "r"(b1));
}
__device__ __forceinline__ void cp16(uint32_t s, const void* g) {
    asm volatile("cp.async.cg.shared.global [%0], [%1], 16;"
                 :: "r"(s), "l"(g) : "memory");
}
#define CP_COMMIT asm volatile("cp.async.commit_group;" ::: "memory")

__device__ __forceinline__ void store_split(__half* d, float v0, float v1,
                                            int mode) {
    float h0 = __half2float(__float2half(v0));
    float h1 = __half2float(__float2half(v1));
    uint32_t hh = packh(h0, h1), ll = packh(v0 - h0, v1 - h1);
    *(uint32_t*)d          = hh;
    *(uint32_t*)(d + 512)  = (mode == 1) ? ll : hh;
    *(uint32_t*)(d + 1024) = (mode == 1) ? hh : ll;
}

// ---------------------------------------------------------------------------
// ONE fused split kernel
// ---------------------------------------------------------------------------
__global__ __launch_bounds__(256) void split_all(
    const float* __restrict__ q, const float* __restrict__ k,
    const float* __restrict__ v, const float* __restrict__ w,
    const float* __restrict__ wo) {
    int idx = blockIdx.x * 256 + threadIdx.x;
    if (idx < 3145728) {
        const float* src = idx < 1048576 ? q : (idx < 2097152 ? k : v);
        __half* dst = idx < 1048576 ? g_aq : (idx < 2097152 ? g_ak : g_av);
        int li = idx & 1048575;
        int r = li >> 9, c = li & 511;
        float x = src[li];
        __half h = __float2half(x);
        __half l = __float2half(x - __half2float(h));
        __half* yr = dst + (size_t)r * KSPLIT;
        yr[c] = h; yr[512 + c] = l; yr[1024 + c] = h;
    } else if (idx < 3932160) {
        int li = idx - 3145728;
        int r = li >> 9, c = li & 511;
        float x = w[li];
        __half h = __float2half(x);
        __half l = __float2half(x - __half2float(h));
        __half* yr = g_wqkv + (size_t)r * KSPLIT;
        yr[c] = h; yr[512 + c] = h; yr[1024 + c] = l;
    } else {
        int li = idx - 3932160;
        int r = li >> 9, c = li & 511;
        float x = wo[li];
        __half h = __float2half(x);
        int cp_ = permute_paircol(c & ~1) + (c & 1);
        g_wo[(size_t)r * KSPLIT + cp_] = h;   // out-proj uses hi-only now
    }
}

// ---------------------------------------------------------------------------
// GEMM: 64 x (32*NF) block tile, 8 warps, warp tile 32 x (8*NF).
// KITERS k-chunks of 32; first 16 fp32-acc (hi*hi), rest fp16-acc (crosses).
// ---------------------------------------------------------------------------
template <int NF, int KITERS>
__device__ __forceinline__ void gemm_core(const __half* __restrict__ A,
                                          const __half* __restrict__ B,
                                          const float* __restrict__ bias,
                                          float* __restrict__ Cf,
                                          __half* __restrict__ Cs,
                                          int cn0, int m0, float scale, int mode) {
    constexpr int BROWS = 32 * NF;
    __shared__ __half As[2][64 * 40];
    __shared__ __half Bs[2][BROWS * 40];
    int tid = threadIdx.x, wid = tid >> 5, lane = tid & 31;
    int gid = lane >> 2, qt = lane & 3;
    int wm = wid >> 2, wn = wid & 3;

    float acc[2][NF][4] = {};
    uint32_t acch[2][NF][2] = {};
    int lrA = tid >> 2, lcA = (tid & 3) * 8;
    const __half* Ap = A + (size_t)(m0 + lrA) * KSPLIT + lcA;
    int lrB = (NF == 4) ? (tid >> 1) : (tid >> 2);
    int lcB = (NF == 4) ? ((tid & 1) * 16) : ((tid & 3) * 8);
    const __half* Bp = B + (size_t)lrB * KSPLIT + lcB;
    uint32_t sA[2] = {smem_to_u32(&As[0][lrA * 40 + lcA]),
                      smem_to_u32(&As[1][lrA * 40 + lcA])};
    uint32_t sB[2] = {smem_to_u32(&Bs[0][lrB * 40 + lcB]),
                      smem_to_u32(&Bs[1][lrB * 40 + lcB])};

    cp16(sA[0], Ap);
    cp16(sB[0], Bp);
    if (NF == 4) cp16(sB[0] + 16, Bp + 8);
    CP_COMMIT;

    for (int kt = 0; kt < KITERS; kt++) {
        int cur = kt & 1;
        if (kt + 1 < KITERS) {
            int nx = cur ^ 1;
            const __half* a = Ap + (kt + 1) * 32;
            const __half* b = Bp + (kt + 1) * 32;
            cp16(sA[nx], a);
            cp16(sB[nx], b);
            if (NF == 4) cp16(sB[nx] + 16, b + 8);
            CP_COMMIT;
            asm volatile("cp.async.wait_group 1;" ::: "memory");
        } else {
            asm volatile("cp.async.wait_group 0;" ::: "memory");
        }
        __syncthreads();
        bool hi_term = (kt < 16);
        #pragma unroll
        for (int kc = 0; kc < 2; kc++) {
            uint32_t a[2][4];
            #pragma unroll
            for (int mf = 0; mf < 2; mf++) {
                int r = wm * 32 + mf * 16 + gid;
                int c = kc * 16 + qt * 2;
                a[mf][0] = *(const uint32_t*)&As[cur][r * 40 + c];
                a[mf][1] = *(const uint32_t*)&As[cur][(r + 8) * 40 + c];
                a[mf][2] = *(const uint32_t*)&As[cur][r * 40 + c + 8];
                a[mf][3] = *(const uint32_t*)&As[cur][(r + 8) * 40 + c + 8];
            }
            #pragma unroll
            for (int nf = 0; nf < NF; nf++) {
                int n = wn * (8 * NF) + nf * 8 + gid;
                int c = kc * 16 + qt * 2;
                uint32_t b0 = *(const uint32_t*)&Bs[cur][n * 40 + c];
                uint32_t b1 = *(const uint32_t*)&Bs[cur][n * 40 + c + 8];
                if (hi_term) {
                    #pragma unroll
                    for (int mf = 0; mf < 2; mf++)
                        mma16816(acc[mf][nf], a[mf], b0, b1);
                } else {
                    #pragma unroll
                    for (int mf = 0; mf < 2; mf++)
                        mma16816h(acch[mf][nf], a[mf], b0, b1);
                }
            }
        }
        __syncthreads();
    }
    #pragma unroll
    for (int mf = 0; mf < 2; mf++) {
        int r = m0 + wm * 32 + mf * 16 + gid;
        #pragma unroll
        for (int nf = 0; nf < NF; nf++) {
            int cb = wn * (8 * NF) + nf * 8 + qt * 2;
            float b0 = __ldg(bias + cb), b1 = __ldg(bias + cb + 1);
            float2 c0 = unph(acch[mf][nf][0]);
            float2 c1 = unph(acch[mf][nf][1]);
            float v00 = scale * (acc[mf][nf][0] + c0.x + b0);
            float v01 = scale * (acc[mf][nf][1] + c0.y + b1);
            float v10 = scale * (acc[mf][nf][2] + c1.x + b0);
            float v11 = scale * (acc[mf][nf][3] + c1.y + b1);
            int col = cn0 + cb;
            if (mode == 0) {
                *(float2*)&Cf[(size_t)r * EMB + col]       = make_float2(v00, v01);
                *(float2*)&Cf[(size_t)(r + 8) * EMB + col] = make_float2(v10, v11);
            } else {
                int colp = permute_paircol(col);
                store_split(Cs + (size_t)r * KSPLIT + colp, v00, v01, mode);
                store_split(Cs + (size_t)(r + 8) * KSPLIT + colp, v10, v11, mode);
            }
        }
    }
}

__global__ void __launch_bounds__(256, 2) gemm_qkv_kernel(const float* __restrict__ bias) {
    int m0 = blockIdx.x * 64;
    int nt = blockIdx.y;          // 0..11
    int sect = nt >> 2;
    int cn0 = (nt & 3) * 128;
    const __half* Bw = g_wqkv + (size_t)nt * 128 * KSPLIT;
    if (sect == 0)
        gemm_core<4, 48>(g_aq, Bw, bias + nt * 128, nullptr, g_sq, cn0, m0, QSCALE, 1);
    else if (sect == 1)
        gemm_core<4, 48>(g_ak, Bw, bias + nt * 128, nullptr, g_sk, cn0, m0, 1.0f, 2);
    else
        gemm_core<4, 48>(g_av, Bw, bias + nt * 128, g_v, nullptr, cn0, m0, 1.0f, 0);
}
// out-proj: hi*hi only (K=512 -> 16 k-chunks, all fp32-acc)
__global__ void __launch_bounds__(256, 2) gemm_out_kernel(const float* __restrict__ bias,
                                                          float* __restrict__ C) {
    gemm_core<2, 16>(g_actx, g_wo + (size_t)blockIdx.y * 64 * KSPLIT,
                     bias + blockIdx.y * 64, C, nullptr, blockIdx.y * 64,
                     blockIdx.x * 64, 1.0f, 0);
}

// ---------------------------------------------------------------------------
// Fused: V split+transpose (blocks 0..255) + type_scores (blocks 256..2303)
// ---------------------------------------------------------------------------
__global__ __launch_bounds__(256) void tsvt_kernel(const float* __restrict__ edge_embs) {
    __shared__ float sh[64 * 68];
    int tid = threadIdx.x;
    if (blockIdx.x < 256) {
        int h = blockIdx.x >> 5, j0 = (blockIdx.x & 31) * 64;
        {
            int row = tid >> 2, cg = (tid & 3) * 16;
            const float* src = g_v + (size_t)(j0 + row) * EMB + h * HDIM + cg;
            #pragma unroll
            for (int i = 0; i < 4; i++)
                *(float4*)&sh[row * 68 + cg + i * 4] = *(const float4*)(src + i * 4);
        }
        __syncthreads();
        int d = tid >> 2, jg = (tid & 3) * 16;
        uint32_t hw[8];
        #pragma unroll
        for (int p = 0; p < 8; p++) {
            float v0 = sh[(jg + 2 * p) * 68 + d], v1 = sh[(jg + 2 * p + 1) * 68 + d];
            hw[p] = packh(v0, v1);    // single fp16 (V-lo dropped)
        }
        __half* dsth = g_svt + ((size_t)(h * 128 + d) * L_SEQ + j0 + jg);
        *(uint4*)dsth       = make_uint4(hw[0], hw[4], hw[1], hw[5]);
        *(uint4*)(dsth + 8) = make_uint4(hw[2], hw[6], hw[3], hw[7]);
    } else {
        float* emb = sh;
        for (int i = tid; i < NTYPE * HDIM; i += 256) emb[i] = edge_embs[i];
        __syncthreads();
        int warp = (blockIdx.x - 256) * 8 + (tid >> 5);
        int lane = tid & 31;
        int h = warp >> 11, i = warp & (L_SEQ - 1);
        int pw = lane & 7;
        int colp = (lane >> 3) * 16 + ((pw & 3) * 2 + (pw >> 2)) * 2;
        const __half* qr = g_sq + (size_t)i * KSPLIT + h * HDIM + colp;
        float2 qh = __half22float2(*(const __half2*)qr);
        float2 ql = __half22float2(*(const __half2*)(qr + 512));
        float2 qv = make_float2(qh.x + ql.x, qh.y + ql.y);
        float s[NTYPE];
        #pragma unroll
        for (int t = 0; t < NTYPE; t++) {
            float2 e = *(const float2*)(emb + t * HDIM + lane * 2);
            s[t] = qv.x * e.x + qv.y * e.y;
        }
        #pragma unroll
        for (int off = 16; off > 0; off >>= 1)
            #pragma unroll
            for (int t = 0; t < NTYPE; t++)
                s[t] += __shfl_xor_sync(0xffffffffu, s[t], off);
        if (lane == 0) {
            float* dst = g_ts + (size_t)warp * 16;
            #pragma unroll
            for (int t = 0; t < NTYPE; t++) dst[t] = s[t];
        }
    }
}

// ---------------------------------------------------------------------------
// Flash attention: i-tile 64, 8 warps = 4 row-warps x 2 n-groups, 2 CTAs/SM.
// S = qh*kh (fp32) + ql*kh (fp16); PV = ph*vh (fp32) — V-lo dropped.
// smem: Q 18432 @0 (288B), K 2x9216 @18432 (144B), V 2x10240 @36864 (160B),
//       Ts 4096 @57344. total 61440.
// ---------------------------------------------------------------------------
#define QPITCH 144   // halfs
#define KPITCH 72
#define VPITCH 80
#define SM_K 18432
#define SM_V 36864
#define SM_T 57344
#define ATTN_SMEM 61440

__global__ void __launch_bounds__(256, 2) attn_mma_kernel(const int* __restrict__ edge_id) {
    extern __shared__ char smb[];
    __half* Qs = (__half*)smb;
    float* Ts = (float*)(smb + SM_T);
    uint32_t sbase = smem_to_u32(smb);

    int h = blockIdx.y;
    int i0 = blockIdx.x * 64;
    int tid = threadIdx.x, wid = tid >> 5, lane = tid & 31;
    int gid = lane >> 2, qt = lane & 3;
    int ngrp = wid >> 2, wg = wid & 3;
    const uint32_t ones2 = 0x3C003C00u;

    auto load_kv = [&](int j0, int buf) {
        {   // K: 64 j-rows x kh(64 halfs)
            int row = tid >> 2, part = tid & 3;
            const __half* src = g_sk + (size_t)(j0 + row) * KSPLIT
                                + h * HDIM + part * 16;
            uint32_t dst = sbase + SM_K + buf * 9216 + row * 144 + part * 32;
            cp16(dst, src); cp16(dst + 16, src + 8);
        }
        {   // V: 64 d-rows x 64 j (vh only)
            int vrow = tid >> 2, part = tid & 3;
            const __half* src = g_svt + (size_t)(h * 128 + vrow) * L_SEQ
                                + j0 + part * 16;
            uint32_t dst = sbase + SM_V + buf * 10240 + vrow * 160 + part * 32;
            cp16(dst, src); cp16(dst + 16, src + 8);
        }
    };

    {   // Q tile (64 rows x [qh|ql]) + Ts
        int row = tid >> 2, q4 = tid & 3;
        int half_ = q4 >> 1, part = q4 & 1;
        const __half* src = g_sq + (size_t)(i0 + row) * KSPLIT
                            + half_ * 512 + h * HDIM + part * 32;
        uint32_t dst = sbase + row * 288 + half_ * 128 + part * 64;
        #pragma unroll
        for (int i = 0; i < 4; i++) cp16(dst + i * 16, src + i * 8);
        *(float4*)(Ts + row * 16 + q4 * 4) =
            *(const float4*)(g_ts + ((size_t)h * L_SEQ + i0 + row) * 16 + q4 * 4);
    }
    CP_COMMIT;
    load_kv(0, 0);
    CP_COMMIT;
    asm volatile("cp.async.wait_group 1;" ::: "memory");
    __syncthreads();

    int r0 = wg * 16 + gid;                    // 0..63
    uint32_t qh[4][4], ql[4][4];
    #pragma unroll
    for (int kc = 0; kc < 4; kc++) {
        uint2 lo = *(const uint2*)&Qs[r0 * QPITCH + kc * 16 + qt * 4];
        uint2 hi = *(const uint2*)&Qs[(r0 + 8) * QPITCH + kc * 16 + qt * 4];
        qh[kc][0] = lo.x; qh[kc][1] = hi.x; qh[kc][2] = lo.y; qh[kc][3] = hi.y;
        uint2 lo2 = *(const uint2*)&Qs[r0 * QPITCH + 64 + kc * 16 + qt * 4];
        uint2 hi2 = *(const uint2*)&Qs[(r0 + 8) * QPITCH + 64 + kc * 16 + qt * 4];
        ql[kc][0] = lo2.x; ql[kc][1] = hi2.x; ql[kc][2] = lo2.y; ql[kc][3] = hi2.y;
    }

    float o[8][4] = {};
    float rm0 = -1e30f, rm1 = -1e30f, rl0 = 0.f, rl1 = 0.f;
    const float* T0 = Ts + r0 * 16;
    const float* T1 = T0 + 128;

    for (int t = 0; t < 32; t++) {
        int cur = t & 1;
        if (t + 1 < 32) {
            load_kv((t + 1) * 64, cur ^ 1);
            CP_COMMIT;
            asm volatile("cp.async.wait_group 1;" ::: "memory");
        } else {
            asm volatile("cp.async.wait_group 0;" ::: "memory");
        }
        __syncthreads();
        const __half* Ks = (const __half*)(smb + SM_K + cur * 9216);
        const __half* Vt = (const __half*)(smb + SM_V + cur * 10240);
        int j0 = t * 64;

        // ---- edge-id prefetch ----
        int grow0 = i0 + r0, grow1 = grow0 + 8;
        int2 e0r[4], e1r[4];
        #pragma unroll
        for (int ntl = 0; ntl < 4; ntl++) {
            int col = j0 + (ngrp * 4 + ntl) * 8 + qt * 2;
            e0r[ntl] = *(const int2*)&edge_id[(size_t)grow0 * L_SEQ + col];
            e1r[ntl] = *(const int2*)&edge_id[(size_t)grow1 * L_SEQ + col];
        }

        // ---- S = qh*kh (fp32) + ql*kh (fp16) ----
        float sa[4][4] = {};
        uint32_t sc[4][2] = {};
        #pragma unroll
        for (int kc = 0; kc < 4; kc++) {
            #pragma unroll
            for (int ntl = 0; ntl < 4; ntl++) {
                int brow = (ngrp * 4 + ntl) * 8 + gid;
                uint2 kh = *(const uint2*)&Ks[brow * KPITCH + kc * 16 + qt * 4];
                mma16816(sa[ntl], qh[kc], kh.x, kh.y);
                mma16816h(sc[ntl], ql[kc], kh.x, kh.y);
            }
        }
        #pragma unroll
        for (int ntl = 0; ntl < 4; ntl++) {
            float2 ca = unph(sc[ntl][0]);
            float2 cb = unph(sc[ntl][1]);
            sa[ntl][0] += ca.x + T0[e0r[ntl].x];
            sa[ntl][1] += ca.y + T0[e0r[ntl].y];
            sa[ntl][2] += cb.x + T1[e1r[ntl].x];
            sa[ntl][3] += cb.y + T1[e1r[ntl].y];
        }

        // ---- online softmax (base 2) ----
        float mx0 = -1e30f, mx1 = -1e30f;
        #pragma unroll
        for (int ntl = 0; ntl < 4; ntl++) {
            mx0 = fmaxf(mx0, fmaxf(sa[ntl][0], sa[ntl][1]));
            mx1 = fmaxf(mx1, fmaxf(sa[ntl][2], sa[ntl][3]));
        }
        mx0 = fmaxf(mx0, __shfl_xor_sync(0xffffffffu, mx0, 1));
        mx0 = fmaxf(mx0, __shfl_xor_sync(0xffffffffu, mx0, 2));
        mx1 = fmaxf(mx1, __shfl_xor_sync(0xffffffffu, mx1, 1));
        mx1 = fmaxf(mx1, __shfl_xor_sync(0xffffffffu, mx1, 2));
        float mn0 = fmaxf(rm0, mx0), mn1 = fmaxf(rm1, mx1);
        bool skip = __all_sync(0xffffffffu, (mn0 == rm0) & (mn1 == rm1));

        // P = 2^(s - m) as packed fp16 A-fragments; row sums via MMA
        uint32_t ph[2][4];
        float ls[4] = {};
        #pragma unroll
        for (int kcp = 0; kcp < 2; kcp++) {
            const float* t0v = sa[2 * kcp];
            const float* t1v = sa[2 * kcp + 1];
            ph[kcp][0] = ex2h2(t0v[0] - mn0, t0v[1] - mn0);
            ph[kcp][1] = ex2h2(t0v[2] - mn1, t0v[3] - mn1);
            ph[kcp][2] = ex2h2(t1v[0] - mn0, t1v[1] - mn0);
            ph[kcp][3] = ex2h2(t1v[2] - mn1, t1v[3] - mn1);
            mma16816(ls, ph[kcp], ones2, ones2);
        }
        if (!skip) {
            float c0 = ex2f(rm0 - mn0), c1 = ex2f(rm1 - mn1);
            rl0 *= c0; rl1 *= c1;
            #pragma unroll
            for (int dt = 0; dt < 8; dt++) {
                o[dt][0] *= c0; o[dt][1] *= c0;
                o[dt][2] *= c1; o[dt][3] *= c1;
            }
            rm0 = mn0; rm1 = mn1;
        }
        rl0 += ls[0];
        rl1 += ls[2];

        // ---- PV over group's 32 j: O += ph*vh (fp32) ----
        #pragma unroll
        for (int kcp = 0; kcp < 2; kcp++) {
            int vc = ngrp * 32 + kcp * 16 + qt * 4;
            #pragma unroll
            for (int dt = 0; dt < 8; dt++) {
                int vrh = dt * 8 + gid;
                uint2 vh = *(const uint2*)&Vt[vrh * VPITCH + vc];
                mma16816(o[dt], ph[kcp], vh.x, vh.y);
            }
        }
        __syncthreads();
    }

    // ---- combine the two n-groups (reuse K region: 18432B >= 17408) ----
    __syncthreads();
    float* co = (float*)(smb + SM_K);            // [64][66]
    float* cm = (float*)(smb + SM_K + 16896);    // [64]
    float* cl = (float*)(smb + SM_K + 17152);    // [64]
    if (ngrp == 1) {
        if (qt == 0) {
            cm[r0] = rm0; cm[r0 + 8] = rm1;
            cl[r0] = rl0; cl[r0 + 8] = rl1;
        }
        #pragma unroll
        for (int dt = 0; dt < 8; dt++) {
            int c = dt * 8 + qt * 2;
            *(float2*)&co[r0 * 66 + c]       = make_float2(o[dt][0], o[dt][1]);
            *(float2*)&co[(r0 + 8) * 66 + c] = make_float2(o[dt][2], o[dt][3]);
        }
    }
    __syncthreads();
    if (ngrp == 0) {
        float m1a = cm[r0], l1a = cl[r0];
        float m1b = cm[r0 + 8], l1b = cl[r0 + 8];
        float M0 = fmaxf(rm0, m1a), M1 = fmaxf(rm1, m1b);
        float a0 = ex2f(rm0 - M0), b0 = ex2f(m1a - M0);
        float a1 = ex2f(rm1 - M1), b1 = ex2f(m1b - M1);
        float inv0 = 1.0f / (rl0 * a0 + l1a * b0);
        float inv1 = 1.0f / (rl1 * a1 + l1b * b1);
        __half* dst0 = g_actx + (size_t)(i0 + r0) * KSPLIT + h * HDIM;
        __half* dst1 = g_actx + (size_t)(i0 + r0 + 8) * KSPLIT + h * HDIM;
        #pragma unroll
        for (int dt = 0; dt < 8; dt++) {
            int c = dt * 8 + qt * 2;
            int cp_ = permute_paircol(c);
            float v0 = (o[dt][0] * a0 + co[r0 * 66 + c] * b0) * inv0;
            float v1 = (o[dt][1] * a0 + co[r0 * 66 + c + 1] * b0) * inv0;
            float w0 = (o[dt][2] * a1 + co[(r0 + 8) * 66 + c] * b1) * inv1;
            float w1 = (o[dt][3] * a1 + co[(r0 + 8) * 66 + c + 1] * b1) * inv1;
            store_split(dst0 + cp_, v0, v1, 1);
            store_split(dst1 + cp_, w0, w1, 1);
        }
    }
}

// ---------------------------------------------------------------------------
extern "C" void kernel_launch(void* const* d_in, const int* in_sizes, int n_in,
                              void* d_out, int out_size)
{
    const float* query = (const float*)d_in[0];
    const float* key   = (const float*)d_in[1];
    const float* value = (const float*)d_in[2];
    const int*   eid   = (const int*)d_in[3];
    const float* w_in  = (const float*)d_in[4];
    const float* b_in  = (const float*)d_in[5];
    const float* w_out = (const float*)d_in[6];
    const float* b_out = (const float*)d_in[7];
    const float* embK  = (const float*)d_in[8];
    float* out = (float*)d_out;

    // launch 0: all splits fused
    split_all<<<16384, 256>>>(query, key, value, w_in, w_out);

    // launch 1: QKV projection
    dim3 qkv_grid(L_SEQ / 64, 12);
    gemm_qkv_kernel<<<qkv_grid, 256>>>(b_in);

    // launch 2: V transpose/split + type scores
    tsvt_kernel<<<2304, 256>>>(embK);

    // launch 3: flash attention
    cudaFuncSetAttribute(attn_mma_kernel, cudaFuncAttributeMaxDynamicSharedMemorySize,
                         ATTN_SMEM);
    dim3 attn_grid(L_SEQ / 64, NHEAD);
    attn_mma_kernel<<<attn_grid, 256, ATTN_SMEM>>>(eid);

    // launch 4: out projection — hi*hi only, K=512
    dim3 out_grid(L_SEQ / 64, EMB / 64);
    gemm_out_kernel<<<out_grid, 256>>>(b_out, out);
}

// round 12
// speedup vs baseline: 1.6846x; 1.1182x over previous
#include <cuda_runtime.h>
#include <cuda_fp16.h>
#include <cstdint>

#define L_SEQ 2048
#define EMB   512
#define NHEAD 8
#define HDIM  64
#define NTYPE 10
#define KSPLIT 1536      // projected-tensor split width (hlh sections)
#define KW     1024      // qkv weight width: [w_hi | w_lo]
#define QSCALE 0.18033688011112042f   // 0.125 * log2(e)

// ---------------------------------------------------------------------------
__device__ float g_v[L_SEQ * EMB];
__device__ float g_ts[NHEAD * L_SEQ * 16];

__device__ __half g_aq[L_SEQ * EMB];      // hi-only activations
__device__ __half g_ak[L_SEQ * EMB];
__device__ __half g_av[L_SEQ * EMB];
__device__ __half g_wqkv[3 * EMB * KW];   // [w_hi | w_lo]
__device__ __half g_wo[EMB * KSPLIT];     // hi-only, k-cols PAIR-PERMUTED
__device__ __half g_sq[L_SEQ * KSPLIT];   // projected q (log2-scaled), hlh, permuted
__device__ __half g_sk[L_SEQ * KSPLIT];   // projected k, hhl, permuted
__device__ __half g_actx[L_SEQ * KSPLIT]; // ctx, hlh, permuted
__device__ __half g_svt[NHEAD * 2 * HDIM * L_SEQ];  // [h][vh|vl][j] permuted pairs

__device__ __forceinline__ int permute_paircol(int col) {   // col even
    int p = (col >> 1) & 7;
    return (col & ~15) + (((p & 3) * 2 + (p >> 2)) << 1);
}

// ---------------------------------------------------------------------------
__device__ __forceinline__ uint32_t packh(float lo, float hi) {
    uint32_t r;
    asm("cvt.rn.f16x2.f32 %0, %1, %2;" : "=r"(r) : "f"(hi), "f"(lo));
    return r;
}
__device__ __forceinline__ uint32_t ex2h2(float lo, float hi) {
    uint32_t r;
    asm("cvt.rn.f16x2.f32 %0, %1, %2;" : "=r"(r) : "f"(hi), "f"(lo));
    asm("ex2.approx.f16x2 %0, %0;" : "+r"(r));
    return r;
}
__device__ __forceinline__ float ex2f(float x) {
    float r;
    asm("ex2.approx.f32 %0, %1;" : "=f"(r) : "f"(x));
    return r;
}
__device__ __forceinline__ float2 unph(uint32_t u) {
    __half2 h = *reinterpret_cast<__half2*>(&u);
    return __half22float2(h);
}
__device__ __forceinline__ uint32_t smem_to_u32(const void* p) {
    uint32_t a;
    asm("{ .reg .u64 t; cvta.to.shared.u64 t, %1; cvt.u32.u64 %0, t; }"
        : "=r"(a) : "l"(p));
    return a;
}
__device__ __forceinline__ void mma16816(float* d, const uint32_t* a,
                                         uint32_t b0, uint32_t b1) {
    asm volatile(
        "mma.sync.aligned.m16n8k16.row.col.f32.f16.f16.f32 "
        "{%0,%1,%2,%3}, {%4,%5,%6,%7}, {%8,%9}, {%0,%1,%2,%3};"
        : "+f"(d[0]), "+f"(d[1]), "+f"(d[2]), "+f"(d[3])
        : "r"(a[0]), "r"(a[1]), "r"(a[2]), "r"(a[3]), "r"(b0), "r"(b1));
}
__device__ __forceinline__ void mma16816h(uint32_t* c, const uint32_t* a,
                                          uint32_t b0, uint32_t b1) {
    asm volatile(
        "mma.sync.aligned.m16n8k16.row.col.f16.f16.f16.f16 "
        "{%0,%1}, {%2,%3,%4,%5}, {%6,%7}, {%0,%1};"
        : "+r"(c[0]), "+r"(c[1])
        : "r"(a[0]), "r"(a[1]), "r"(a[2]), "r"(a[3]), "r"(b0), "r"(b1));
}
__device__ __forceinline__ void cp16(uint32_t s, const void* g) {
    asm volatile("cp.async.cg.shared.global [%0], [%1], 16;"
                 :: "r"(s), "l"(g) : "memory");
}
#define CP_COMMIT asm volatile("cp.async.commit_group;" ::: "memory")

__device__ __forceinline__ void store_split(__half* d, float v0, float v1,
                                            int mode) {
    float h0 = __half2float(__float2half(v0));
    float h1 = __half2float(__float2half(v1));
    uint32_t hh = packh(h0, h1), ll = packh(v0 - h0, v1 - h1);
    *(uint32_t*)d          = hh;
    *(uint32_t*)(d + 512)  = (mode == 1) ? ll : hh;
    *(uint32_t*)(d + 1024) = (mode == 1) ? hh : ll;
}

// ---------------------------------------------------------------------------
// ONE fused split kernel: activations hi-only; w_in [hi|lo]; w_out hi perm
// ---------------------------------------------------------------------------
__global__ __launch_bounds__(256) void split_all(
    const float* __restrict__ q, const float* __restrict__ k,
    const float* __restrict__ v, const float* __restrict__ w,
    const float* __restrict__ wo) {
    int idx = blockIdx.x * 256 + threadIdx.x;   // 0 .. 4194303
    if (idx < 3145728) {                        // activations: plain fp16
        const float* src = idx < 1048576 ? q : (idx < 2097152 ? k : v);
        __half* dst = idx < 1048576 ? g_aq : (idx < 2097152 ? g_ak : g_av);
        int li = idx & 1048575;
        dst[li] = __float2half(src[li]);
    } else if (idx < 3932160) {                 // w_in: [hi | lo], width 1024
        int li = idx - 3145728;
        int r = li >> 9, c = li & 511;
        float x = w[li];
        __half h = __float2half(x);
        __half l = __float2half(x - __half2float(h));
        __half* yr = g_wqkv + (size_t)r * KW;
        yr[c] = h; yr[512 + c] = l;
    } else {                                    // w_out: hi only, permuted
        int li = idx - 3932160;
        int r = li >> 9, c = li & 511;
        int cp_ = permute_paircol(c & ~1) + (c & 1);
        g_wo[(size_t)r * KSPLIT + cp_] = __float2half(wo[li]);
    }
}

// ---------------------------------------------------------------------------
// GEMM: 64 x (32*NF) block tile, 8 warps, warp tile 32 x (8*NF).
// KITERS chunks of 32; A chunk index wraps at KAMASK (A re-read for lo pass).
// kt<16 -> fp32 acc (hi*hi); kt>=16 -> fp16 acc (a_hi * w_lo).
// ---------------------------------------------------------------------------
template <int NF, int KITERS, int KAMASK>
__device__ __forceinline__ void gemm_core(const __half* __restrict__ A,
                                          const __half* __restrict__ B,
                                          const float* __restrict__ bias,
                                          float* __restrict__ Cf,
                                          __half* __restrict__ Cs,
                                          int cn0, int m0, float scale, int mode,
                                          int lda, int ldb) {
    constexpr int BROWS = 32 * NF;
    __shared__ __half As[2][64 * 40];
    __shared__ __half Bs[2][BROWS * 40];
    int tid = threadIdx.x, wid = tid >> 5, lane = tid & 31;
    int gid = lane >> 2, qt = lane & 3;
    int wm = wid >> 2, wn = wid & 3;

    float acc[2][NF][4] = {};
    uint32_t acch[2][NF][2] = {};
    int lrA = tid >> 2, lcA = (tid & 3) * 8;
    const __half* Ap = A + (size_t)(m0 + lrA) * lda + lcA;
    int lrB = (NF == 4) ? (tid >> 1) : (tid >> 2);
    int lcB = (NF == 4) ? ((tid & 1) * 16) : ((tid & 3) * 8);
    const __half* Bp = B + (size_t)lrB * ldb + lcB;
    uint32_t sA[2] = {smem_to_u32(&As[0][lrA * 40 + lcA]),
                      smem_to_u32(&As[1][lrA * 40 + lcA])};
    uint32_t sB[2] = {smem_to_u32(&Bs[0][lrB * 40 + lcB]),
                      smem_to_u32(&Bs[1][lrB * 40 + lcB])};

    cp16(sA[0], Ap);
    cp16(sB[0], Bp);
    if (NF == 4) cp16(sB[0] + 16, Bp + 8);
    CP_COMMIT;

    for (int kt = 0; kt < KITERS; kt++) {
        int cur = kt & 1;
        if (kt + 1 < KITERS) {
            int nx = cur ^ 1;
            const __half* a = Ap + ((kt + 1) & KAMASK) * 32;
            const __half* b = Bp + (kt + 1) * 32;
            cp16(sA[nx], a);
            cp16(sB[nx], b);
            if (NF == 4) cp16(sB[nx] + 16, b + 8);
            CP_COMMIT;
            asm volatile("cp.async.wait_group 1;" ::: "memory");
        } else {
            asm volatile("cp.async.wait_group 0;" ::: "memory");
        }
        __syncthreads();
        bool hi_term = (kt < 16);
        #pragma unroll
        for (int kc = 0; kc < 2; kc++) {
            uint32_t a[2][4];
            #pragma unroll
            for (int mf = 0; mf < 2; mf++) {
                int r = wm * 32 + mf * 16 + gid;
                int c = kc * 16 + qt * 2;
                a[mf][0] = *(const uint32_t*)&As[cur][r * 40 + c];
                a[mf][1] = *(const uint32_t*)&As[cur][(r + 8) * 40 + c];
                a[mf][2] = *(const uint32_t*)&As[cur][r * 40 + c + 8];
                a[mf][3] = *(const uint32_t*)&As[cur][(r + 8) * 40 + c + 8];
            }
            #pragma unroll
            for (int nf = 0; nf < NF; nf++) {
                int n = wn * (8 * NF) + nf * 8 + gid;
                int c = kc * 16 + qt * 2;
                uint32_t b0 = *(const uint32_t*)&Bs[cur][n * 40 + c];
                uint32_t b1 = *(const uint32_t*)&Bs[cur][n * 40 + c + 8];
                if (hi_term) {
                    #pragma unroll
                    for (int mf = 0; mf < 2; mf++)
                        mma16816(acc[mf][nf], a[mf], b0, b1);
                } else {
                    #pragma unroll
                    for (int mf = 0; mf < 2; mf++)
                        mma16816h(acch[mf][nf], a[mf], b0, b1);
                }
            }
        }
        __syncthreads();
    }
    #pragma unroll
    for (int mf = 0; mf < 2; mf++) {
        int r = m0 + wm * 32 + mf * 16 + gid;
        #pragma unroll
        for (int nf = 0; nf < NF; nf++) {
            int cb = wn * (8 * NF) + nf * 8 + qt * 2;
            float b0 = __ldg(bias + cb), b1 = __ldg(bias + cb + 1);
            float2 c0 = unph(acch[mf][nf][0]);
            float2 c1 = unph(acch[mf][nf][1]);
            float v00 = scale * (acc[mf][nf][0] + c0.x + b0);
            float v01 = scale * (acc[mf][nf][1] + c0.y + b1);
            float v10 = scale * (acc[mf][nf][2] + c1.x + b0);
            float v11 = scale * (acc[mf][nf][3] + c1.y + b1);
            int col = cn0 + cb;
            if (mode == 0) {
                *(float2*)&Cf[(size_t)r * EMB + col]       = make_float2(v00, v01);
                *(float2*)&Cf[(size_t)(r + 8) * EMB + col] = make_float2(v10, v11);
            } else {
                int colp = permute_paircol(col);
                store_split(Cs + (size_t)r * KSPLIT + colp, v00, v01, mode);
                store_split(Cs + (size_t)(r + 8) * KSPLIT + colp, v10, v11, mode);
            }
        }
    }
}

__global__ void __launch_bounds__(256, 2) gemm_qkv_kernel(const float* __restrict__ bias) {
    int m0 = blockIdx.x * 64;
    int nt = blockIdx.y;          // 0..11
    int sect = nt >> 2;
    int cn0 = (nt & 3) * 128;
    const __half* Bw = g_wqkv + (size_t)nt * 128 * KW;
    if (sect == 0)
        gemm_core<4, 32, 15>(g_aq, Bw, bias + nt * 128, nullptr, g_sq,
                             cn0, m0, QSCALE, 1, EMB, KW);
    else if (sect == 1)
        gemm_core<4, 32, 15>(g_ak, Bw, bias + nt * 128, nullptr, g_sk,
                             cn0, m0, 1.0f, 2, EMB, KW);
    else
        gemm_core<4, 32, 15>(g_av, Bw, bias + nt * 128, g_v, nullptr,
                             cn0, m0, 1.0f, 0, EMB, KW);
}
// out-proj: hi*hi only (16 chunks, all fp32-acc)
__global__ void __launch_bounds__(256, 2) gemm_out_kernel(const float* __restrict__ bias,
                                                          float* __restrict__ C) {
    gemm_core<2, 16, 63>(g_actx, g_wo + (size_t)blockIdx.y * 64 * KSPLIT,
                         bias + blockIdx.y * 64, C, nullptr, blockIdx.y * 64,
                         blockIdx.x * 64, 1.0f, 0, KSPLIT, KSPLIT);
}

// ---------------------------------------------------------------------------
// Fused: V split+transpose (blocks 0..255) + type_scores (blocks 256..2303)
// ---------------------------------------------------------------------------
__global__ __launch_bounds__(256) void tsvt_kernel(const float* __restrict__ edge_embs) {
    __shared__ float sh[64 * 68];
    int tid = threadIdx.x;
    if (blockIdx.x < 256) {
        int h = blockIdx.x >> 5, j0 = (blockIdx.x & 31) * 64;
        {
            int row = tid >> 2, cg = (tid & 3) * 16;
            const float* src = g_v + (size_t)(j0 + row) * EMB + h * HDIM + cg;
            #pragma unroll
            for (int i = 0; i < 4; i++)
                *(float4*)&sh[row * 68 + cg + i * 4] = *(const float4*)(src + i * 4);
        }
        __syncthreads();
        int d = tid >> 2, jg = (tid & 3) * 16;
        uint32_t hw[8];
        #pragma unroll
        for (int p = 0; p < 8; p++) {
            float v0 = sh[(jg + 2 * p) * 68 + d], v1 = sh[(jg + 2 * p + 1) * 68 + d];
            hw[p] = packh(v0, v1);
        }
        __half* dsth = g_svt + ((size_t)(h * 128 + d) * L_SEQ + j0 + jg);
        *(uint4*)dsth       = make_uint4(hw[0], hw[4], hw[1], hw[5]);
        *(uint4*)(dsth + 8) = make_uint4(hw[2], hw[6], hw[3], hw[7]);
    } else {
        float* emb = sh;
        for (int i = tid; i < NTYPE * HDIM; i += 256) emb[i] = edge_embs[i];
        __syncthreads();
        int warp = (blockIdx.x - 256) * 8 + (tid >> 5);
        int lane = tid & 31;
        int h = warp >> 11, i = warp & (L_SEQ - 1);
        int pw = lane & 7;
        int colp = (lane >> 3) * 16 + ((pw & 3) * 2 + (pw >> 2)) * 2;
        const __half* qr = g_sq + (size_t)i * KSPLIT + h * HDIM + colp;
        float2 qh = __half22float2(*(const __half2*)qr);
        float2 ql = __half22float2(*(const __half2*)(qr + 512));
        float2 qv = make_float2(qh.x + ql.x, qh.y + ql.y);
        float s[NTYPE];
        #pragma unroll
        for (int t = 0; t < NTYPE; t++) {
            float2 e = *(const float2*)(emb + t * HDIM + lane * 2);
            s[t] = qv.x * e.x + qv.y * e.y;
        }
        #pragma unroll
        for (int off = 16; off > 0; off >>= 1)
            #pragma unroll
            for (int t = 0; t < NTYPE; t++)
                s[t] += __shfl_xor_sync(0xffffffffu, s[t], off);
        if (lane == 0) {
            float* dst = g_ts + (size_t)warp * 16;
            #pragma unroll
            for (int t = 0; t < NTYPE; t++) dst[t] = s[t];
        }
    }
}

// ---------------------------------------------------------------------------
// Flash attention: i-tile 64, 8 warps = 4 row-warps x 2 n-groups, 2 CTAs/SM.
// S = qh*kh (fp32 only); PV = ph*vh (fp32). q-lo / k-lo / v-lo all dropped.
// smem: Q 9216 @0 (144B), K 2x9216 @9216, V 2x10240 @27648, Ts 4096 @48128.
// total 52224.
// ---------------------------------------------------------------------------
#define QPITCH 72    // halfs
#define KPITCH 72
#define VPITCH 80
#define SM_K 9216
#define SM_V 27648
#define SM_T 48128
#define ATTN_SMEM 52224

__global__ void __launch_bounds__(256, 2) attn_mma_kernel(const int* __restrict__ edge_id) {
    extern __shared__ char smb[];
    __half* Qs = (__half*)smb;
    float* Ts = (float*)(smb + SM_T);
    uint32_t sbase = smem_to_u32(smb);

    int h = blockIdx.y;
    int i0 = blockIdx.x * 64;
    int tid = threadIdx.x, wid = tid >> 5, lane = tid & 31;
    int gid = lane >> 2, qt = lane & 3;
    int ngrp = wid >> 2, wg = wid & 3;
    const uint32_t ones2 = 0x3C003C00u;

    auto load_kv = [&](int j0, int buf) {
        int row = tid >> 2, part = tid & 3;
        {   // K: 64 j-rows x kh(64 halfs)
            const __half* src = g_sk + (size_t)(j0 + row) * KSPLIT
                                + h * HDIM + part * 16;
            uint32_t dst = sbase + SM_K + buf * 9216 + row * 144 + part * 32;
            cp16(dst, src); cp16(dst + 16, src + 8);
        }
        {   // V: 64 d-rows x 64 j
            const __half* src = g_svt + (size_t)(h * 128 + row) * L_SEQ
                                + j0 + part * 16;
            uint32_t dst = sbase + SM_V + buf * 10240 + row * 160 + part * 32;
            cp16(dst, src); cp16(dst + 16, src + 8);
        }
    };

    {   // Q tile (64 rows x qh) + Ts
        int row = tid >> 2, part = tid & 3;
        const __half* src = g_sq + (size_t)(i0 + row) * KSPLIT + h * HDIM + part * 16;
        uint32_t dst = sbase + row * 144 + part * 32;
        cp16(dst, src); cp16(dst + 16, src + 8);
        *(float4*)(Ts + row * 16 + part * 4) =
            *(const float4*)(g_ts + ((size_t)h * L_SEQ + i0 + row) * 16 + part * 4);
    }
    CP_COMMIT;
    load_kv(0, 0);
    CP_COMMIT;
    asm volatile("cp.async.wait_group 1;" ::: "memory");
    __syncthreads();

    int r0 = wg * 16 + gid;                    // 0..63
    uint32_t qh[4][4];
    #pragma unroll
    for (int kc = 0; kc < 4; kc++) {
        uint2 lo = *(const uint2*)&Qs[r0 * QPITCH + kc * 16 + qt * 4];
        uint2 hi = *(const uint2*)&Qs[(r0 + 8) * QPITCH + kc * 16 + qt * 4];
        qh[kc][0] = lo.x; qh[kc][1] = hi.x; qh[kc][2] = lo.y; qh[kc][3] = hi.y;
    }

    float o[8][4] = {};
    float rm0 = -1e30f, rm1 = -1e30f, rl0 = 0.f, rl1 = 0.f;
    const float* T0 = Ts + r0 * 16;
    const float* T1 = T0 + 128;

    for (int t = 0; t < 32; t++) {
        int cur = t & 1;
        if (t + 1 < 32) {
            load_kv((t + 1) * 64, cur ^ 1);
            CP_COMMIT;
            asm volatile("cp.async.wait_group 1;" ::: "memory");
        } else {
            asm volatile("cp.async.wait_group 0;" ::: "memory");
        }
        __syncthreads();
        const __half* Ks = (const __half*)(smb + SM_K + cur * 9216);
        const __half* Vt = (const __half*)(smb + SM_V + cur * 10240);
        int j0 = t * 64;

        // ---- edge-id prefetch ----
        int grow0 = i0 + r0, grow1 = grow0 + 8;
        int2 e0r[4], e1r[4];
        #pragma unroll
        for (int ntl = 0; ntl < 4; ntl++) {
            int col = j0 + (ngrp * 4 + ntl) * 8 + qt * 2;
            e0r[ntl] = *(const int2*)&edge_id[(size_t)grow0 * L_SEQ + col];
            e1r[ntl] = *(const int2*)&edge_id[(size_t)grow1 * L_SEQ + col];
        }

        // ---- S = qh*kh (fp32) ----
        float sa[4][4] = {};
        #pragma unroll
        for (int kc = 0; kc < 4; kc++) {
            #pragma unroll
            for (int ntl = 0; ntl < 4; ntl++) {
                int brow = (ngrp * 4 + ntl) * 8 + gid;
                uint2 kh = *(const uint2*)&Ks[brow * KPITCH + kc * 16 + qt * 4];
                mma16816(sa[ntl], qh[kc], kh.x, kh.y);
            }
        }
        #pragma unroll
        for (int ntl = 0; ntl < 4; ntl++) {
            sa[ntl][0] += T0[e0r[ntl].x];
            sa[ntl][1] += T0[e0r[ntl].y];
            sa[ntl][2] += T1[e1r[ntl].x];
            sa[ntl][3] += T1[e1r[ntl].y];
        }

        // ---- online softmax (base 2) ----
        float mx0 = -1e30f, mx1 = -1e30f;
        #pragma unroll
        for (int ntl = 0; ntl < 4; ntl++) {
            mx0 = fmaxf(mx0, fmaxf(sa[ntl][0], sa[ntl][1]));
            mx1 = fmaxf(mx1, fmaxf(sa[ntl][2], sa[ntl][3]));
        }
        mx0 = fmaxf(mx0, __shfl_xor_sync(0xffffffffu, mx0, 1));
        mx0 = fmaxf(mx0, __shfl_xor_sync(0xffffffffu, mx0, 2));
        mx1 = fmaxf(mx1, __shfl_xor_sync(0xffffffffu, mx1, 1));
        mx1 = fmaxf(mx1, __shfl_xor_sync(0xffffffffu, mx1, 2));
        float mn0 = fmaxf(rm0, mx0), mn1 = fmaxf(rm1, mx1);
        bool skip = __all_sync(0xffffffffu, (mn0 == rm0) & (mn1 == rm1));

        uint32_t ph[2][4];
        float ls[4] = {};
        #pragma unroll
        for (int kcp = 0; kcp < 2; kcp++) {
            const float* t0v = sa[2 * kcp];
            const float* t1v = sa[2 * kcp + 1];
            ph[kcp][0] = ex2h2(t0v[0] - mn0, t0v[1] - mn0);
            ph[kcp][1] = ex2h2(t0v[2] - mn1, t0v[3] - mn1);
            ph[kcp][2] = ex2h2(t1v[0] - mn0, t1v[1] - mn0);
            ph[kcp][3] = ex2h2(t1v[2] - mn1, t1v[3] - mn1);
            mma16816(ls, ph[kcp], ones2, ones2);
        }
        if (!skip) {
            float c0 = ex2f(rm0 - mn0), c1 = ex2f(rm1 - mn1);
            rl0 *= c0; rl1 *= c1;
            #pragma unroll
            for (int dt = 0; dt < 8; dt++) {
                o[dt][0] *= c0; o[dt][1] *= c0;
                o[dt][2] *= c1; o[dt][3] *= c1;
            }
            rm0 = mn0; rm1 = mn1;
        }
        rl0 += ls[0];
        rl1 += ls[2];

        // ---- PV over group's 32 j: O += ph*vh (fp32) ----
        #pragma unroll
        for (int kcp = 0; kcp < 2; kcp++) {
            int vc = ngrp * 32 + kcp * 16 + qt * 4;
            #pragma unroll
            for (int dt = 0; dt < 8; dt++) {
                int vrh = dt * 8 + gid;
                uint2 vh = *(const uint2*)&Vt[vrh * VPITCH + vc];
                mma16816(o[dt], ph[kcp], vh.x, vh.y);
            }
        }
        __syncthreads();
    }

    // ---- combine the two n-groups (reuse K region: 2x9216 >= 17408) ----
    __syncthreads();
    float* co = (float*)(smb + SM_K);            // [64][66]
    float* cm = (float*)(smb + SM_K + 16896);    // [64]
    float* cl = (float*)(smb + SM_K + 17152);    // [64]
    if (ngrp == 1) {
        if (qt == 0) {
            cm[r0] = rm0; cm[r0 + 8] = rm1;
            cl[r0] = rl0; cl[r0 + 8] = rl1;
        }
        #pragma unroll
        for (int dt = 0; dt < 8; dt++) {
            int c = dt * 8 + qt * 2;
            *(float2*)&co[r0 * 66 + c]       = make_float2(o[dt][0], o[dt][1]);
            *(float2*)&co[(r0 + 8) * 66 + c] = make_float2(o[dt][2], o[dt][3]);
        }
    }
    __syncthreads();
    if (ngrp == 0) {
        float m1a = cm[r0], l1a = cl[r0];
        float m1b = cm[r0 + 8], l1b = cl[r0 + 8];
        float M0 = fmaxf(rm0, m1a), M1 = fmaxf(rm1, m1b);
        float a0 = ex2f(rm0 - M0), b0 = ex2f(m1a - M0);
        float a1 = ex2f(rm1 - M1), b1 = ex2f(m1b - M1);
        float inv0 = 1.0f / (rl0 * a0 + l1a * b0);
        float inv1 = 1.0f / (rl1 * a1 + l1b * b1);
        __half* dst0 = g_actx + (size_t)(i0 + r0) * KSPLIT + h * HDIM;
        __half* dst1 = g_actx + (size_t)(i0 + r0 + 8) * KSPLIT + h * HDIM;
        #pragma unroll
        for (int dt = 0; dt < 8; dt++) {
            int c = dt * 8 + qt * 2;
            int cp_ = permute_paircol(c);
            float v0 = (o[dt][0] * a0 + co[r0 * 66 + c] * b0) * inv0;
            float v1 = (o[dt][1] * a0 + co[r0 * 66 + c + 1] * b0) * inv0;
            float w0 = (o[dt][2] * a1 + co[(r0 + 8) * 66 + c] * b1) * inv1;
            float w1 = (o[dt][3] * a1 + co[(r0 + 8) * 66 + c + 1] * b1) * inv1;
            store_split(dst0 + cp_, v0, v1, 1);
            store_split(dst1 + cp_, w0, w1, 1);
        }
    }
}

// ---------------------------------------------------------------------------
extern "C" void kernel_launch(void* const* d_in, const int* in_sizes, int n_in,
                              void* d_out, int out_size)
{
    const float* query = (const float*)d_in[0];
    const float* key   = (const float*)d_in[1];
    const float* value = (const float*)d_in[2];
    const int*   eid   = (const int*)d_in[3];
    const float* w_in  = (const float*)d_in[4];
    const float* b_in  = (const float*)d_in[5];
    const float* w_out = (const float*)d_in[6];
    const float* b_out = (const float*)d_in[7];
    const float* embK  = (const float*)d_in[8];
    float* out = (float*)d_out;

    // launch 0: all splits fused
    split_all<<<16384, 256>>>(query, key, value, w_in, w_out);

    // launch 1: QKV projection (K=1024 effective, A hi re-read)
    dim3 qkv_grid(L_SEQ / 64, 12);
    gemm_qkv_kernel<<<qkv_grid, 256>>>(b_in);

    // launch 2: V transpose + type scores
    tsvt_kernel<<<2304, 256>>>(embK);

    // launch 3: flash attention
    cudaFuncSetAttribute(attn_mma_kernel, cudaFuncAttributeMaxDynamicSharedMemorySize,
                         ATTN_SMEM);
    dim3 attn_grid(L_SEQ / 64, NHEAD);
    attn_mma_kernel<<<attn_grid, 256, ATTN_SMEM>>>(eid);

    // launch 4: out projection — hi*hi only
    dim3 out_grid(L_SEQ / 64, EMB / 64);
    gemm_out_kernel<<<out_grid, 256>>>(b_out, out);
}

// round 13
// speedup vs baseline: 1.8374x; 1.0907x over previous
#include <cuda_runtime.h>
#include <cuda_fp16.h>
#include <cstdint>

#define L_SEQ 2048
#define EMB   512
#define NHEAD 8
#define HDIM  64
#define NTYPE 10
#define KSPLIT 1536      // projected-tensor split width (hlh sections)
#define KW     1024      // qkv weight width: [w_hi | w_lo]
#define QSCALE 0.18033688011112042f   // 0.125 * log2(e)

// ---------------------------------------------------------------------------
__device__ float g_v[L_SEQ * EMB];
__device__ float g_ts[NHEAD * L_SEQ * 16];
__device__ uint8_t g_eid8[L_SEQ * L_SEQ];   // edge ids compressed to int8

__device__ __half g_aq[L_SEQ * EMB];      // hi-only activations
__device__ __half g_ak[L_SEQ * EMB];
__device__ __half g_av[L_SEQ * EMB];
__device__ __half g_wqkv[3 * EMB * KW];   // [w_hi | w_lo]
__device__ __half g_wo[EMB * KSPLIT];     // hi-only, k-cols PAIR-PERMUTED
__device__ __half g_sq[L_SEQ * KSPLIT];   // projected q (log2-scaled), hlh, permuted
__device__ __half g_sk[L_SEQ * KSPLIT];   // projected k, hhl, permuted
__device__ __half g_actx[L_SEQ * KSPLIT]; // ctx, hlh, permuted
__device__ __half g_svt[NHEAD * 2 * HDIM * L_SEQ];  // [h][vh|vl][j] permuted pairs

__device__ __forceinline__ int permute_paircol(int col) {   // col even
    int p = (col >> 1) & 7;
    return (col & ~15) + (((p & 3) * 2 + (p >> 2)) << 1);
}

// ---------------------------------------------------------------------------
__device__ __forceinline__ uint32_t packh(float lo, float hi) {
    uint32_t r;
    asm("cvt.rn.f16x2.f32 %0, %1, %2;" : "=r"(r) : "f"(hi), "f"(lo));
    return r;
}
__device__ __forceinline__ uint32_t ex2h2(float lo, float hi) {
    uint32_t r;
    asm("cvt.rn.f16x2.f32 %0, %1, %2;" : "=r"(r) : "f"(hi), "f"(lo));
    asm("ex2.approx.f16x2 %0, %0;" : "+r"(r));
    return r;
}
__device__ __forceinline__ float ex2f(float x) {
    float r;
    asm("ex2.approx.f32 %0, %1;" : "=f"(r) : "f"(x));
    return r;
}
__device__ __forceinline__ float2 unph(uint32_t u) {
    __half2 h = *reinterpret_cast<__half2*>(&u);
    return __half22float2(h);
}
__device__ __forceinline__ uint32_t smem_to_u32(const void* p) {
    uint32_t a;
    asm("{ .reg .u64 t; cvta.to.shared.u64 t, %1; cvt.u32.u64 %0, t; }"
        : "=r"(a) : "l"(p));
    return a;
}
__device__ __forceinline__ void mma16816(float* d, const uint32_t* a,
                                         uint32_t b0, uint32_t b1) {
    asm volatile(
        "mma.sync.aligned.m16n8k16.row.col.f32.f16.f16.f32 "
        "{%0,%1,%2,%3}, {%4,%5,%6,%7}, {%8,%9}, {%0,%1,%2,%3};"
        : "+f"(d[0]), "+f"(d[1]), "+f"(d[2]), "+f"(d[3])
        : "r"(a[0]), "r"(a[1]), "r"(a[2]), "r"(a[3]), "r"(b0), "r"(b1));
}
__device__ __forceinline__ void mma16816h(uint32_t* c, const uint32_t* a,
                                          uint32_t b0, uint32_t b1) {
    asm volatile(
        "mma.sync.aligned.m16n8k16.row.col.f16.f16.f16.f16 "
        "{%0,%1}, {%2,%3,%4,%5}, {%6,%7}, {%0,%1};"
        : "+r"(c[0]), "+r"(c[1])
        : "r"(a[0]), "r"(a[1]), "r"(a[2]), "r"(a[3]), "r"(b0), "r"(b1));
}
__device__ __forceinline__ void cp16(uint32_t s, const void* g) {
    asm volatile("cp.async.cg.shared.global [%0], [%1], 16;"
                 :: "r"(s), "l"(g) : "memory");
}
#define CP_COMMIT asm volatile("cp.async.commit_group;" ::: "memory")

__device__ __forceinline__ void store_split(__half* d, float v0, float v1,
                                            int mode) {
    float h0 = __half2float(__float2half(v0));
    float h1 = __half2float(__float2half(v1));
    uint32_t hh = packh(h0, h1), ll = packh(v0 - h0, v1 - h1);
    *(uint32_t*)d          = hh;
    *(uint32_t*)(d + 512)  = (mode == 1) ? ll : hh;
    *(uint32_t*)(d + 1024) = (mode == 1) ? hh : ll;
}

// ---------------------------------------------------------------------------
// ONE fused split kernel: activations hi-only; w_in [hi|lo]; w_out hi perm;
// edge_id int32 -> int8 compression.
// ---------------------------------------------------------------------------
__global__ __launch_bounds__(256) void split_all(
    const float* __restrict__ q, const float* __restrict__ k,
    const float* __restrict__ v, const float* __restrict__ w,
    const float* __restrict__ wo, const int* __restrict__ eid) {
    int idx = blockIdx.x * 256 + threadIdx.x;   // 0 .. 5242879
    if (idx < 3145728) {                        // activations: plain fp16
        const float* src = idx < 1048576 ? q : (idx < 2097152 ? k : v);
        __half* dst = idx < 1048576 ? g_aq : (idx < 2097152 ? g_ak : g_av);
        int li = idx & 1048575;
        dst[li] = __float2half(src[li]);
    } else if (idx < 3932160) {                 // w_in: [hi | lo], width 1024
        int li = idx - 3145728;
        int r = li >> 9, c = li & 511;
        float x = w[li];
        __half h = __float2half(x);
        __half l = __float2half(x - __half2float(h));
        __half* yr = g_wqkv + (size_t)r * KW;
        yr[c] = h; yr[512 + c] = l;
    } else if (idx < 4194304) {                 // w_out: hi only, permuted
        int li = idx - 3932160;
        int r = li >> 9, c = li & 511;
        int cp_ = permute_paircol(c & ~1) + (c & 1);
        g_wo[(size_t)r * KSPLIT + cp_] = __float2half(wo[li]);
    } else {                                    // edge compression: int4->uchar4
        int li = idx - 4194304;                 // 0 .. 1048575
        int4 e = *(const int4*)(eid + (size_t)li * 4);
        uchar4 c = make_uchar4((unsigned char)e.x, (unsigned char)e.y,
                               (unsigned char)e.z, (unsigned char)e.w);
        *(uchar4*)(g_eid8 + (size_t)li * 4) = c;
    }
}

// ---------------------------------------------------------------------------
// GEMM: 64 x (32*NF) block tile, 8 warps, warp tile 32 x (8*NF).
// KITERS chunks of 32; A chunk index wraps at KAMASK (A re-read for lo pass).
// kt<16 -> fp32 acc (hi*hi); kt>=16 -> fp16 acc (a_hi * w_lo).
// ---------------------------------------------------------------------------
template <int NF, int KITERS, int KAMASK>
__device__ __forceinline__ void gemm_core(const __half* __restrict__ A,
                                          const __half* __restrict__ B,
                                          const float* __restrict__ bias,
                                          float* __restrict__ Cf,
                                          __half* __restrict__ Cs,
                                          int cn0, int m0, float scale, int mode,
                                          int lda, int ldb) {
    constexpr int BROWS = 32 * NF;
    __shared__ __half As[2][64 * 40];
    __shared__ __half Bs[2][BROWS * 40];
    int tid = threadIdx.x, wid = tid >> 5, lane = tid & 31;
    int gid = lane >> 2, qt = lane & 3;
    int wm = wid >> 2, wn = wid & 3;

    float acc[2][NF][4] = {};
    uint32_t acch[2][NF][2] = {};
    int lrA = tid >> 2, lcA = (tid & 3) * 8;
    const __half* Ap = A + (size_t)(m0 + lrA) * lda + lcA;
    int lrB = (NF == 4) ? (tid >> 1) : (tid >> 2);
    int lcB = (NF == 4) ? ((tid & 1) * 16) : ((tid & 3) * 8);
    const __half* Bp = B + (size_t)lrB * ldb + lcB;
    uint32_t sA[2] = {smem_to_u32(&As[0][lrA * 40 + lcA]),
                      smem_to_u32(&As[1][lrA * 40 + lcA])};
    uint32_t sB[2] = {smem_to_u32(&Bs[0][lrB * 40 + lcB]),
                      smem_to_u32(&Bs[1][lrB * 40 + lcB])};

    cp16(sA[0], Ap);
    cp16(sB[0], Bp);
    if (NF == 4) cp16(sB[0] + 16, Bp + 8);
    CP_COMMIT;

    for (int kt = 0; kt < KITERS; kt++) {
        int cur = kt & 1;
        if (kt + 1 < KITERS) {
            int nx = cur ^ 1;
            const __half* a = Ap + ((kt + 1) & KAMASK) * 32;
            const __half* b = Bp + (kt + 1) * 32;
            cp16(sA[nx], a);
            cp16(sB[nx], b);
            if (NF == 4) cp16(sB[nx] + 16, b + 8);
            CP_COMMIT;
            asm volatile("cp.async.wait_group 1;" ::: "memory");
        } else {
            asm volatile("cp.async.wait_group 0;" ::: "memory");
        }
        __syncthreads();
        bool hi_term = (kt < 16);
        #pragma unroll
        for (int kc = 0; kc < 2; kc++) {
            uint32_t a[2][4];
            #pragma unroll
            for (int mf = 0; mf < 2; mf++) {
                int r = wm * 32 + mf * 16 + gid;
                int c = kc * 16 + qt * 2;
                a[mf][0] = *(const uint32_t*)&As[cur][r * 40 + c];
                a[mf][1] = *(const uint32_t*)&As[cur][(r + 8) * 40 + c];
                a[mf][2] = *(const uint32_t*)&As[cur][r * 40 + c + 8];
                a[mf][3] = *(const uint32_t*)&As[cur][(r + 8) * 40 + c + 8];
            }
            #pragma unroll
            for (int nf = 0; nf < NF; nf++) {
                int n = wn * (8 * NF) + nf * 8 + gid;
                int c = kc * 16 + qt * 2;
                uint32_t b0 = *(const uint32_t*)&Bs[cur][n * 40 + c];
                uint32_t b1 = *(const uint32_t*)&Bs[cur][n * 40 + c + 8];
                if (hi_term) {
                    #pragma unroll
                    for (int mf = 0; mf < 2; mf++)
                        mma16816(acc[mf][nf], a[mf], b0, b1);
                } else {
                    #pragma unroll
                    for (int mf = 0; mf < 2; mf++)
                        mma16816h(acch[mf][nf], a[mf], b0, b1);
                }
            }
        }
        __syncthreads();
    }
    #pragma unroll
    for (int mf = 0; mf < 2; mf++) {
        int r = m0 + wm * 32 + mf * 16 + gid;
        #pragma unroll
        for (int nf = 0; nf < NF; nf++) {
            int cb = wn * (8 * NF) + nf * 8 + qt * 2;
            float b0 = __ldg(bias + cb), b1 = __ldg(bias + cb + 1);
            float2 c0 = unph(acch[mf][nf][0]);
            float2 c1 = unph(acch[mf][nf][1]);
            float v00 = scale * (acc[mf][nf][0] + c0.x + b0);
            float v01 = scale * (acc[mf][nf][1] + c0.y + b1);
            float v10 = scale * (acc[mf][nf][2] + c1.x + b0);
            float v11 = scale * (acc[mf][nf][3] + c1.y + b1);
            int col = cn0 + cb;
            if (mode == 0) {
                *(float2*)&Cf[(size_t)r * EMB + col]       = make_float2(v00, v01);
                *(float2*)&Cf[(size_t)(r + 8) * EMB + col] = make_float2(v10, v11);
            } else {
                int colp = permute_paircol(col);
                store_split(Cs + (size_t)r * KSPLIT + colp, v00, v01, mode);
                store_split(Cs + (size_t)(r + 8) * KSPLIT + colp, v10, v11, mode);
            }
        }
    }
}

__global__ void __launch_bounds__(256, 2) gemm_qkv_kernel(const float* __restrict__ bias) {
    int m0 = blockIdx.x * 64;
    int nt = blockIdx.y;          // 0..11
    int sect = nt >> 2;
    int cn0 = (nt & 3) * 128;
    const __half* Bw = g_wqkv + (size_t)nt * 128 * KW;
    if (sect == 0)        // q keeps w_lo refinement (feeds edge LUT)
        gemm_core<4, 32, 15>(g_aq, Bw, bias + nt * 128, nullptr, g_sq,
                             cn0, m0, QSCALE, 1, EMB, KW);
    else if (sect == 1)   // k: hi*hi only (k is fp16-rounded downstream anyway)
        gemm_core<4, 16, 15>(g_ak, Bw, bias + nt * 128, nullptr, g_sk,
                             cn0, m0, 1.0f, 2, EMB, KW);
    else                  // v: hi*hi only (v is fp16-rounded downstream anyway)
        gemm_core<4, 16, 15>(g_av, Bw, bias + nt * 128, g_v, nullptr,
                             cn0, m0, 1.0f, 0, EMB, KW);
}
// out-proj: hi*hi only (16 chunks, all fp32-acc)
__global__ void __launch_bounds__(256, 2) gemm_out_kernel(const float* __restrict__ bias,
                                                          float* __restrict__ C) {
    gemm_core<2, 16, 63>(g_actx, g_wo + (size_t)blockIdx.y * 64 * KSPLIT,
                         bias + blockIdx.y * 64, C, nullptr, blockIdx.y * 64,
                         blockIdx.x * 64, 1.0f, 0, KSPLIT, KSPLIT);
}

// ---------------------------------------------------------------------------
// Fused: V split+transpose (blocks 0..255) + type_scores (blocks 256..2303)
// ---------------------------------------------------------------------------
__global__ __launch_bounds__(256) void tsvt_kernel(const float* __restrict__ edge_embs) {
    __shared__ float sh[64 * 68];
    int tid = threadIdx.x;
    if (blockIdx.x < 256) {
        int h = blockIdx.x >> 5, j0 = (blockIdx.x & 31) * 64;
        {
            int row = tid >> 2, cg = (tid & 3) * 16;
            const float* src = g_v + (size_t)(j0 + row) * EMB + h * HDIM + cg;
            #pragma unroll
            for (int i = 0; i < 4; i++)
                *(float4*)&sh[row * 68 + cg + i * 4] = *(const float4*)(src + i * 4);
        }
        __syncthreads();
        int d = tid >> 2, jg = (tid & 3) * 16;
        uint32_t hw[8];
        #pragma unroll
        for (int p = 0; p < 8; p++) {
            float v0 = sh[(jg + 2 * p) * 68 + d], v1 = sh[(jg + 2 * p + 1) * 68 + d];
            hw[p] = packh(v0, v1);
        }
        __half* dsth = g_svt + ((size_t)(h * 128 + d) * L_SEQ + j0 + jg);
        *(uint4*)dsth       = make_uint4(hw[0], hw[4], hw[1], hw[5]);
        *(uint4*)(dsth + 8) = make_uint4(hw[2], hw[6], hw[3], hw[7]);
    } else {
        float* emb = sh;
        for (int i = tid; i < NTYPE * HDIM; i += 256) emb[i] = edge_embs[i];
        __syncthreads();
        int warp = (blockIdx.x - 256) * 8 + (tid >> 5);
        int lane = tid & 31;
        int h = warp >> 11, i = warp & (L_SEQ - 1);
        int pw = lane & 7;
        int colp = (lane >> 3) * 16 + ((pw & 3) * 2 + (pw >> 2)) * 2;
        const __half* qr = g_sq + (size_t)i * KSPLIT + h * HDIM + colp;
        float2 qh = __half22float2(*(const __half2*)qr);
        float2 ql = __half22float2(*(const __half2*)(qr + 512));
        float2 qv = make_float2(qh.x + ql.x, qh.y + ql.y);
        float s[NTYPE];
        #pragma unroll
        for (int t = 0; t < NTYPE; t++) {
            float2 e = *(const float2*)(emb + t * HDIM + lane * 2);
            s[t] = qv.x * e.x + qv.y * e.y;
        }
        #pragma unroll
        for (int off = 16; off > 0; off >>= 1)
            #pragma unroll
            for (int t = 0; t < NTYPE; t++)
                s[t] += __shfl_xor_sync(0xffffffffu, s[t], off);
        if (lane == 0) {
            float* dst = g_ts + (size_t)warp * 16;
            #pragma unroll
            for (int t = 0; t < NTYPE; t++) dst[t] = s[t];
        }
    }
}

// ---------------------------------------------------------------------------
// Flash attention: i-tile 64, 8 warps = 4 row-warps x 2 n-groups, 2 CTAs/SM.
// S = qh*kh (fp32); PV = ph*vh (fp32). Edge ids from int8-compressed matrix.
// smem: Q 9216 @0 (144B), K 2x9216 @9216, V 2x10240 @27648, Ts 4096 @48128.
// total 52224.
// ---------------------------------------------------------------------------
#define QPITCH 72    // halfs
#define KPITCH 72
#define VPITCH 80
#define SM_K 9216
#define SM_V 27648
#define SM_T 48128
#define ATTN_SMEM 52224

__global__ void __launch_bounds__(256, 2) attn_mma_kernel() {
    extern __shared__ char smb[];
    __half* Qs = (__half*)smb;
    float* Ts = (float*)(smb + SM_T);
    uint32_t sbase = smem_to_u32(smb);

    int h = blockIdx.y;
    int i0 = blockIdx.x * 64;
    int tid = threadIdx.x, wid = tid >> 5, lane = tid & 31;
    int gid = lane >> 2, qt = lane & 3;
    int ngrp = wid >> 2, wg = wid & 3;
    const uint32_t ones2 = 0x3C003C00u;

    auto load_kv = [&](int j0, int buf) {
        int row = tid >> 2, part = tid & 3;
        {   // K: 64 j-rows x kh(64 halfs)
            const __half* src = g_sk + (size_t)(j0 + row) * KSPLIT
                                + h * HDIM + part * 16;
            uint32_t dst = sbase + SM_K + buf * 9216 + row * 144 + part * 32;
            cp16(dst, src); cp16(dst + 16, src + 8);
        }
        {   // V: 64 d-rows x 64 j
            const __half* src = g_svt + (size_t)(h * 128 + row) * L_SEQ
                                + j0 + part * 16;
            uint32_t dst = sbase + SM_V + buf * 10240 + row * 160 + part * 32;
            cp16(dst, src); cp16(dst + 16, src + 8);
        }
    };

    {   // Q tile (64 rows x qh) + Ts
        int row = tid >> 2, part = tid & 3;
        const __half* src = g_sq + (size_t)(i0 + row) * KSPLIT + h * HDIM + part * 16;
        uint32_t dst = sbase + row * 144 + part * 32;
        cp16(dst, src); cp16(dst + 16, src + 8);
        *(float4*)(Ts + row * 16 + part * 4) =
            *(const float4*)(g_ts + ((size_t)h * L_SEQ + i0 + row) * 16 + part * 4);
    }
    CP_COMMIT;
    load_kv(0, 0);
    CP_COMMIT;
    asm volatile("cp.async.wait_group 1;" ::: "memory");
    __syncthreads();

    int r0 = wg * 16 + gid;                    // 0..63
    uint32_t qh[4][4];
    #pragma unroll
    for (int kc = 0; kc < 4; kc++) {
        uint2 lo = *(const uint2*)&Qs[r0 * QPITCH + kc * 16 + qt * 4];
        uint2 hi = *(const uint2*)&Qs[(r0 + 8) * QPITCH + kc * 16 + qt * 4];
        qh[kc][0] = lo.x; qh[kc][1] = hi.x; qh[kc][2] = lo.y; qh[kc][3] = hi.y;
    }

    float o[8][4] = {};
    float rm0 = -1e30f, rm1 = -1e30f, rl0 = 0.f, rl1 = 0.f;
    const float* T0 = Ts + r0 * 16;
    const float* T1 = T0 + 128;
    const uint8_t* eb0 = g_eid8 + (size_t)(i0 + r0) * L_SEQ;
    const uint8_t* eb1 = eb0 + 8 * L_SEQ;

    for (int t = 0; t < 32; t++) {
        int cur = t & 1;
        if (t + 1 < 32) {
            load_kv((t + 1) * 64, cur ^ 1);
            CP_COMMIT;
            asm volatile("cp.async.wait_group 1;" ::: "memory");
        } else {
            asm volatile("cp.async.wait_group 0;" ::: "memory");
        }
        __syncthreads();
        const __half* Ks = (const __half*)(smb + SM_K + cur * 9216);
        const __half* Vt = (const __half*)(smb + SM_V + cur * 10240);
        int j0 = t * 64;

        // ---- edge-id prefetch (int8, 2 bytes per row-pair per ntl) ----
        unsigned short e0r[4], e1r[4];
        #pragma unroll
        for (int ntl = 0; ntl < 4; ntl++) {
            int col = j0 + (ngrp * 4 + ntl) * 8 + qt * 2;
            e0r[ntl] = *(const unsigned short*)(eb0 + col);
            e1r[ntl] = *(const unsigned short*)(eb1 + col);
        }

        // ---- S = qh*kh (fp32) ----
        float sa[4][4] = {};
        #pragma unroll
        for (int kc = 0; kc < 4; kc++) {
            #pragma unroll
            for (int ntl = 0; ntl < 4; ntl++) {
                int brow = (ngrp * 4 + ntl) * 8 + gid;
                uint2 kh = *(const uint2*)&Ks[brow * KPITCH + kc * 16 + qt * 4];
                mma16816(sa[ntl], qh[kc], kh.x, kh.y);
            }
        }
        #pragma unroll
        for (int ntl = 0; ntl < 4; ntl++) {
            sa[ntl][0] += T0[e0r[ntl] & 0xFF];
            sa[ntl][1] += T0[e0r[ntl] >> 8];
            sa[ntl][2] += T1[e1r[ntl] & 0xFF];
            sa[ntl][3] += T1[e1r[ntl] >> 8];
        }

        // ---- online softmax (base 2) ----
        float mx0 = -1e30f, mx1 = -1e30f;
        #pragma unroll
        for (int ntl = 0; ntl < 4; ntl++) {
            mx0 = fmaxf(mx0, fmaxf(sa[ntl][0], sa[ntl][1]));
            mx1 = fmaxf(mx1, fmaxf(sa[ntl][2], sa[ntl][3]));
        }
        mx0 = fmaxf(mx0, __shfl_xor_sync(0xffffffffu, mx0, 1));
        mx0 = fmaxf(mx0, __shfl_xor_sync(0xffffffffu, mx0, 2));
        mx1 = fmaxf(mx1, __shfl_xor_sync(0xffffffffu, mx1, 1));
        mx1 = fmaxf(mx1, __shfl_xor_sync(0xffffffffu, mx1, 2));
        float mn0 = fmaxf(rm0, mx0), mn1 = fmaxf(rm1, mx1);
        bool skip = __all_sync(0xffffffffu, (mn0 == rm0) & (mn1 == rm1));

        uint32_t ph[2][4];
        float ls[4] = {};
        #pragma unroll
        for (int kcp = 0; kcp < 2; kcp++) {
            const float* t0v = sa[2 * kcp];
            const float* t1v = sa[2 * kcp + 1];
            ph[kcp][0] = ex2h2(t0v[0] - mn0, t0v[1] - mn0);
            ph[kcp][1] = ex2h2(t0v[2] - mn1, t0v[3] - mn1);
            ph[kcp][2] = ex2h2(t1v[0] - mn0, t1v[1] - mn0);
            ph[kcp][3] = ex2h2(t1v[2] - mn1, t1v[3] - mn1);
            mma16816(ls, ph[kcp], ones2, ones2);
        }
        if (!skip) {
            float c0 = ex2f(rm0 - mn0), c1 = ex2f(rm1 - mn1);
            rl0 *= c0; rl1 *= c1;
            #pragma unroll
            for (int dt = 0; dt < 8; dt++) {
                o[dt][0] *= c0; o[dt][1] *= c0;
                o[dt][2] *= c1; o[dt][3] *= c1;
            }
            rm0 = mn0; rm1 = mn1;
        }
        rl0 += ls[0];
        rl1 += ls[2];

        // ---- PV over group's 32 j: O += ph*vh (fp32) ----
        #pragma unroll
        for (int kcp = 0; kcp < 2; kcp++) {
            int vc = ngrp * 32 + kcp * 16 + qt * 4;
            #pragma unroll
            for (int dt = 0; dt < 8; dt++) {
                int vrh = dt * 8 + gid;
                uint2 vh = *(const uint2*)&Vt[vrh * VPITCH + vc];
                mma16816(o[dt], ph[kcp], vh.x, vh.y);
            }
        }
        __syncthreads();
    }

    // ---- combine the two n-groups (reuse K region: 2x9216 >= 17408) ----
    __syncthreads();
    float* co = (float*)(smb + SM_K);            // [64][66]
    float* cm = (float*)(smb + SM_K + 16896);    // [64]
    float* cl = (float*)(smb + SM_K + 17152);    // [64]
    if (ngrp == 1) {
        if (qt == 0) {
            cm[r0] = rm0; cm[r0 + 8] = rm1;
            cl[r0] = rl0; cl[r0 + 8] = rl1;
        }
        #pragma unroll
        for (int dt = 0; dt < 8; dt++) {
            int c = dt * 8 + qt * 2;
            *(float2*)&co[r0 * 66 + c]       = make_float2(o[dt][0], o[dt][1]);
            *(float2*)&co[(r0 + 8) * 66 + c] = make_float2(o[dt][2], o[dt][3]);
        }
    }
    __syncthreads();
    if (ngrp == 0) {
        float m1a = cm[r0], l1a = cl[r0];
        float m1b = cm[r0 + 8], l1b = cl[r0 + 8];
        float M0 = fmaxf(rm0, m1a), M1 = fmaxf(rm1, m1b);
        float a0 = ex2f(rm0 - M0), b0 = ex2f(m1a - M0);
        float a1 = ex2f(rm1 - M1), b1 = ex2f(m1b - M1);
        float inv0 = 1.0f / (rl0 * a0 + l1a * b0);
        float inv1 = 1.0f / (rl1 * a1 + l1b * b1);
        __half* dst0 = g_actx + (size_t)(i0 + r0) * KSPLIT + h * HDIM;
        __half* dst1 = g_actx + (size_t)(i0 + r0 + 8) * KSPLIT + h * HDIM;
        #pragma unroll
        for (int dt = 0; dt < 8; dt++) {
            int c = dt * 8 + qt * 2;
            int cp_ = permute_paircol(c);
            float v0 = (o[dt][0] * a0 + co[r0 * 66 + c] * b0) * inv0;
            float v1 = (o[dt][1] * a0 + co[r0 * 66 + c + 1] * b0) * inv0;
            float w0 = (o[dt][2] * a1 + co[(r0 + 8) * 66 + c] * b1) * inv1;
            float w1 = (o[dt][3] * a1 + co[(r0 + 8) * 66 + c + 1] * b1) * inv1;
            store_split(dst0 + cp_, v0, v1, 1);
            store_split(dst1 + cp_, w0, w1, 1);
        }
    }
}

// ---------------------------------------------------------------------------
extern "C" void kernel_launch(void* const* d_in, const int* in_sizes, int n_in,
                              void* d_out, int out_size)
{
    const float* query = (const float*)d_in[0];
    const float* key   = (const float*)d_in[1];
    const float* value = (const float*)d_in[2];
    const int*   eid   = (const int*)d_in[3];
    const float* w_in  = (const float*)d_in[4];
    const float* b_in  = (const float*)d_in[5];
    const float* w_out = (const float*)d_in[6];
    const float* b_out = (const float*)d_in[7];
    const float* embK  = (const float*)d_in[8];
    float* out = (float*)d_out;

    // launch 0: splits + edge int8 compression
    split_all<<<20480, 256>>>(query, key, value, w_in, w_out, eid);

    // launch 1: QKV projection (q: hi+lo; k,v: hi only)
    dim3 qkv_grid(L_SEQ / 64, 12);
    gemm_qkv_kernel<<<qkv_grid, 256>>>(b_in);

    // launch 2: V transpose + type scores
    tsvt_kernel<<<2304, 256>>>(embK);

    // launch 3: flash attention
    cudaFuncSetAttribute(attn_mma_kernel, cudaFuncAttributeMaxDynamicSharedMemorySize,
                         ATTN_SMEM);
    dim3 attn_grid(L_SEQ / 64, NHEAD);
    attn_mma_kernel<<<attn_grid, 256, ATTN_SMEM>>>();

    // launch 4: out projection — hi*hi only
    dim3 out_grid(L_SEQ / 64, EMB / 64);
    gemm_out_kernel<<<out_grid, 256>>>(b_out, out);
}

// round 14
// speedup vs baseline: 1.9281x; 1.0494x over previous
#include <cuda_runtime.h>
#include <cuda_fp16.h>
#include <cstdint>

#define L_SEQ 2048
#define EMB   512
#define NHEAD 8
#define HDIM  64
#define NTYPE 10
#define KSPLIT 1536      // projected-tensor split width (hlh sections)
#define KW     1024      // qkv weight width: [w_hi | w_lo]
#define QSCALE 0.18033688011112042f   // 0.125 * log2(e)

// ---------------------------------------------------------------------------
__device__ float g_v[L_SEQ * EMB];
__device__ float g_ts[NHEAD * L_SEQ * 16];
__device__ uint8_t g_eid8[L_SEQ * L_SEQ];   // edge ids compressed to int8

__device__ __half g_aq[L_SEQ * EMB];      // hi-only activations
__device__ __half g_ak[L_SEQ * EMB];
__device__ __half g_av[L_SEQ * EMB];
__device__ __half g_wqkv[3 * EMB * KW];   // [w_hi | w_lo]
__device__ __half g_wo[EMB * KSPLIT];     // hi-only, k-cols PAIR-PERMUTED
__device__ __half g_sq[L_SEQ * KSPLIT];   // projected q (log2-scaled), hlh, permuted
__device__ __half g_sk[L_SEQ * KSPLIT];   // projected k, hhl, permuted
__device__ __half g_actx[L_SEQ * KSPLIT]; // ctx, hlh, permuted
__device__ __half g_svt[NHEAD * 2 * HDIM * L_SEQ];  // [h][vh|vl][j] permuted pairs

__device__ __forceinline__ int permute_paircol(int col) {   // col even
    int p = (col >> 1) & 7;
    return (col & ~15) + (((p & 3) * 2 + (p >> 2)) << 1);
}

// ---------------------------------------------------------------------------
__device__ __forceinline__ uint32_t packh(float lo, float hi) {
    uint32_t r;
    asm("cvt.rn.f16x2.f32 %0, %1, %2;" : "=r"(r) : "f"(hi), "f"(lo));
    return r;
}
__device__ __forceinline__ uint32_t ex2h2(float lo, float hi) {
    uint32_t r;
    asm("cvt.rn.f16x2.f32 %0, %1, %2;" : "=r"(r) : "f"(hi), "f"(lo));
    asm("ex2.approx.f16x2 %0, %0;" : "+r"(r));
    return r;
}
__device__ __forceinline__ float ex2f(float x) {
    float r;
    asm("ex2.approx.f32 %0, %1;" : "=f"(r) : "f"(x));
    return r;
}
__device__ __forceinline__ float2 unph(uint32_t u) {
    __half2 h = *reinterpret_cast<__half2*>(&u);
    return __half22float2(h);
}
__device__ __forceinline__ uint32_t smem_to_u32(const void* p) {
    uint32_t a;
    asm("{ .reg .u64 t; cvta.to.shared.u64 t, %1; cvt.u32.u64 %0, t; }"
        : "=r"(a) : "l"(p));
    return a;
}
__device__ __forceinline__ void mma16816(float* d, const uint32_t* a,
                                         uint32_t b0, uint32_t b1) {
    asm volatile(
        "mma.sync.aligned.m16n8k16.row.col.f32.f16.f16.f32 "
        "{%0,%1,%2,%3}, {%4,%5,%6,%7}, {%8,%9}, {%0,%1,%2,%3};"
        : "+f"(d[0]), "+f"(d[1]), "+f"(d[2]), "+f"(d[3])
        : "r"(a[0]), "r"(a[1]), "r"(a[2]), "r"(a[3]), "r"(b0), "r"(b1));
}
__device__ __forceinline__ void mma16816h(uint32_t* c, const uint32_t* a,
                                          uint32_t b0, uint32_t b1) {
    asm volatile(
        "mma.sync.aligned.m16n8k16.row.col.f16.f16.f16.f16 "
        "{%0,%1}, {%2,%3,%4,%5}, {%6,%7}, {%0,%1};"
        : "+r"(c[0]), "+r"(c[1])
        : "r"(a[0]), "r"(a[1]), "r"(a[2]), "r"(a[3]), "r"(b0), "r"(b1));
}
__device__ __forceinline__ void cp16(uint32_t s, const void* g) {
    asm volatile("cp.async.cg.shared.global [%0], [%1], 16;"
                 :: "r"(s), "l"(g) : "memory");
}
#define CP_COMMIT asm volatile("cp.async.commit_group;" ::: "memory")

__device__ __forceinline__ void store_split(__half* d, float v0, float v1,
                                            int mode) {
    float h0 = __half2float(__float2half(v0));
    float h1 = __half2float(__float2half(v1));
    uint32_t hh = packh(h0, h1), ll = packh(v0 - h0, v1 - h1);
    *(uint32_t*)d          = hh;
    *(uint32_t*)(d + 512)  = (mode == 1) ? ll : hh;
    *(uint32_t*)(d + 1024) = (mode == 1) ? hh : ll;
}

// ---------------------------------------------------------------------------
// ONE fused split kernel: activations hi-only; w_in [hi|lo]; w_out hi perm;
// edge_id int32 -> int8 compression.
// ---------------------------------------------------------------------------
__global__ __launch_bounds__(256) void split_all(
    const float* __restrict__ q, const float* __restrict__ k,
    const float* __restrict__ v, const float* __restrict__ w,
    const float* __restrict__ wo, const int* __restrict__ eid) {
    int idx = blockIdx.x * 256 + threadIdx.x;   // 0 .. 5242879
    if (idx < 3145728) {                        // activations: plain fp16
        const float* src = idx < 1048576 ? q : (idx < 2097152 ? k : v);
        __half* dst = idx < 1048576 ? g_aq : (idx < 2097152 ? g_ak : g_av);
        int li = idx & 1048575;
        dst[li] = __float2half(src[li]);
    } else if (idx < 3932160) {                 // w_in: [hi | lo], width 1024
        int li = idx - 3145728;
        int r = li >> 9, c = li & 511;
        float x = w[li];
        __half h = __float2half(x);
        __half l = __float2half(x - __half2float(h));
        __half* yr = g_wqkv + (size_t)r * KW;
        yr[c] = h; yr[512 + c] = l;
    } else if (idx < 4194304) {                 // w_out: hi only, permuted
        int li = idx - 3932160;
        int r = li >> 9, c = li & 511;
        int cp_ = permute_paircol(c & ~1) + (c & 1);
        g_wo[(size_t)r * KSPLIT + cp_] = __float2half(wo[li]);
    } else {                                    // edge compression: int4->uchar4
        int li = idx - 4194304;                 // 0 .. 1048575
        int4 e = *(const int4*)(eid + (size_t)li * 4);
        uchar4 c = make_uchar4((unsigned char)e.x, (unsigned char)e.y,
                               (unsigned char)e.z, (unsigned char)e.w);
        *(uchar4*)(g_eid8 + (size_t)li * 4) = c;
    }
}

// ---------------------------------------------------------------------------
// GEMM: 64 x (32*NF) block tile, 8 warps, warp tile 32 x (8*NF).
// ---------------------------------------------------------------------------
template <int NF, int KITERS, int KAMASK>
__device__ __forceinline__ void gemm_core(const __half* __restrict__ A,
                                          const __half* __restrict__ B,
                                          const float* __restrict__ bias,
                                          float* __restrict__ Cf,
                                          __half* __restrict__ Cs,
                                          int cn0, int m0, float scale, int mode,
                                          int lda, int ldb) {
    constexpr int BROWS = 32 * NF;
    __shared__ __half As[2][64 * 40];
    __shared__ __half Bs[2][BROWS * 40];
    int tid = threadIdx.x, wid = tid >> 5, lane = tid & 31;
    int gid = lane >> 2, qt = lane & 3;
    int wm = wid >> 2, wn = wid & 3;

    float acc[2][NF][4] = {};
    uint32_t acch[2][NF][2] = {};
    int lrA = tid >> 2, lcA = (tid & 3) * 8;
    const __half* Ap = A + (size_t)(m0 + lrA) * lda + lcA;
    int lrB = (NF == 4) ? (tid >> 1) : (tid >> 2);
    int lcB = (NF == 4) ? ((tid & 1) * 16) : ((tid & 3) * 8);
    const __half* Bp = B + (size_t)lrB * ldb + lcB;
    uint32_t sA[2] = {smem_to_u32(&As[0][lrA * 40 + lcA]),
                      smem_to_u32(&As[1][lrA * 40 + lcA])};
    uint32_t sB[2] = {smem_to_u32(&Bs[0][lrB * 40 + lcB]),
                      smem_to_u32(&Bs[1][lrB * 40 + lcB])};

    cp16(sA[0], Ap);
    cp16(sB[0], Bp);
    if (NF == 4) cp16(sB[0] + 16, Bp + 8);
    CP_COMMIT;

    for (int kt = 0; kt < KITERS; kt++) {
        int cur = kt & 1;
        if (kt + 1 < KITERS) {
            int nx = cur ^ 1;
            const __half* a = Ap + ((kt + 1) & KAMASK) * 32;
            const __half* b = Bp + (kt + 1) * 32;
            cp16(sA[nx], a);
            cp16(sB[nx], b);
            if (NF == 4) cp16(sB[nx] + 16, b + 8);
            CP_COMMIT;
            asm volatile("cp.async.wait_group 1;" ::: "memory");
        } else {
            asm volatile("cp.async.wait_group 0;" ::: "memory");
        }
        __syncthreads();
        bool hi_term = (kt < 16);
        #pragma unroll
        for (int kc = 0; kc < 2; kc++) {
            uint32_t a[2][4];
            #pragma unroll
            for (int mf = 0; mf < 2; mf++) {
                int r = wm * 32 + mf * 16 + gid;
                int c = kc * 16 + qt * 2;
                a[mf][0] = *(const uint32_t*)&As[cur][r * 40 + c];
                a[mf][1] = *(const uint32_t*)&As[cur][(r + 8) * 40 + c];
                a[mf][2] = *(const uint32_t*)&As[cur][r * 40 + c + 8];
                a[mf][3] = *(const uint32_t*)&As[cur][(r + 8) * 40 + c + 8];
            }
            #pragma unroll
            for (int nf = 0; nf < NF; nf++) {
                int n = wn * (8 * NF) + nf * 8 + gid;
                int c = kc * 16 + qt * 2;
                uint32_t b0 = *(const uint32_t*)&Bs[cur][n * 40 + c];
                uint32_t b1 = *(const uint32_t*)&Bs[cur][n * 40 + c + 8];
                if (hi_term) {
                    #pragma unroll
                    for (int mf = 0; mf < 2; mf++)
                        mma16816(acc[mf][nf], a[mf], b0, b1);
                } else {
                    #pragma unroll
                    for (int mf = 0; mf < 2; mf++)
                        mma16816h(acch[mf][nf], a[mf], b0, b1);
                }
            }
        }
        __syncthreads();
    }
    #pragma unroll
    for (int mf = 0; mf < 2; mf++) {
        int r = m0 + wm * 32 + mf * 16 + gid;
        #pragma unroll
        for (int nf = 0; nf < NF; nf++) {
            int cb = wn * (8 * NF) + nf * 8 + qt * 2;
            float b0 = __ldg(bias + cb), b1 = __ldg(bias + cb + 1);
            float2 c0 = unph(acch[mf][nf][0]);
            float2 c1 = unph(acch[mf][nf][1]);
            float v00 = scale * (acc[mf][nf][0] + c0.x + b0);
            float v01 = scale * (acc[mf][nf][1] + c0.y + b1);
            float v10 = scale * (acc[mf][nf][2] + c1.x + b0);
            float v11 = scale * (acc[mf][nf][3] + c1.y + b1);
            int col = cn0 + cb;
            if (mode == 0) {
                *(float2*)&Cf[(size_t)r * EMB + col]       = make_float2(v00, v01);
                *(float2*)&Cf[(size_t)(r + 8) * EMB + col] = make_float2(v10, v11);
            } else {
                int colp = permute_paircol(col);
                store_split(Cs + (size_t)r * KSPLIT + colp, v00, v01, mode);
                store_split(Cs + (size_t)(r + 8) * KSPLIT + colp, v10, v11, mode);
            }
        }
    }
}

__global__ void __launch_bounds__(256, 2) gemm_qkv_kernel(const float* __restrict__ bias) {
    int m0 = blockIdx.x * 64;
    int nt = blockIdx.y;          // 0..11
    int sect = nt >> 2;
    int cn0 = (nt & 3) * 128;
    const __half* Bw = g_wqkv + (size_t)nt * 128 * KW;
    if (sect == 0)        // q keeps w_lo refinement (feeds edge LUT)
        gemm_core<4, 32, 15>(g_aq, Bw, bias + nt * 128, nullptr, g_sq,
                             cn0, m0, QSCALE, 1, EMB, KW);
    else if (sect == 1)   // k: hi*hi only
        gemm_core<4, 16, 15>(g_ak, Bw, bias + nt * 128, nullptr, g_sk,
                             cn0, m0, 1.0f, 2, EMB, KW);
    else                  // v: hi*hi only
        gemm_core<4, 16, 15>(g_av, Bw, bias + nt * 128, g_v, nullptr,
                             cn0, m0, 1.0f, 0, EMB, KW);
}
__global__ void __launch_bounds__(256, 2) gemm_out_kernel(const float* __restrict__ bias,
                                                          float* __restrict__ C) {
    gemm_core<2, 16, 63>(g_actx, g_wo + (size_t)blockIdx.y * 64 * KSPLIT,
                         bias + blockIdx.y * 64, C, nullptr, blockIdx.y * 64,
                         blockIdx.x * 64, 1.0f, 0, KSPLIT, KSPLIT);
}

// ---------------------------------------------------------------------------
// Fused: V split+transpose (blocks 0..255) + type_scores (blocks 256..2303)
// ---------------------------------------------------------------------------
__global__ __launch_bounds__(256) void tsvt_kernel(const float* __restrict__ edge_embs) {
    __shared__ float sh[64 * 68];
    int tid = threadIdx.x;
    if (blockIdx.x < 256) {
        int h = blockIdx.x >> 5, j0 = (blockIdx.x & 31) * 64;
        {
            int row = tid >> 2, cg = (tid & 3) * 16;
            const float* src = g_v + (size_t)(j0 + row) * EMB + h * HDIM + cg;
            #pragma unroll
            for (int i = 0; i < 4; i++)
                *(float4*)&sh[row * 68 + cg + i * 4] = *(const float4*)(src + i * 4);
        }
        __syncthreads();
        int d = tid >> 2, jg = (tid & 3) * 16;
        uint32_t hw[8];
        #pragma unroll
        for (int p = 0; p < 8; p++) {
            float v0 = sh[(jg + 2 * p) * 68 + d], v1 = sh[(jg + 2 * p + 1) * 68 + d];
            hw[p] = packh(v0, v1);
        }
        __half* dsth = g_svt + ((size_t)(h * 128 + d) * L_SEQ + j0 + jg);
        *(uint4*)dsth       = make_uint4(hw[0], hw[4], hw[1], hw[5]);
        *(uint4*)(dsth + 8) = make_uint4(hw[2], hw[6], hw[3], hw[7]);
    } else {
        float* emb = sh;
        for (int i = tid; i < NTYPE * HDIM; i += 256) emb[i] = edge_embs[i];
        __syncthreads();
        int warp = (blockIdx.x - 256) * 8 + (tid >> 5);
        int lane = tid & 31;
        int h = warp >> 11, i = warp & (L_SEQ - 1);
        int pw = lane & 7;
        int colp = (lane >> 3) * 16 + ((pw & 3) * 2 + (pw >> 2)) * 2;
        const __half* qr = g_sq + (size_t)i * KSPLIT + h * HDIM + colp;
        float2 qh = __half22float2(*(const __half2*)qr);
        float2 ql = __half22float2(*(const __half2*)(qr + 512));
        float2 qv = make_float2(qh.x + ql.x, qh.y + ql.y);
        float s[NTYPE];
        #pragma unroll
        for (int t = 0; t < NTYPE; t++) {
            float2 e = *(const float2*)(emb + t * HDIM + lane * 2);
            s[t] = qv.x * e.x + qv.y * e.y;
        }
        #pragma unroll
        for (int off = 16; off > 0; off >>= 1)
            #pragma unroll
            for (int t = 0; t < NTYPE; t++)
                s[t] += __shfl_xor_sync(0xffffffffu, s[t], off);
        if (lane == 0) {
            float* dst = g_ts + (size_t)warp * 16;
            #pragma unroll
            for (int t = 0; t < NTYPE; t++) dst[t] = s[t];
        }
    }
}

// ---------------------------------------------------------------------------
// Flash attention: i-tile 64, 8 warps = 2 independent 4-warp groups.
// Each group owns PRIVATE double-buffered K/V half-tiles (its 32-j slice) and
// syncs via named barriers only -> groups fully decoupled. Conflict-free
// pitches: Q/K 160B, V 80B. End: cross-group softmax combine.
// smem: Q 10240 @0, K 2grp x 2buf x 5120 @10240, V same @30720, Ts @51200.
// total 55296. 2 CTAs/SM.
// ---------------------------------------------------------------------------
#define QPITCH 80    // halfs
#define KPITCH 80    // halfs (local half-tile rows)
#define VPITCH 40    // halfs (local 32-j rows)
#define SM_K 10240
#define SM_V 30720
#define SM_T 51200
#define ATTN_SMEM 55296

__global__ void __launch_bounds__(256, 2) attn_mma_kernel() {
    extern __shared__ char smb[];
    __half* Qs = (__half*)smb;
    float* Ts = (float*)(smb + SM_T);
    uint32_t sbase = smem_to_u32(smb);

    int h = blockIdx.y;
    int i0 = blockIdx.x * 64;
    int tid = threadIdx.x, wid = tid >> 5, lane = tid & 31;
    int gid = lane >> 2, qt = lane & 3;
    int ngrp = wid >> 2, wg = wid & 3, gtid = tid & 127;
    const uint32_t ones2 = 0x3C003C00u;
    const uint32_t kbase = sbase + SM_K + ngrp * 10240;
    const uint32_t vbase = sbase + SM_V + ngrp * 10240;

    auto load_kv = [&](int j0, int buf) {
        {   // K half-tile: 32 j-rows x 64 halfs, pitch 160B
            int row = gtid >> 2, part = gtid & 3;
            const __half* src = g_sk + (size_t)(j0 + ngrp * 32 + row) * KSPLIT
                                + h * HDIM + part * 16;
            uint32_t dst = kbase + buf * 5120 + row * 160 + part * 32;
            cp16(dst, src); cp16(dst + 16, src + 8);
        }
        {   // V half: 64 d-rows x 32 j, pitch 80B
            int row = gtid >> 1, part = gtid & 1;
            const __half* src = g_svt + (size_t)(h * 128 + row) * L_SEQ
                                + j0 + ngrp * 32 + part * 16;
            uint32_t dst = vbase + buf * 5120 + row * 80 + part * 32;
            cp16(dst, src); cp16(dst + 16, src + 8);
        }
    };

    {   // Q tile (64 rows x qh, pitch 160B) + Ts — all 256 threads
        int row = tid >> 2, part = tid & 3;
        const __half* src = g_sq + (size_t)(i0 + row) * KSPLIT + h * HDIM + part * 16;
        uint32_t dst = sbase + row * 160 + part * 32;
        cp16(dst, src); cp16(dst + 16, src + 8);
        *(float4*)(Ts + row * 16 + part * 4) =
            *(const float4*)(g_ts + ((size_t)h * L_SEQ + i0 + row) * 16 + part * 4);
    }
    load_kv(0, 0);
    CP_COMMIT;
    asm volatile("cp.async.wait_group 0;" ::: "memory");
    __syncthreads();

    int r0 = wg * 16 + gid;                    // 0..63
    uint32_t qh[4][4];
    #pragma unroll
    for (int kc = 0; kc < 4; kc++) {
        uint2 lo = *(const uint2*)&Qs[r0 * QPITCH + kc * 16 + qt * 4];
        uint2 hi = *(const uint2*)&Qs[(r0 + 8) * QPITCH + kc * 16 + qt * 4];
        qh[kc][0] = lo.x; qh[kc][1] = hi.x; qh[kc][2] = lo.y; qh[kc][3] = hi.y;
    }

    float o[8][4] = {};
    float rm0 = -1e30f, rm1 = -1e30f, rl0 = 0.f, rl1 = 0.f;
    const float* T0 = Ts + r0 * 16;
    const float* T1 = T0 + 128;
    const uint8_t* eb0 = g_eid8 + (size_t)(i0 + r0) * L_SEQ;
    const uint8_t* eb1 = eb0 + 8 * L_SEQ;
    const int bid = ngrp + 1;

    for (int t = 0; t < 32; t++) {
        int cur = t & 1;
        if (t + 1 < 32) {
            load_kv((t + 1) * 64, cur ^ 1);
            CP_COMMIT;
            asm volatile("cp.async.wait_group 1;" ::: "memory");
        } else {
            asm volatile("cp.async.wait_group 0;" ::: "memory");
        }
        asm volatile("bar.sync %0, 128;" :: "r"(bid) : "memory");
        const __half* Ks = (const __half*)(smb + SM_K + ngrp * 10240 + cur * 5120);
        const __half* Vt = (const __half*)(smb + SM_V + ngrp * 10240 + cur * 5120);
        int j0 = t * 64;

        // ---- edge-id prefetch (int8) ----
        unsigned short e0r[4], e1r[4];
        #pragma unroll
        for (int ntl = 0; ntl < 4; ntl++) {
            int col = j0 + (ngrp * 4 + ntl) * 8 + qt * 2;
            e0r[ntl] = *(const unsigned short*)(eb0 + col);
            e1r[ntl] = *(const unsigned short*)(eb1 + col);
        }

        // ---- S = qh*kh (fp32), local K rows ----
        float sa[4][4] = {};
        #pragma unroll
        for (int kc = 0; kc < 4; kc++) {
            #pragma unroll
            for (int ntl = 0; ntl < 4; ntl++) {
                int brow = ntl * 8 + gid;      // local 0..31
                uint2 kh = *(const uint2*)&Ks[brow * KPITCH + kc * 16 + qt * 4];
                mma16816(sa[ntl], qh[kc], kh.x, kh.y);
            }
        }
        #pragma unroll
        for (int ntl = 0; ntl < 4; ntl++) {
            sa[ntl][0] += T0[e0r[ntl] & 0xFF];
            sa[ntl][1] += T0[e0r[ntl] >> 8];
            sa[ntl][2] += T1[e1r[ntl] & 0xFF];
            sa[ntl][3] += T1[e1r[ntl] >> 8];
        }

        // ---- online softmax (base 2) ----
        float mx0 = -1e30f, mx1 = -1e30f;
        #pragma unroll
        for (int ntl = 0; ntl < 4; ntl++) {
            mx0 = fmaxf(mx0, fmaxf(sa[ntl][0], sa[ntl][1]));
            mx1 = fmaxf(mx1, fmaxf(sa[ntl][2], sa[ntl][3]));
        }
        mx0 = fmaxf(mx0, __shfl_xor_sync(0xffffffffu, mx0, 1));
        mx0 = fmaxf(mx0, __shfl_xor_sync(0xffffffffu, mx0, 2));
        mx1 = fmaxf(mx1, __shfl_xor_sync(0xffffffffu, mx1, 1));
        mx1 = fmaxf(mx1, __shfl_xor_sync(0xffffffffu, mx1, 2));
        float mn0 = fmaxf(rm0, mx0), mn1 = fmaxf(rm1, mx1);
        bool skip = __all_sync(0xffffffffu, (mn0 == rm0) & (mn1 == rm1));

        uint32_t ph[2][4];
        float ls[4] = {};
        #pragma unroll
        for (int kcp = 0; kcp < 2; kcp++) {
            const float* t0v = sa[2 * kcp];
            const float* t1v = sa[2 * kcp + 1];
            ph[kcp][0] = ex2h2(t0v[0] - mn0, t0v[1] - mn0);
            ph[kcp][1] = ex2h2(t0v[2] - mn1, t0v[3] - mn1);
            ph[kcp][2] = ex2h2(t1v[0] - mn0, t1v[1] - mn0);
            ph[kcp][3] = ex2h2(t1v[2] - mn1, t1v[3] - mn1);
            mma16816(ls, ph[kcp], ones2, ones2);
        }
        if (!skip) {
            float c0 = ex2f(rm0 - mn0), c1 = ex2f(rm1 - mn1);
            rl0 *= c0; rl1 *= c1;
            #pragma unroll
            for (int dt = 0; dt < 8; dt++) {
                o[dt][0] *= c0; o[dt][1] *= c0;
                o[dt][2] *= c1; o[dt][3] *= c1;
            }
            rm0 = mn0; rm1 = mn1;
        }
        rl0 += ls[0];
        rl1 += ls[2];

        // ---- PV over group's 32 j (local V cols) ----
        #pragma unroll
        for (int kcp = 0; kcp < 2; kcp++) {
            int vc = kcp * 16 + qt * 4;
            #pragma unroll
            for (int dt = 0; dt < 8; dt++) {
                int vrh = dt * 8 + gid;
                uint2 vh = *(const uint2*)&Vt[vrh * VPITCH + vc];
                mma16816(o[dt], ph[kcp], vh.x, vh.y);
            }
        }
        asm volatile("bar.sync %0, 128;" :: "r"(bid) : "memory");
    }

    // ---- combine the two n-groups (reuse K/V region) ----
    __syncthreads();
    float* co = (float*)(smb + SM_K);            // [64][66]
    float* cm = (float*)(smb + SM_K + 16896);    // [64]
    float* cl = (float*)(smb + SM_K + 17152);    // [64]
    if (ngrp == 1) {
        if (qt == 0) {
            cm[r0] = rm0; cm[r0 + 8] = rm1;
            cl[r0] = rl0; cl[r0 + 8] = rl1;
        }
        #pragma unroll
        for (int dt = 0; dt < 8; dt++) {
            int c = dt * 8 + qt * 2;
            *(float2*)&co[r0 * 66 + c]       = make_float2(o[dt][0], o[dt][1]);
            *(float2*)&co[(r0 + 8) * 66 + c] = make_float2(o[dt][2], o[dt][3]);
        }
    }
    __syncthreads();
    if (ngrp == 0) {
        float m1a = cm[r0], l1a = cl[r0];
        float m1b = cm[r0 + 8], l1b = cl[r0 + 8];
        float M0 = fmaxf(rm0, m1a), M1 = fmaxf(rm1, m1b);
        float a0 = ex2f(rm0 - M0), b0 = ex2f(m1a - M0);
        float a1 = ex2f(rm1 - M1), b1 = ex2f(m1b - M1);
        float inv0 = 1.0f / (rl0 * a0 + l1a * b0);
        float inv1 = 1.0f / (rl1 * a1 + l1b * b1);
        __half* dst0 = g_actx + (size_t)(i0 + r0) * KSPLIT + h * HDIM;
        __half* dst1 = g_actx + (size_t)(i0 + r0 + 8) * KSPLIT + h * HDIM;
        #pragma unroll
        for (int dt = 0; dt < 8; dt++) {
            int c = dt * 8 + qt * 2;
            int cp_ = permute_paircol(c);
            float v0 = (o[dt][0] * a0 + co[r0 * 66 + c] * b0) * inv0;
            float v1 = (o[dt][1] * a0 + co[r0 * 66 + c + 1] * b0) * inv0;
            float w0 = (o[dt][2] * a1 + co[(r0 + 8) * 66 + c] * b1) * inv1;
            float w1 = (o[dt][3] * a1 + co[(r0 + 8) * 66 + c + 1] * b1) * inv1;
            store_split(dst0 + cp_, v0, v1, 1);
            store_split(dst1 + cp_, w0, w1, 1);
        }
    }
}

// ---------------------------------------------------------------------------
extern "C" void kernel_launch(void* const* d_in, const int* in_sizes, int n_in,
                              void* d_out, int out_size)
{
    const float* query = (const float*)d_in[0];
    const float* key   = (const float*)d_in[1];
    const float* value = (const float*)d_in[2];
    const int*   eid   = (const int*)d_in[3];
    const float* w_in  = (const float*)d_in[4];
    const float* b_in  = (const float*)d_in[5];
    const float* w_out = (const float*)d_in[6];
    const float* b_out = (const float*)d_in[7];
    const float* embK  = (const float*)d_in[8];
    float* out = (float*)d_out;

    // launch 0: splits + edge int8 compression
    split_all<<<20480, 256>>>(query, key, value, w_in, w_out, eid);

    // launch 1: QKV projection (q: hi+lo; k,v: hi only)
    dim3 qkv_grid(L_SEQ / 64, 12);
    gemm_qkv_kernel<<<qkv_grid, 256>>>(b_in);

    // launch 2: V transpose + type scores
    tsvt_kernel<<<2304, 256>>>(embK);

    // launch 3: flash attention (decoupled groups, conflict-free pitches)
    cudaFuncSetAttribute(attn_mma_kernel, cudaFuncAttributeMaxDynamicSharedMemorySize,
                         ATTN_SMEM);
    dim3 attn_grid(L_SEQ / 64, NHEAD);
    attn_mma_kernel<<<attn_grid, 256, ATTN_SMEM>>>();

    // launch 4: out projection — hi*hi only
    dim3 out_grid(L_SEQ / 64, EMB / 64);
    gemm_out_kernel<<<out_grid, 256>>>(b_out, out);
}

// round 16
// speedup vs baseline: 2.0723x; 1.0748x over previous
#include <cuda_runtime.h>
#include <cuda_fp16.h>
#include <cstdint>

#define L_SEQ 2048
#define EMB   512
#define NHEAD 8
#define HDIM  64
#define NTYPE 10
#define KW    1024      // qkv weight width: [w_hi | w_lo]
#define QW    1024      // projected q width: [hi | lo]
#define QSCALE 0.18033688011112042f   // 0.125 * log2(e)

// ---------------------------------------------------------------------------
__device__ float g_v[L_SEQ * EMB];
__device__ float g_ts[NHEAD * L_SEQ * 16];
__device__ uint8_t g_eid8[L_SEQ * L_SEQ];

__device__ __half g_aq[L_SEQ * EMB];      // hi-only activations
__device__ __half g_ak[L_SEQ * EMB];
__device__ __half g_av[L_SEQ * EMB];
__device__ __half g_wqkv[3 * EMB * KW];   // [w_hi | w_lo]
__device__ __half g_wo[EMB * EMB];        // hi-only, natural
__device__ __half g_sq[L_SEQ * QW];       // projected q (log2-scaled) [hi|lo]
__device__ __half g_sk[L_SEQ * EMB];      // projected k, fp16, natural
__device__ __half g_actx[L_SEQ * EMB];    // ctx, fp16, natural
__device__ __half g_svt[NHEAD * HDIM * L_SEQ];  // [h][d][j] natural

// ---------------------------------------------------------------------------
__device__ __forceinline__ uint32_t packh(float lo, float hi) {
    uint32_t r;
    asm("cvt.rn.f16x2.f32 %0, %1, %2;" : "=r"(r) : "f"(hi), "f"(lo));
    return r;
}
__device__ __forceinline__ uint32_t ex2h2(float lo, float hi) {
    uint32_t r;
    asm("cvt.rn.f16x2.f32 %0, %1, %2;" : "=r"(r) : "f"(hi), "f"(lo));
    asm("ex2.approx.f16x2 %0, %0;" : "+r"(r));
    return r;
}
__device__ __forceinline__ float ex2f(float x) {
    float r;
    asm("ex2.approx.f32 %0, %1;" : "=f"(r) : "f"(x));
    return r;
}
__device__ __forceinline__ float2 unph(uint32_t u) {
    __half2 h = *reinterpret_cast<__half2*>(&u);
    return __half22float2(h);
}
__device__ __forceinline__ uint32_t smem_to_u32(const void* p) {
    uint32_t a;
    asm("{ .reg .u64 t; cvta.to.shared.u64 t, %1; cvt.u32.u64 %0, t; }"
        : "=r"(a) : "l"(p));
    return a;
}
__device__ __forceinline__ void mma16816(float* d, const uint32_t* a,
                                         uint32_t b0, uint32_t b1) {
    asm volatile(
        "mma.sync.aligned.m16n8k16.row.col.f32.f16.f16.f32 "
        "{%0,%1,%2,%3}, {%4,%5,%6,%7}, {%8,%9}, {%0,%1,%2,%3};"
        : "+f"(d[0]), "+f"(d[1]), "+f"(d[2]), "+f"(d[3])
        : "r"(a[0]), "r"(a[1]), "r"(a[2]), "r"(a[3]), "r"(b0), "r"(b1));
}
__device__ __forceinline__ void mma16816h(uint32_t* c, const uint32_t* a,
                                          uint32_t b0, uint32_t b1) {
    asm volatile(
        "mma.sync.aligned.m16n8k16.row.col.f16.f16.f16.f16 "
        "{%0,%1}, {%2,%3,%4,%5}, {%6,%7}, {%0,%1};"
        : "+r"(c[0]), "+r"(c[1])
        : "r"(a[0]), "r"(a[1]), "r"(a[2]), "r"(a[3]), "r"(b0), "r"(b1));
}
__device__ __forceinline__ void ldsm4(uint32_t& r0, uint32_t& r1,
                                      uint32_t& r2, uint32_t& r3, uint32_t a) {
    asm volatile("ldmatrix.sync.aligned.m8n8.x4.shared.b16 {%0,%1,%2,%3}, [%4];"
                 : "=r"(r0), "=r"(r1), "=r"(r2), "=r"(r3) : "r"(a));
}
__device__ __forceinline__ void cp16(uint32_t s, const void* g) {
    asm volatile("cp.async.cg.shared.global [%0], [%1], 16;"
                 :: "r"(s), "l"(g) : "memory");
}
#define CP_COMMIT asm volatile("cp.async.commit_group;" ::: "memory")

// ---------------------------------------------------------------------------
// ONE fused split kernel
// ---------------------------------------------------------------------------
__global__ __launch_bounds__(256) void split_all(
    const float* __restrict__ q, const float* __restrict__ k,
    const float* __restrict__ v, const float* __restrict__ w,
    const float* __restrict__ wo, const int* __restrict__ eid) {
    int idx = blockIdx.x * 256 + threadIdx.x;   // 0 .. 5242879
    if (idx < 3145728) {                        // activations: plain fp16
        const float* src = idx < 1048576 ? q : (idx < 2097152 ? k : v);
        __half* dst = idx < 1048576 ? g_aq : (idx < 2097152 ? g_ak : g_av);
        int li = idx & 1048575;
        dst[li] = __float2half(src[li]);
    } else if (idx < 3932160) {                 // w_in: [hi | lo]
        int li = idx - 3145728;
        int r = li >> 9, c = li & 511;
        float x = w[li];
        __half h = __float2half(x);
        __half l = __float2half(x - __half2float(h));
        __half* yr = g_wqkv + (size_t)r * KW;
        yr[c] = h; yr[512 + c] = l;
    } else if (idx < 4194304) {                 // w_out: hi only, natural
        int li = idx - 3932160;
        g_wo[li] = __float2half(wo[li]);
    } else {                                    // edge int4->uchar4
        int li = idx - 4194304;
        int4 e = *(const int4*)(eid + (size_t)li * 4);
        uchar4 c = make_uchar4((unsigned char)e.x, (unsigned char)e.y,
                               (unsigned char)e.z, (unsigned char)e.w);
        *(uchar4*)(g_eid8 + (size_t)li * 4) = c;
    }
}

// ---------------------------------------------------------------------------
// GEMM: 64 x (32*NF) block tile, 8 warps, warp tile 32 x (8*NF).
// mode 0: fp32 out; mode 1: q [hi|lo] width 1024; mode 4: plain fp16 width 512
// ---------------------------------------------------------------------------
template <int NF, int KITERS, int KAMASK>
__device__ __forceinline__ void gemm_core(const __half* __restrict__ A,
                                          const __half* __restrict__ B,
                                          const float* __restrict__ bias,
                                          float* __restrict__ Cf,
                                          __half* __restrict__ Cs,
                                          int cn0, int m0, float scale, int mode,
                                          int lda, int ldb) {
    constexpr int BROWS = 32 * NF;
    __shared__ __half As[2][64 * 40];
    __shared__ __half Bs[2][BROWS * 40];
    int tid = threadIdx.x, wid = tid >> 5, lane = tid & 31;
    int gid = lane >> 2, qt = lane & 3;
    int wm = wid >> 2, wn = wid & 3;

    float acc[2][NF][4] = {};
    uint32_t acch[2][NF][2] = {};
    int lrA = tid >> 2, lcA = (tid & 3) * 8;
    const __half* Ap = A + (size_t)(m0 + lrA) * lda + lcA;
    int lrB = (NF == 4) ? (tid >> 1) : (tid >> 2);
    int lcB = (NF == 4) ? ((tid & 1) * 16) : ((tid & 3) * 8);
    const __half* Bp = B + (size_t)lrB * ldb + lcB;
    uint32_t sA[2] = {smem_to_u32(&As[0][lrA * 40 + lcA]),
                      smem_to_u32(&As[1][lrA * 40 + lcA])};
    uint32_t sB[2] = {smem_to_u32(&Bs[0][lrB * 40 + lcB]),
                      smem_to_u32(&Bs[1][lrB * 40 + lcB])};

    cp16(sA[0], Ap);
    cp16(sB[0], Bp);
    if (NF == 4) cp16(sB[0] + 16, Bp + 8);
    CP_COMMIT;

    for (int kt = 0; kt < KITERS; kt++) {
        int cur = kt & 1;
        if (kt + 1 < KITERS) {
            int nx = cur ^ 1;
            const __half* a = Ap + ((kt + 1) & KAMASK) * 32;
            const __half* b = Bp + (kt + 1) * 32;
            cp16(sA[nx], a);
            cp16(sB[nx], b);
            if (NF == 4) cp16(sB[nx] + 16, b + 8);
            CP_COMMIT;
            asm volatile("cp.async.wait_group 1;" ::: "memory");
        } else {
            asm volatile("cp.async.wait_group 0;" ::: "memory");
        }
        __syncthreads();
        bool hi_term = (kt < 16);
        #pragma unroll
        for (int kc = 0; kc < 2; kc++) {
            uint32_t a[2][4];
            #pragma unroll
            for (int mf = 0; mf < 2; mf++) {
                int r = wm * 32 + mf * 16 + gid;
                int c = kc * 16 + qt * 2;
                a[mf][0] = *(const uint32_t*)&As[cur][r * 40 + c];
                a[mf][1] = *(const uint32_t*)&As[cur][(r + 8) * 40 + c];
                a[mf][2] = *(const uint32_t*)&As[cur][r * 40 + c + 8];
                a[mf][3] = *(const uint32_t*)&As[cur][(r + 8) * 40 + c + 8];
            }
            #pragma unroll
            for (int nf = 0; nf < NF; nf++) {
                int n = wn * (8 * NF) + nf * 8 + gid;
                int c = kc * 16 + qt * 2;
                uint32_t b0 = *(const uint32_t*)&Bs[cur][n * 40 + c];
                uint32_t b1 = *(const uint32_t*)&Bs[cur][n * 40 + c + 8];
                if (hi_term) {
                    #pragma unroll
                    for (int mf = 0; mf < 2; mf++)
                        mma16816(acc[mf][nf], a[mf], b0, b1);
                } else {
                    #pragma unroll
                    for (int mf = 0; mf < 2; mf++)
                        mma16816h(acch[mf][nf], a[mf], b0, b1);
                }
            }
        }
        __syncthreads();
    }
    #pragma unroll
    for (int mf = 0; mf < 2; mf++) {
        int r = m0 + wm * 32 + mf * 16 + gid;
        #pragma unroll
        for (int nf = 0; nf < NF; nf++) {
            int cb = wn * (8 * NF) + nf * 8 + qt * 2;
            float b0 = __ldg(bias + cb), b1 = __ldg(bias + cb + 1);
            float2 c0 = unph(acch[mf][nf][0]);
            float2 c1 = unph(acch[mf][nf][1]);
            float v00 = scale * (acc[mf][nf][0] + c0.x + b0);
            float v01 = scale * (acc[mf][nf][1] + c0.y + b1);
            float v10 = scale * (acc[mf][nf][2] + c1.x + b0);
            float v11 = scale * (acc[mf][nf][3] + c1.y + b1);
            int col = cn0 + cb;
            if (mode == 0) {
                *(float2*)&Cf[(size_t)r * EMB + col]       = make_float2(v00, v01);
                *(float2*)&Cf[(size_t)(r + 8) * EMB + col] = make_float2(v10, v11);
            } else if (mode == 1) {      // q: [hi|lo], width 1024
                float h00 = __half2float(__float2half(v00));
                float h01 = __half2float(__float2half(v01));
                float h10 = __half2float(__float2half(v10));
                float h11 = __half2float(__float2half(v11));
                __half* d0 = Cs + (size_t)r * QW + col;
                __half* d1 = Cs + (size_t)(r + 8) * QW + col;
                *(uint32_t*)d0         = packh(h00, h01);
                *(uint32_t*)(d0 + 512) = packh(v00 - h00, v01 - h01);
                *(uint32_t*)d1         = packh(h10, h11);
                *(uint32_t*)(d1 + 512) = packh(v10 - h10, v11 - h11);
            } else {                     // plain fp16, width 512
                *(uint32_t*)(Cs + (size_t)r * EMB + col)       = packh(v00, v01);
                *(uint32_t*)(Cs + (size_t)(r + 8) * EMB + col) = packh(v10, v11);
            }
        }
    }
}

__global__ void __launch_bounds__(256, 2) gemm_qkv_kernel(const float* __restrict__ bias) {
    int m0 = blockIdx.x * 64;
    int nt = blockIdx.y;          // 0..11
    int sect = nt >> 2;
    int cn0 = (nt & 3) * 128;
    const __half* Bw = g_wqkv + (size_t)nt * 128 * KW;
    if (sect == 0)
        gemm_core<4, 32, 15>(g_aq, Bw, bias + nt * 128, nullptr, g_sq,
                             cn0, m0, QSCALE, 1, EMB, KW);
    else if (sect == 1)
        gemm_core<4, 16, 15>(g_ak, Bw, bias + nt * 128, nullptr, g_sk,
                             cn0, m0, 1.0f, 4, EMB, KW);
    else
        gemm_core<4, 16, 15>(g_av, Bw, bias + nt * 128, g_v, nullptr,
                             cn0, m0, 1.0f, 0, EMB, KW);
}
__global__ void __launch_bounds__(256, 2) gemm_out_kernel(const float* __restrict__ bias,
                                                          float* __restrict__ C) {
    gemm_core<2, 16, 1023>(g_actx, g_wo + (size_t)blockIdx.y * 64 * EMB,
                           bias + blockIdx.y * 64, C, nullptr, blockIdx.y * 64,
                           blockIdx.x * 64, 1.0f, 0, EMB, EMB);
}

// ---------------------------------------------------------------------------
// Fused: V transpose (blocks 0..255) + type_scores (blocks 256..2303)
// ---------------------------------------------------------------------------
__global__ __launch_bounds__(256) void tsvt_kernel(const float* __restrict__ edge_embs) {
    __shared__ float sh[64 * 68];
    int tid = threadIdx.x;
    if (blockIdx.x < 256) {
        int h = blockIdx.x >> 5, j0 = (blockIdx.x & 31) * 64;
        {
            int row = tid >> 2, cg = (tid & 3) * 16;
            const float* src = g_v + (size_t)(j0 + row) * EMB + h * HDIM + cg;
            #pragma unroll
            for (int i = 0; i < 4; i++)
                *(float4*)&sh[row * 68 + cg + i * 4] = *(const float4*)(src + i * 4);
        }
        __syncthreads();
        int d = tid >> 2, jg = (tid & 3) * 16;
        uint32_t hw[8];
        #pragma unroll
        for (int p = 0; p < 8; p++) {
            float v0 = sh[(jg + 2 * p) * 68 + d], v1 = sh[(jg + 2 * p + 1) * 68 + d];
            hw[p] = packh(v0, v1);
        }
        __half* dsth = g_svt + ((size_t)(h * 64 + d) * L_SEQ + j0 + jg);
        *(uint4*)dsth       = make_uint4(hw[0], hw[1], hw[2], hw[3]);
        *(uint4*)(dsth + 8) = make_uint4(hw[4], hw[5], hw[6], hw[7]);
    } else {
        float* emb = sh;
        for (int i = tid; i < NTYPE * HDIM; i += 256) emb[i] = edge_embs[i];
        __syncthreads();
        int warp = (blockIdx.x - 256) * 8 + (tid >> 5);
        int lane = tid & 31;
        int h = warp >> 11, i = warp & (L_SEQ - 1);
        const __half* qr = g_sq + (size_t)i * QW + h * HDIM + lane * 2;
        float2 qh = __half22float2(*(const __half2*)qr);
        float2 ql = __half22float2(*(const __half2*)(qr + 512));
        float2 qv = make_float2(qh.x + ql.x, qh.y + ql.y);
        float s[NTYPE];
        #pragma unroll
        for (int t = 0; t < NTYPE; t++) {
            float2 e = *(const float2*)(emb + t * HDIM + lane * 2);
            s[t] = qv.x * e.x + qv.y * e.y;
        }
        #pragma unroll
        for (int off = 16; off > 0; off >>= 1)
            #pragma unroll
            for (int t = 0; t < NTYPE; t++)
                s[t] += __shfl_xor_sync(0xffffffffu, s[t], off);
        if (lane == 0) {
            float* dst = g_ts + (size_t)warp * 16;
            #pragma unroll
            for (int t = 0; t < NTYPE; t++) dst[t] = s[t];
        }
    }
}

// ---------------------------------------------------------------------------
// Flash attention: i-tile 64, 2 independent 4-warp groups, 2 CTAs/SM.
// All fragments via ldmatrix.x4; 16B-ALIGNED conflict-free pitches:
// Q/K 144B (16*9), V 80B (16*5; banks 20r mod 32 distinct).
// smem: Q 9216 @0; K 2grp x 2buf x 4608 @9216; V 2grp x 2buf x 5120 @27648;
// Ts @48128. total 52224. 2 CTAs/SM.
// ---------------------------------------------------------------------------
#define SM_K 9216
#define SM_V 27648
#define SM_T 48128
#define ATTN_SMEM 52224

__global__ void __launch_bounds__(256, 2) attn_mma_kernel() {
    extern __shared__ char smb[];
    float* Ts = (float*)(smb + SM_T);
    uint32_t sbase = smem_to_u32(smb);

    int h = blockIdx.y;
    int i0 = blockIdx.x * 64;
    int tid = threadIdx.x, wid = tid >> 5, lane = tid & 31;
    int gid = lane >> 2, qt = lane & 3;
    int ngrp = wid >> 2, wg = wid & 3, gtid = tid & 127;
    const uint32_t ones2 = 0x3C003C00u;
    const uint32_t kgrp = sbase + SM_K + ngrp * 9216;
    const uint32_t vgrp = sbase + SM_V + ngrp * 10240;

    auto load_kv = [&](int j0, int buf) {
        {   // K half-tile: 32 j-rows x 128B, pitch 144B
            int row = gtid >> 2, part = gtid & 3;
            const __half* src = g_sk + (size_t)(j0 + ngrp * 32 + row) * EMB
                                + h * HDIM + part * 16;
            uint32_t dst = kgrp + buf * 4608 + row * 144 + part * 32;
            cp16(dst, src); cp16(dst + 16, src + 8);
        }
        {   // V half: 64 d-rows x 64B, pitch 80B
            int row = gtid >> 1, part = gtid & 1;
            const __half* src = g_svt + (size_t)(h * 64 + row) * L_SEQ
                                + j0 + ngrp * 32 + part * 16;
            uint32_t dst = vgrp + buf * 5120 + row * 80 + part * 32;
            cp16(dst, src); cp16(dst + 16, src + 8);
        }
    };

    {   // Q tile (64 rows x 128B, pitch 144B) + Ts
        int row = tid >> 2, part = tid & 3;
        const __half* src = g_sq + (size_t)(i0 + row) * QW + h * HDIM + part * 16;
        uint32_t dst = sbase + row * 144 + part * 32;
        cp16(dst, src); cp16(dst + 16, src + 8);
        *(float4*)(Ts + row * 16 + part * 4) =
            *(const float4*)(g_ts + ((size_t)h * L_SEQ + i0 + row) * 16 + part * 4);
    }
    load_kv(0, 0);
    CP_COMMIT;
    asm volatile("cp.async.wait_group 0;" ::: "memory");
    __syncthreads();

    int r0 = wg * 16 + gid;
    int lm_row = (lane & 7) | (((lane >> 3) & 1) << 3);
    int lm_hi  = (lane >> 4) & 1;

    uint32_t qh[4][4];
    {
        uint32_t qa = sbase + (wg * 16 + lm_row) * 144 + lm_hi * 16;
        #pragma unroll
        for (int kc = 0; kc < 4; kc++)
            ldsm4(qh[kc][0], qh[kc][1], qh[kc][2], qh[kc][3], qa + kc * 32);
    }

    float o[8][4] = {};
    float rm0 = -1e30f, rm1 = -1e30f, rl0 = 0.f, rl1 = 0.f;
    const float* T0 = Ts + r0 * 16;
    const float* T1 = T0 + 128;
    const uint8_t* eb0 = g_eid8 + (size_t)(i0 + r0) * L_SEQ;
    const uint8_t* eb1 = eb0 + 8 * L_SEQ;
    const int bid = ngrp + 1;
    const uint32_t klm = kgrp + lm_row * 144 + lm_hi * 16;
    const uint32_t vlm = vgrp + lm_row * 80 + lm_hi * 16;

    for (int t = 0; t < 32; t++) {
        int cur = t & 1;
        if (t + 1 < 32) {
            load_kv((t + 1) * 64, cur ^ 1);
            CP_COMMIT;
            asm volatile("cp.async.wait_group 1;" ::: "memory");
        } else {
            asm volatile("cp.async.wait_group 0;" ::: "memory");
        }
        asm volatile("bar.sync %0, 128;" :: "r"(bid) : "memory");
        int j0 = t * 64;

        // ---- edge-id prefetch (int8) ----
        unsigned short e0r[4], e1r[4];
        #pragma unroll
        for (int ntl = 0; ntl < 4; ntl++) {
            int col = j0 + ngrp * 32 + ntl * 8 + qt * 2;
            e0r[ntl] = *(const unsigned short*)(eb0 + col);
            e1r[ntl] = *(const unsigned short*)(eb1 + col);
        }

        // ---- S = qh*kh via ldmatrix B-fragments ----
        uint32_t ka = klm + cur * 4608;
        float sa[4][4] = {};
        #pragma unroll
        for (int kc = 0; kc < 4; kc++) {
            uint32_t b0, b1, b2, b3, c0, c1, c2, c3;
            ldsm4(b0, b1, b2, b3, ka + kc * 32);
            ldsm4(c0, c1, c2, c3, ka + 16 * 144 + kc * 32);
            mma16816(sa[0], qh[kc], b0, b2);
            mma16816(sa[1], qh[kc], b1, b3);
            mma16816(sa[2], qh[kc], c0, c2);
            mma16816(sa[3], qh[kc], c1, c3);
        }
        #pragma unroll
        for (int ntl = 0; ntl < 4; ntl++) {
            sa[ntl][0] += T0[e0r[ntl] & 0xFF];
            sa[ntl][1] += T0[e0r[ntl] >> 8];
            sa[ntl][2] += T1[e1r[ntl] & 0xFF];
            sa[ntl][3] += T1[e1r[ntl] >> 8];
        }

        // ---- online softmax (base 2) ----
        float mx0 = -1e30f, mx1 = -1e30f;
        #pragma unroll
        for (int ntl = 0; ntl < 4; ntl++) {
            mx0 = fmaxf(mx0, fmaxf(sa[ntl][0], sa[ntl][1]));
            mx1 = fmaxf(mx1, fmaxf(sa[ntl][2], sa[ntl][3]));
        }
        mx0 = fmaxf(mx0, __shfl_xor_sync(0xffffffffu, mx0, 1));
        mx0 = fmaxf(mx0, __shfl_xor_sync(0xffffffffu, mx0, 2));
        mx1 = fmaxf(mx1, __shfl_xor_sync(0xffffffffu, mx1, 1));
        mx1 = fmaxf(mx1, __shfl_xor_sync(0xffffffffu, mx1, 2));
        float mn0 = fmaxf(rm0, mx0), mn1 = fmaxf(rm1, mx1);
        bool skip = __all_sync(0xffffffffu, (mn0 == rm0) & (mn1 == rm1));

        uint32_t ph[2][4];
        float ls[4] = {};
        #pragma unroll
        for (int kcp = 0; kcp < 2; kcp++) {
            const float* t0v = sa[2 * kcp];
            const float* t1v = sa[2 * kcp + 1];
            ph[kcp][0] = ex2h2(t0v[0] - mn0, t0v[1] - mn0);
            ph[kcp][1] = ex2h2(t0v[2] - mn1, t0v[3] - mn1);
            ph[kcp][2] = ex2h2(t1v[0] - mn0, t1v[1] - mn0);
            ph[kcp][3] = ex2h2(t1v[2] - mn1, t1v[3] - mn1);
            mma16816(ls, ph[kcp], ones2, ones2);
        }
        if (!skip) {
            float c0 = ex2f(rm0 - mn0), c1 = ex2f(rm1 - mn1);
            rl0 *= c0; rl1 *= c1;
            #pragma unroll
            for (int dt = 0; dt < 8; dt++) {
                o[dt][0] *= c0; o[dt][1] *= c0;
                o[dt][2] *= c1; o[dt][3] *= c1;
            }
            rm0 = mn0; rm1 = mn1;
        }
        rl0 += ls[0];
        rl1 += ls[2];

        // ---- PV via ldmatrix V B-fragments ----
        uint32_t va = vlm + cur * 5120;
        #pragma unroll
        for (int kcp = 0; kcp < 2; kcp++) {
            #pragma unroll
            for (int b = 0; b < 4; b++) {
                uint32_t v0, v1, v2, v3;
                ldsm4(v0, v1, v2, v3, va + b * 16 * 80 + kcp * 32);
                mma16816(o[2 * b],     ph[kcp], v0, v2);
                mma16816(o[2 * b + 1], ph[kcp], v1, v3);
            }
        }
        asm volatile("bar.sync %0, 128;" :: "r"(bid) : "memory");
    }

    // ---- combine the two n-groups (reuse K region: 18432 >= 17408) ----
    __syncthreads();
    float* co = (float*)(smb + SM_K);            // [64][66]
    float* cm = (float*)(smb + SM_K + 16896);
    float* cl = (float*)(smb + SM_K + 17152);
    if (ngrp == 1) {
        if (qt == 0) {
            cm[r0] = rm0; cm[r0 + 8] = rm1;
            cl[r0] = rl0; cl[r0 + 8] = rl1;
        }
        #pragma unroll
        for (int dt = 0; dt < 8; dt++) {
            int c = dt * 8 + qt * 2;
            *(float2*)&co[r0 * 66 + c]       = make_float2(o[dt][0], o[dt][1]);
            *(float2*)&co[(r0 + 8) * 66 + c] = make_float2(o[dt][2], o[dt][3]);
        }
    }
    __syncthreads();
    if (ngrp == 0) {
        float m1a = cm[r0], l1a = cl[r0];
        float m1b = cm[r0 + 8], l1b = cl[r0 + 8];
        float M0 = fmaxf(rm0, m1a), M1 = fmaxf(rm1, m1b);
        float a0 = ex2f(rm0 - M0), b0 = ex2f(m1a - M0);
        float a1 = ex2f(rm1 - M1), b1 = ex2f(m1b - M1);
        float inv0 = 1.0f / (rl0 * a0 + l1a * b0);
        float inv1 = 1.0f / (rl1 * a1 + l1b * b1);
        __half* dst0 = g_actx + (size_t)(i0 + r0) * EMB + h * HDIM;
        __half* dst1 = g_actx + (size_t)(i0 + r0 + 8) * EMB + h * HDIM;
        #pragma unroll
        for (int dt = 0; dt < 8; dt++) {
            int c = dt * 8 + qt * 2;
            float v0 = (o[dt][0] * a0 + co[r0 * 66 + c] * b0) * inv0;
            float v1 = (o[dt][1] * a0 + co[r0 * 66 + c + 1] * b0) * inv0;
            float w0 = (o[dt][2] * a1 + co[(r0 + 8) * 66 + c] * b1) * inv1;
            float w1 = (o[dt][3] * a1 + co[(r0 + 8) * 66 + c + 1] * b1) * inv1;
            *(uint32_t*)(dst0 + c) = packh(v0, v1);
            *(uint32_t*)(dst1 + c) = packh(w0, w1);
        }
    }
}

// ---------------------------------------------------------------------------
extern "C" void kernel_launch(void* const* d_in, const int* in_sizes, int n_in,
                              void* d_out, int out_size)
{
    const float* query = (const float*)d_in[0];
    const float* key   = (const float*)d_in[1];
    const float* value = (const float*)d_in[2];
    const int*   eid   = (const int*)d_in[3];
    const float* w_in  = (const float*)d_in[4];
    const float* b_in  = (const float*)d_in[5];
    const float* w_out = (const float*)d_in[6];
    const float* b_out = (const float*)d_in[7];
    const float* embK  = (const float*)d_in[8];
    float* out = (float*)d_out;

    // launch 0: splits + edge int8 compression
    split_all<<<20480, 256>>>(query, key, value, w_in, w_out, eid);

    // launch 1: QKV projection
    dim3 qkv_grid(L_SEQ / 64, 12);
    gemm_qkv_kernel<<<qkv_grid, 256>>>(b_in);

    // launch 2: V transpose + type scores
    tsvt_kernel<<<2304, 256>>>(embK);

    // launch 3: flash attention (ldmatrix fragments, aligned pitches)
    cudaFuncSetAttribute(attn_mma_kernel, cudaFuncAttributeMaxDynamicSharedMemorySize,
                         ATTN_SMEM);
    dim3 attn_grid(L_SEQ / 64, NHEAD);
    attn_mma_kernel<<<attn_grid, 256, ATTN_SMEM>>>();

    // launch 4: out projection
    dim3 out_grid(L_SEQ / 64, EMB / 64);
    gemm_out_kernel<<<out_grid, 256>>>(b_out, out);
}